// round 5
// baseline (speedup 1.0000x reference)
#include <cuda_runtime.h>
#include <math.h>
#include <stdint.h>

#define TOK   12544
#define BATCH 4
#define LSEQ  3136
#define NWIN  256
#define NCH   49
#define CH    64

// ---------------- scratch ----------------
__device__ float g_xn[TOK*128];
__device__ float g_qkv[TOK*384];
__device__ float g_awb[TOK*128];
__device__ float g_attn[TOK*128];
__device__ float g_xz[TOK*512];
__device__ float g_xc[TOK*256];
__device__ float g_dbl[TOK*40];
__device__ float g_dt[TOK*256];
__device__ float g_y[TOK*256];
__device__ float g_mamba[TOK*128];
__device__ float g_x1[TOK*128];
__device__ float g_h2[TOK*128];
__device__ float g_hid[TOK*512];
__device__ float g_hend[BATCH*NCH*256*16];
__device__ float g_hin[BATCH*NCH*256*16];
__device__ float g_sumdt[BATCH*NCH*256];

__device__ __forceinline__ float gelu_f(float x){ return 0.5f*x*(1.f+erff(x*0.70710678118f)); }
__device__ __forceinline__ uint32_t tf32r(float x){
    uint32_t r; asm("cvt.rna.tf32.f32 %0, %1;" : "=r"(r) : "f"(x)); return r;
}
__device__ __forceinline__ void mma8(float* c, const uint32_t* a, const uint32_t* b){
    asm volatile("mma.sync.aligned.m16n8k8.row.col.f32.tf32.tf32.f32 "
        "{%0,%1,%2,%3}, {%4,%5,%6,%7}, {%8,%9}, {%0,%1,%2,%3};"
        : "+f"(c[0]),"+f"(c[1]),"+f"(c[2]),"+f"(c[3])
        : "r"(a[0]),"r"(a[1]),"r"(a[2]),"r"(a[3]), "r"(b[0]),"r"(b[1]));
}

// ================= tf32 mma.sync GEMM =================
// C[M,Nout] = A[M,K] @ W[Nout,K]^T (+bias, epilogue). CTA tile 128 x NT, Ktile 32.
// EPI: 0 none, 1 gelu, 2 gate-fuse (e0=x,e1=attn,e2=mamba), 3 residual(e0)
// AG: A gathered as [e1|e2] (K==256). NP: skip W rows / C cols >= Nout (pad).
template<int NT, int EPI, int AG, int NP>
__global__ __launch_bounds__(256)
void mma_gemm(const float* __restrict__ A, const float* __restrict__ W,
              const float* __restrict__ bias, float* __restrict__ C,
              int Nout, int K,
              const float* __restrict__ e0, const float* __restrict__ e1,
              const float* __restrict__ e2)
{
    // A staged as [8 mt][4 ks][32 lane][4 slots] floats (fragment order)
    // B staged as [NT/8 nt][4 ks][32 lane][2 slots]
    __shared__ __align__(16) float As[4096];
    __shared__ __align__(16) float Bs[NT*32];
    const int NW = NT/32;              // warps along N
    const int MT = (NT==128) ? 4 : 2;  // m16 frags per warp
    int tid = threadIdx.x, wid = tid>>5, lane = tid&31;
    int warp_n = wid % NW, warp_m = wid / NW;
    int bm = blockIdx.y*128, bn = blockIdx.x*NT;
    int m0 = warp_m * MT * 16;

    float acc[MT][4][4];
    #pragma unroll
    for (int i=0;i<MT;i++)
        #pragma unroll
        for (int j=0;j<4;j++)
            #pragma unroll
            for (int q=0;q<4;q++) acc[i][j][q]=0.f;

    int KT = K >> 5;
    for (int kt=0; kt<KT; kt++){
        int kc = kt*32;
        // ---- stage A (128x32) ----
        #pragma unroll
        for (int i=0;i<4;i++){
            int f = tid + i*256;
            int row = f>>3, cq = f&7;
            float4 v;
            if (AG){
                int kg = kc + cq*4;
                const float* src = (kg<128) ? e1 + (size_t)(bm+row)*128 + kg
                                            : e2 + (size_t)(bm+row)*128 + (kg-128);
                v = *(const float4*)src;
            } else {
                v = *(const float4*)(A + (size_t)(bm+row)*K + kc + cq*4);
            }
            int boff = ((((row>>4)*4 + (cq>>1))*32 + 4*(row&7))<<2) + ((row>>3)&1) + ((cq&1)<<1);
            As[boff+0]  = __uint_as_float(tf32r(v.x));
            As[boff+4]  = __uint_as_float(tf32r(v.y));
            As[boff+8]  = __uint_as_float(tf32r(v.z));
            As[boff+12] = __uint_as_float(tf32r(v.w));
        }
        // ---- stage B (NTx32) ----
        #pragma unroll
        for (int i=0;i<NT/32;i++){
            int f = tid + i*256;
            int row = f>>3, cq = f&7;
            float4 v;
            if (NP && (bn+row) >= Nout) v = make_float4(0.f,0.f,0.f,0.f);
            else v = *(const float4*)(W + (size_t)(bn+row)*K + kc + cq*4);
            int boff = ((((row>>3)*4 + (cq>>1))*32 + 4*(row&7))<<1) + (cq&1);
            Bs[boff+0] = __uint_as_float(tf32r(v.x));
            Bs[boff+2] = __uint_as_float(tf32r(v.y));
            Bs[boff+4] = __uint_as_float(tf32r(v.z));
            Bs[boff+6] = __uint_as_float(tf32r(v.w));
        }
        __syncthreads();
        // ---- compute ----
        const float4* As4 = (const float4*)As;
        const float2* Bs2 = (const float2*)Bs;
        #pragma unroll
        for (int ks=0; ks<4; ks++){
            uint32_t af[MT][4];
            #pragma unroll
            for (int i=0;i<MT;i++){
                float4 a = As4[((warp_m*MT+i)*4 + ks)*32 + lane];
                af[i][0]=__float_as_uint(a.x); af[i][1]=__float_as_uint(a.y);
                af[i][2]=__float_as_uint(a.z); af[i][3]=__float_as_uint(a.w);
            }
            uint32_t bf[4][2];
            #pragma unroll
            for (int j=0;j<4;j++){
                float2 b = Bs2[((warp_n*4+j)*4 + ks)*32 + lane];
                bf[j][0]=__float_as_uint(b.x); bf[j][1]=__float_as_uint(b.y);
            }
            #pragma unroll
            for (int i=0;i<MT;i++)
                #pragma unroll
                for (int j=0;j<4;j++) mma8(acc[i][j], af[i], bf[j]);
        }
        if (kt+1 < KT) __syncthreads();
    }

    // ---- epilogue ----
    #pragma unroll
    for (int i=0;i<MT;i++){
        #pragma unroll
        for (int j=0;j<4;j++){
            int n = bn + warp_n*32 + j*8 + 2*(lane&3);
            if (NP && n >= Nout) continue;
            float2 bv = bias ? *(const float2*)(bias + n) : make_float2(0.f,0.f);
            #pragma unroll
            for (int half=0; half<2; half++){
                int m = bm + m0 + i*16 + (lane>>2) + half*8;
                float vx = acc[i][j][half*2+0] + bv.x;
                float vy = acc[i][j][half*2+1] + bv.y;
                size_t idx = (size_t)m*Nout + n;
                if (EPI == 1){
                    vx = gelu_f(vx); vy = gelu_f(vy);
                } else if (EPI == 2){
                    float2 r0 = *(const float2*)(e0 + idx);
                    float2 r1 = *(const float2*)(e1 + idx);
                    float2 r2 = *(const float2*)(e2 + idx);
                    float gx = 1.f/(1.f+__expf(-vx));
                    float gy = 1.f/(1.f+__expf(-vy));
                    vx = r0.x + gx*r1.x + (1.f-gx)*r2.x;
                    vy = r0.y + gy*r1.y + (1.f-gy)*r2.y;
                } else if (EPI == 3){
                    float2 r0 = *(const float2*)(e0 + idx);
                    vx += r0.x; vy += r0.y;
                }
                *(float2*)(C + idx) = make_float2(vx, vy);
            }
        }
    }
}

// ---------------- LayerNorm ----------------
__global__ void ln_kernel(const float* __restrict__ in, const float* __restrict__ g,
                          const float* __restrict__ b, float* __restrict__ out) {
    int warp = (blockIdx.x * blockDim.x + threadIdx.x) >> 5;
    int lane = threadIdx.x & 31;
    if (warp >= TOK) return;
    float4 v = ((const float4*)(in + (size_t)warp*128))[lane];
    float s = v.x+v.y+v.z+v.w;
    #pragma unroll
    for (int o=16;o;o>>=1) s += __shfl_xor_sync(~0u, s, o);
    float mean = s * (1.f/128.f);
    float dx=v.x-mean, dy=v.y-mean, dz=v.z-mean, dw=v.w-mean;
    float q = dx*dx+dy*dy+dz*dz+dw*dw;
    #pragma unroll
    for (int o=16;o;o>>=1) q += __shfl_xor_sync(~0u, q, o);
    float rstd = rsqrtf(q*(1.f/128.f) + 1e-5f);
    float4 gv = ((const float4*)g)[lane];
    float4 bv = ((const float4*)b)[lane];
    float4 ov;
    ov.x = dx*rstd*gv.x + bv.x;
    ov.y = dy*rstd*gv.y + bv.y;
    ov.z = dz*rstd*gv.z + bv.z;
    ov.w = dw*rstd*gv.w + bv.w;
    ((float4*)(out + (size_t)warp*128))[lane] = ov;
}

// ---------------- window attention ----------------
__global__ void attn_kernel(const float* __restrict__ rpb) {
    int w = blockIdx.x >> 2;
    int head = blockIdx.x & 3;
    int b = w >> 6, wh = (w >> 3) & 7, ww = w & 7;
    __shared__ float qs[49][32], ks[49][32], vs[49][32];
    __shared__ float sc[49][49];
    int tid = threadIdx.x;
    const float scale = 0.17677669529663689f;
    for (int i = tid; i < 49*32; i += 128) {
        int n = i >> 5, d = i & 31;
        int t = ((b*56 + wh*7 + n/7)*56 + ww*7 + n%7);
        const float* base = g_qkv + (size_t)t*384 + head*32 + d;
        qs[n][d] = base[0] * scale;
        ks[n][d] = base[128];
        vs[n][d] = base[256];
    }
    __syncthreads();
    for (int idx = tid; idx < 49*49; idx += 128) {
        int i = idx/49, j = idx%49;
        float s = 0.f;
        const float4* qp = (const float4*)qs[i];
        const float4* kp = (const float4*)ks[j];
        #pragma unroll
        for (int k=0;k<8;k++){ float4 a=qp[k], c=kp[k]; s += a.x*c.x+a.y*c.y+a.z*c.z+a.w*c.w; }
        int dr = i/7 - j/7 + 6, dc = i%7 - j%7 + 6;
        sc[i][j] = s + rpb[(dr*13+dc)*4 + head];
    }
    __syncthreads();
    if (tid < 49) {
        int i = tid;
        float m = -1e30f;
        for (int j=0;j<49;j++) m = fmaxf(m, sc[i][j]);
        float sum = 0.f;
        for (int j=0;j<49;j++){ float e=__expf(sc[i][j]-m); sc[i][j]=e; sum+=e; }
        float inv = 1.f/sum;
        for (int j=0;j<49;j++) sc[i][j] *= inv;
    }
    __syncthreads();
    for (int idx = tid; idx < 49*32; idx += 128) {
        int i = idx >> 5, d = idx & 31;
        float o = 0.f;
        for (int j=0;j<49;j++) o += sc[i][j]*vs[j][d];
        int t = ((b*56 + wh*7 + i/7)*56 + ww*7 + i%7);
        g_awb[(size_t)t*128 + head*32 + d] = o;
    }
}

// ---------------- causal depthwise conv + SiLU ----------------
__global__ void conv_kernel(const float* __restrict__ cw, const float* __restrict__ cb) {
    int idx = blockIdx.x*blockDim.x + threadIdx.x;
    if (idx >= TOK*256) return;
    int t = idx >> 8, d = idx & 255;
    int b = t / LSEQ, l = t % LSEQ;
    float acc = cb[d];
    #pragma unroll
    for (int j=0;j<4;j++){
        int ll = l - 3 + j;
        if (ll >= 0) acc = fmaf(cw[d*4+j], g_xz[((size_t)(b*LSEQ+ll))*512 + d], acc);
    }
    float sg = 1.f/(1.f+__expf(-acc));
    g_xc[idx] = acc * sg;
}

// ---------------- dt_proj + softplus ----------------
__global__ void dtproj_kernel(const float* __restrict__ wt, const float* __restrict__ bias){
    int idx = blockIdx.x*blockDim.x + threadIdx.x;
    if (idx >= TOK*256) return;
    int t = idx >> 8, d = idx & 255;
    float acc = bias[d];
    const float* r = g_dbl + (size_t)t*40;
    const float* wr = wt + d*8;
    #pragma unroll
    for (int k=0;k<8;k++) acc = fmaf(r[k], wr[k], acc);
    float sp = (acc > 20.f) ? acc : log1pf(__expf(acc));
    g_dt[idx] = sp;
}

// ============ chunk-parallel selective scan ============
__global__ __launch_bounds__(256) void scan_phase1(const float* __restrict__ A_log){
    int gw = (blockIdx.x*blockDim.x + threadIdx.x) >> 5;
    int lane = threadIdx.x & 31;
    int dpair = gw & 127;
    int chunk = (gw >> 7) % NCH;
    int b = gw / (128*NCH);
    int d = dpair*2 + (lane >> 4);
    int s = lane & 15;
    float Aval = -__expf(A_log[d*16 + s]);
    float h = 0.f, sd = 0.f;
    int t0 = b*LSEQ + chunk*CH;
    for (int g = 0; g < CH; g += 8) {
        float dtv[8], xcv[8], Bv[8];
        #pragma unroll
        for (int u=0;u<8;u++){
            int t = t0 + g + u;
            dtv[u] = g_dt[(size_t)t*256 + d];
            xcv[u] = g_xc[(size_t)t*256 + d];
            Bv[u]  = g_dbl[(size_t)t*40 + 8 + s];
        }
        #pragma unroll
        for (int u=0;u<8;u++){
            sd += dtv[u];
            float a = __expf(dtv[u]*Aval);
            h = a*h + dtv[u]*Bv[u]*xcv[u];
        }
    }
    size_t hidx = ((size_t)(b*NCH + chunk)*256 + d)*16 + s;
    g_hend[hidx] = h;
    if (s == 0) g_sumdt[(b*NCH + chunk)*256 + d] = sd;
}

__global__ __launch_bounds__(256) void scan_phase2(const float* __restrict__ A_log){
    int gw = (blockIdx.x*blockDim.x + threadIdx.x) >> 5;
    int lane = threadIdx.x & 31;
    int b = gw >> 7;
    int dpair = gw & 127;
    int d = dpair*2 + (lane >> 4);
    int s = lane & 15;
    float Aval = -__expf(A_log[d*16 + s]);
    float h = 0.f;
    for (int c = 0; c < NCH; c++) {
        size_t hidx = ((size_t)(b*NCH + c)*256 + d)*16 + s;
        g_hin[hidx] = h;
        float sd = g_sumdt[(b*NCH + c)*256 + d];
        h = __expf(Aval*sd)*h + g_hend[hidx];
    }
}

__global__ __launch_bounds__(256) void scan_phase3(const float* __restrict__ A_log,
                                                   const float* __restrict__ Dp){
    __shared__ float part[8*32*33];
    int warp = threadIdx.x >> 5, lane = threadIdx.x & 31;
    int gw = blockIdx.x * 8 + warp;
    int dpair = gw & 127;
    int chunk = (gw >> 7) % NCH;
    int b = gw / (128*NCH);
    int dbase = dpair*2;
    int d = dbase + (lane >> 4);
    int s = lane & 15;
    float Aval = -__expf(A_log[d*16 + s]);
    float dp0 = Dp[dbase], dp1 = Dp[dbase+1];
    size_t hidx = ((size_t)(b*NCH + chunk)*256 + d)*16 + s;
    float h = g_hin[hidx];
    float* pp = part + warp*32*33 + lane*33;
    float* wp = part + warp*32*33;
    int tb = b*LSEQ + chunk*CH;
    #pragma unroll 1
    for (int half = 0; half < 2; half++) {
        int base = half*32;
        #pragma unroll 1
        for (int g = 0; g < 32; g += 8) {
            float dtv[8], xcv[8], Bv[8], Cv[8];
            #pragma unroll
            for (int u=0;u<8;u++){
                int t = tb + base + g + u;
                dtv[u] = g_dt[(size_t)t*256 + d];
                xcv[u] = g_xc[(size_t)t*256 + d];
                Bv[u]  = g_dbl[(size_t)t*40 + 8 + s];
                Cv[u]  = g_dbl[(size_t)t*40 + 24 + s];
            }
            #pragma unroll
            for (int u=0;u<8;u++){
                float a = __expf(dtv[u]*Aval);
                h = a*h + dtv[u]*Bv[u]*xcv[u];
                pp[g+u] = h * Cv[u];
            }
        }
        __syncwarp();
        {
            int lu = lane;
            int t = tb + base + lu;
            #pragma unroll
            for (int c2=0;c2<2;c2++){
                float ys = 0.f;
                #pragma unroll
                for (int ss=0; ss<16; ss++) ys += wp[(c2*16+ss)*33 + lu];
                int d2 = dbase + c2;
                float xcv2 = g_xc[(size_t)t*256 + d2];
                float zv = g_xz[(size_t)t*512 + 256 + d2];
                float yv = ys + xcv2 * (c2 ? dp1 : dp0);
                float sg = 1.f/(1.f+__expf(-zv));
                g_y[(size_t)t*256 + d2] = yv * zv * sg;
            }
        }
        __syncwarp();
    }
}

// ---------------- launch ----------------
extern "C" void kernel_launch(void* const* d_in, const int* in_sizes, int n_in,
                              void* d_out, int out_size) {
    const float* x        = (const float*)d_in[0];
    const float* ln1_g    = (const float*)d_in[1];
    const float* ln1_b    = (const float*)d_in[2];
    const float* qkv_w    = (const float*)d_in[3];
    const float* qkv_b    = (const float*)d_in[4];
    const float* rpb      = (const float*)d_in[5];
    const float* proj_w   = (const float*)d_in[6];
    const float* proj_b   = (const float*)d_in[7];
    const float* in_w     = (const float*)d_in[8];
    const float* in_b     = (const float*)d_in[9];
    const float* conv_w   = (const float*)d_in[10];
    const float* conv_b   = (const float*)d_in[11];
    const float* xproj_w  = (const float*)d_in[12];
    const float* dtw      = (const float*)d_in[13];
    const float* dtb      = (const float*)d_in[14];
    const float* A_log    = (const float*)d_in[15];
    const float* Dp       = (const float*)d_in[16];
    const float* out_w    = (const float*)d_in[17];
    const float* out_b    = (const float*)d_in[18];
    const float* gate_w   = (const float*)d_in[19];
    const float* gate_b   = (const float*)d_in[20];
    const float* ln2_g    = (const float*)d_in[21];
    const float* ln2_b    = (const float*)d_in[22];
    const float* mlp_w1   = (const float*)d_in[23];
    const float* mlp_b1   = (const float*)d_in[24];
    const float* mlp_w2   = (const float*)d_in[25];
    const float* mlp_b2   = (const float*)d_in[26];
    float* out = (float*)d_out;

    float *xn, *qkv, *awb, *attn, *xz, *y, *mamba, *x1, *h2, *hid, *xc, *dbl;
    cudaGetSymbolAddress((void**)&xn,    g_xn);
    cudaGetSymbolAddress((void**)&qkv,   g_qkv);
    cudaGetSymbolAddress((void**)&awb,   g_awb);
    cudaGetSymbolAddress((void**)&attn,  g_attn);
    cudaGetSymbolAddress((void**)&xz,    g_xz);
    cudaGetSymbolAddress((void**)&y,     g_y);
    cudaGetSymbolAddress((void**)&mamba, g_mamba);
    cudaGetSymbolAddress((void**)&x1,    g_x1);
    cudaGetSymbolAddress((void**)&h2,    g_h2);
    cudaGetSymbolAddress((void**)&hid,   g_hid);
    cudaGetSymbolAddress((void**)&xc,    g_xc);
    cudaGetSymbolAddress((void**)&dbl,   g_dbl);

    // LN1
    ln_kernel<<<TOK/8, 256>>>(x, ln1_g, ln1_b, xn);
    // qkv GEMM (N=384, K=128)
    mma_gemm<128,0,0,0><<<dim3(3,98), 256>>>(xn, qkv_w, qkv_b, qkv, 384, 128, nullptr, nullptr, nullptr);
    // window attention
    attn_kernel<<<NWIN*4, 128>>>(rpb);
    // proj GEMM (N=128, K=128) -> attn_out
    mma_gemm<64,0,0,0><<<dim3(2,98), 256>>>(awb, proj_w, proj_b, attn, 128, 128, nullptr, nullptr, nullptr);
    // in_proj GEMM (N=512, K=128) -> xz
    mma_gemm<128,0,0,0><<<dim3(4,98), 256>>>(xn, in_w, in_b, xz, 512, 128, nullptr, nullptr, nullptr);
    // causal conv + silu -> xc
    conv_kernel<<<TOK, 256>>>(conv_w, conv_b);
    // x_proj GEMM (N=40 pad 64, K=256) -> dbl
    mma_gemm<64,0,0,1><<<dim3(1,98), 256>>>(xc, xproj_w, nullptr, dbl, 40, 256, nullptr, nullptr, nullptr);
    // dt_proj + softplus -> dt
    dtproj_kernel<<<TOK, 256>>>(dtw, dtb);
    // chunk-parallel selective scan
    scan_phase1<<<(BATCH*NCH*128)/8, 256>>>(A_log);
    scan_phase2<<<64, 256>>>(A_log);
    scan_phase3<<<(BATCH*NCH*128)/8, 256>>>(A_log, Dp);
    // out_proj GEMM (N=128, K=256) -> mamba
    mma_gemm<64,0,0,0><<<dim3(2,98), 256>>>(y, out_w, out_b, mamba, 128, 256, nullptr, nullptr, nullptr);
    // gate GEMM (A=[attn|mamba], K=256) + fused blend + residual -> x1
    mma_gemm<64,2,1,0><<<dim3(2,98), 256>>>(nullptr, gate_w, gate_b, x1, 128, 256, x, attn, mamba);
    // LN2
    ln_kernel<<<TOK/8, 256>>>(x1, ln2_g, ln2_b, h2);
    // MLP1 + gelu (N=512, K=128)
    mma_gemm<128,1,0,0><<<dim3(4,98), 256>>>(h2, mlp_w1, mlp_b1, hid, 512, 128, nullptr, nullptr, nullptr);
    // MLP2 + residual (N=128, K=512) -> out
    mma_gemm<64,3,0,0><<<dim3(2,98), 256>>>(hid, mlp_w2, mlp_b2, out, 128, 512, x1, nullptr, nullptr);

    (void)in_sizes; (void)n_in; (void)out_size;
}

// round 6
// speedup vs baseline: 1.5299x; 1.5299x over previous
#include <cuda_runtime.h>
#include <math.h>
#include <stdint.h>

#define TOK   12544
#define BATCH 4
#define LSEQ  3136
#define NWIN  256
#define NCH   49
#define CH    64

// ---------------- scratch ----------------
__device__ float g_xn[TOK*128];
__device__ float g_qkv[TOK*384];
__device__ float g_awb[TOK*128];
__device__ float g_attn[TOK*128];
__device__ float g_xz[TOK*512];
__device__ float g_xc[TOK*256];
__device__ float g_dbl[TOK*40];
__device__ float g_dt[TOK*256];
__device__ float g_y[TOK*256];
__device__ float g_mamba[TOK*128];
__device__ float g_x1[TOK*128];
__device__ float g_h2[TOK*128];
__device__ float g_hid[TOK*512];
__device__ float g_hend[BATCH*NCH*256*16];
__device__ float g_hin[BATCH*NCH*256*16];
__device__ float g_sumdt[BATCH*NCH*256];

__device__ __forceinline__ float gelu_f(float x){ return 0.5f*x*(1.f+erff(x*0.70710678118f)); }
__device__ __forceinline__ float tf32f(float x){
    uint32_t r; asm("cvt.rna.tf32.f32 %0, %1;" : "=r"(r) : "f"(x)); return __uint_as_float(r);
}
__device__ __forceinline__ void mma8(float* c, const uint32_t* a, const uint32_t* b){
    asm volatile("mma.sync.aligned.m16n8k8.row.col.f32.tf32.tf32.f32 "
        "{%0,%1,%2,%3}, {%4,%5,%6,%7}, {%8,%9}, {%0,%1,%2,%3};"
        : "+f"(c[0]),"+f"(c[1]),"+f"(c[2]),"+f"(c[3])
        : "r"(a[0]),"r"(a[1]),"r"(a[2]),"r"(a[3]), "r"(b[0]),"r"(b[1]));
}

// ================= pipelined tf32 mma.sync GEMM =================
// C[M,Nout] = A[M,K] @ W[Nout,K]^T (+bias, epilogue). CTA tile 64 x NT, Ktile 32.
// 256 threads / 8 warps. 2-stage smem + register prefetch.
// EPI: 0 none, 1 gelu, 2 gate-fuse (e0=x,e1=attn,e2=mamba), 3 residual(e0)
// AG: A gathered as [e1|e2] (K==256). NP: W rows / C cols >= Nout are zero/skipped.
template<int NT, int EPI, int AG, int NP>
__global__ __launch_bounds__(256)
void mma_gemm(const float* __restrict__ A, const float* __restrict__ W,
              const float* __restrict__ bias, float* __restrict__ C,
              int Nout, int K,
              const float* __restrict__ e0, const float* __restrict__ e1,
              const float* __restrict__ e2)
{
    extern __shared__ float sm[];
    const int BF  = NT/32;            // B float4 loads per thread
    const int NW  = NT/32;            // warps along N
    const int MW  = 8/NW;             // warps along M
    const int MT  = 64/(16*MW);       // m16 frags per warp
    const int STG = 2048 + NT*32;     // floats per stage (A + B)
    int tid = threadIdx.x, wid = tid>>5, lane = tid&31;
    int warp_n = wid % NW, warp_m = wid / NW;
    int bm = blockIdx.y*64, bn = blockIdx.x*NT;
    int m0 = warp_m * MT * 16;

    float acc[MT][4][4];
    #pragma unroll
    for (int i=0;i<MT;i++)
        #pragma unroll
        for (int j=0;j<4;j++)
            #pragma unroll
            for (int q=0;q<4;q++) acc[i][j][q]=0.f;

    float4 pa[2], pb[BF];

    auto loadA = [&](int kc){
        #pragma unroll
        for (int i=0;i<2;i++){
            int f = tid + i*256;
            int row = f>>3, cq = f&7;
            if (AG){
                int kg = kc + cq*4;
                const float* src = (kg<128) ? e1 + (size_t)(bm+row)*128 + kg
                                            : e2 + (size_t)(bm+row)*128 + (kg-128);
                pa[i] = *(const float4*)src;
            } else {
                pa[i] = *(const float4*)(A + (size_t)(bm+row)*K + kc + cq*4);
            }
        }
    };
    auto loadB = [&](int kc){
        #pragma unroll
        for (int i=0;i<BF;i++){
            int f = tid + i*256;
            int row = f>>3, cq = f&7;
            if (NP && (bn+row) >= Nout) pb[i] = make_float4(0.f,0.f,0.f,0.f);
            else pb[i] = *(const float4*)(W + (size_t)(bn+row)*K + kc + cq*4);
        }
    };
    auto store = [&](int st){
        float* As = sm + st*STG;
        float* Bs = As + 2048;
        #pragma unroll
        for (int i=0;i<2;i++){
            int f = tid + i*256;
            int row = f>>3, cq = f&7;
            int boff = ((((row>>4)*4 + (cq>>1))*32 + 4*(row&7))<<2) + ((row>>3)&1) + ((cq&1)<<1);
            As[boff+0]  = tf32f(pa[i].x);
            As[boff+4]  = tf32f(pa[i].y);
            As[boff+8]  = tf32f(pa[i].z);
            As[boff+12] = tf32f(pa[i].w);
        }
        #pragma unroll
        for (int i=0;i<BF;i++){
            int f = tid + i*256;
            int row = f>>3, cq = f&7;
            int boff = ((((row>>3)*4 + (cq>>1))*32 + 4*(row&7))<<1) + (cq&1);
            Bs[boff+0] = tf32f(pb[i].x);
            Bs[boff+2] = tf32f(pb[i].y);
            Bs[boff+4] = tf32f(pb[i].z);
            Bs[boff+6] = tf32f(pb[i].w);
        }
    };

    int KT = K >> 5;
    loadA(0); loadB(0);
    store(0);
    __syncthreads();

    for (int kt=0; kt<KT; kt++){
        bool more = (kt+1) < KT;
        if (more){ loadA((kt+1)*32); loadB((kt+1)*32); }
        const float4* As4 = (const float4*)(sm + (kt&1)*STG);
        const float2* Bs2 = (const float2*)(sm + (kt&1)*STG + 2048);
        #pragma unroll
        for (int ks=0; ks<4; ks++){
            uint32_t af[MT][4];
            #pragma unroll
            for (int i=0;i<MT;i++){
                float4 a = As4[((warp_m*MT+i)*4 + ks)*32 + lane];
                af[i][0]=__float_as_uint(a.x); af[i][1]=__float_as_uint(a.y);
                af[i][2]=__float_as_uint(a.z); af[i][3]=__float_as_uint(a.w);
            }
            uint32_t bf[4][2];
            #pragma unroll
            for (int j=0;j<4;j++){
                float2 b = Bs2[((warp_n*4+j)*4 + ks)*32 + lane];
                bf[j][0]=__float_as_uint(b.x); bf[j][1]=__float_as_uint(b.y);
            }
            #pragma unroll
            for (int i=0;i<MT;i++)
                #pragma unroll
                for (int j=0;j<4;j++) mma8(acc[i][j], af[i], bf[j]);
        }
        if (more){
            store((kt+1)&1);
            __syncthreads();
        }
    }

    // ---- epilogue ----
    #pragma unroll
    for (int i=0;i<MT;i++){
        #pragma unroll
        for (int j=0;j<4;j++){
            int n = bn + warp_n*32 + j*8 + 2*(lane&3);
            if (NP && n >= Nout) continue;
            float2 bv = bias ? *(const float2*)(bias + n) : make_float2(0.f,0.f);
            #pragma unroll
            for (int half=0; half<2; half++){
                int m = bm + m0 + i*16 + (lane>>2) + half*8;
                float vx = acc[i][j][half*2+0] + bv.x;
                float vy = acc[i][j][half*2+1] + bv.y;
                size_t idx = (size_t)m*Nout + n;
                if (EPI == 1){
                    vx = gelu_f(vx); vy = gelu_f(vy);
                } else if (EPI == 2){
                    float2 r0 = *(const float2*)(e0 + idx);
                    float2 r1 = *(const float2*)(e1 + idx);
                    float2 r2 = *(const float2*)(e2 + idx);
                    float gx = 1.f/(1.f+__expf(-vx));
                    float gy = 1.f/(1.f+__expf(-vy));
                    vx = r0.x + gx*r1.x + (1.f-gx)*r2.x;
                    vy = r0.y + gy*r1.y + (1.f-gy)*r2.y;
                } else if (EPI == 3){
                    float2 r0 = *(const float2*)(e0 + idx);
                    vx += r0.x; vy += r0.y;
                }
                *(float2*)(C + idx) = make_float2(vx, vy);
            }
        }
    }
}

// ---------------- LayerNorm ----------------
__global__ void ln_kernel(const float* __restrict__ in, const float* __restrict__ g,
                          const float* __restrict__ b, float* __restrict__ out) {
    int warp = (blockIdx.x * blockDim.x + threadIdx.x) >> 5;
    int lane = threadIdx.x & 31;
    if (warp >= TOK) return;
    float4 v = ((const float4*)(in + (size_t)warp*128))[lane];
    float s = v.x+v.y+v.z+v.w;
    #pragma unroll
    for (int o=16;o;o>>=1) s += __shfl_xor_sync(~0u, s, o);
    float mean = s * (1.f/128.f);
    float dx=v.x-mean, dy=v.y-mean, dz=v.z-mean, dw=v.w-mean;
    float q = dx*dx+dy*dy+dz*dz+dw*dw;
    #pragma unroll
    for (int o=16;o;o>>=1) q += __shfl_xor_sync(~0u, q, o);
    float rstd = rsqrtf(q*(1.f/128.f) + 1e-5f);
    float4 gv = ((const float4*)g)[lane];
    float4 bv = ((const float4*)b)[lane];
    float4 ov;
    ov.x = dx*rstd*gv.x + bv.x;
    ov.y = dy*rstd*gv.y + bv.y;
    ov.z = dz*rstd*gv.z + bv.z;
    ov.w = dw*rstd*gv.w + bv.w;
    ((float4*)(out + (size_t)warp*128))[lane] = ov;
}

// ---------------- window attention ----------------
__global__ void attn_kernel(const float* __restrict__ rpb) {
    int w = blockIdx.x >> 2;
    int head = blockIdx.x & 3;
    int b = w >> 6, wh = (w >> 3) & 7, ww = w & 7;
    __shared__ float qs[49][32], ks[49][32], vs[49][32];
    __shared__ float sc[49][49];
    int tid = threadIdx.x;
    const float scale = 0.17677669529663689f;
    for (int i = tid; i < 49*32; i += 128) {
        int n = i >> 5, d = i & 31;
        int t = ((b*56 + wh*7 + n/7)*56 + ww*7 + n%7);
        const float* base = g_qkv + (size_t)t*384 + head*32 + d;
        qs[n][d] = base[0] * scale;
        ks[n][d] = base[128];
        vs[n][d] = base[256];
    }
    __syncthreads();
    for (int idx = tid; idx < 49*49; idx += 128) {
        int i = idx/49, j = idx%49;
        float s = 0.f;
        const float4* qp = (const float4*)qs[i];
        const float4* kp = (const float4*)ks[j];
        #pragma unroll
        for (int k=0;k<8;k++){ float4 a=qp[k], c=kp[k]; s += a.x*c.x+a.y*c.y+a.z*c.z+a.w*c.w; }
        int dr = i/7 - j/7 + 6, dc = i%7 - j%7 + 6;
        sc[i][j] = s + rpb[(dr*13+dc)*4 + head];
    }
    __syncthreads();
    if (tid < 49) {
        int i = tid;
        float m = -1e30f;
        for (int j=0;j<49;j++) m = fmaxf(m, sc[i][j]);
        float sum = 0.f;
        for (int j=0;j<49;j++){ float e=__expf(sc[i][j]-m); sc[i][j]=e; sum+=e; }
        float inv = 1.f/sum;
        for (int j=0;j<49;j++) sc[i][j] *= inv;
    }
    __syncthreads();
    for (int idx = tid; idx < 49*32; idx += 128) {
        int i = idx >> 5, d = idx & 31;
        float o = 0.f;
        for (int j=0;j<49;j++) o += sc[i][j]*vs[j][d];
        int t = ((b*56 + wh*7 + i/7)*56 + ww*7 + i%7);
        g_awb[(size_t)t*128 + head*32 + d] = o;
    }
}

// ---------------- causal depthwise conv + SiLU ----------------
__global__ void conv_kernel(const float* __restrict__ cw, const float* __restrict__ cb) {
    int idx = blockIdx.x*blockDim.x + threadIdx.x;
    if (idx >= TOK*256) return;
    int t = idx >> 8, d = idx & 255;
    int b = t / LSEQ, l = t % LSEQ;
    float acc = cb[d];
    #pragma unroll
    for (int j=0;j<4;j++){
        int ll = l - 3 + j;
        if (ll >= 0) acc = fmaf(cw[d*4+j], g_xz[((size_t)(b*LSEQ+ll))*512 + d], acc);
    }
    float sg = 1.f/(1.f+__expf(-acc));
    g_xc[idx] = acc * sg;
}

// ---------------- dt_proj + softplus ----------------
__global__ void dtproj_kernel(const float* __restrict__ wt, const float* __restrict__ bias){
    int idx = blockIdx.x*blockDim.x + threadIdx.x;
    if (idx >= TOK*256) return;
    int t = idx >> 8, d = idx & 255;
    float acc = bias[d];
    const float* r = g_dbl + (size_t)t*40;
    const float* wr = wt + d*8;
    #pragma unroll
    for (int k=0;k<8;k++) acc = fmaf(r[k], wr[k], acc);
    float sp = (acc > 20.f) ? acc : log1pf(__expf(acc));
    g_dt[idx] = sp;
}

// ============ chunk-parallel selective scan ============
__global__ __launch_bounds__(256) void scan_phase1(const float* __restrict__ A_log){
    int gw = (blockIdx.x*blockDim.x + threadIdx.x) >> 5;
    int lane = threadIdx.x & 31;
    int dpair = gw & 127;
    int chunk = (gw >> 7) % NCH;
    int b = gw / (128*NCH);
    int d = dpair*2 + (lane >> 4);
    int s = lane & 15;
    float Aval = -__expf(A_log[d*16 + s]);
    float h = 0.f, sd = 0.f;
    int t0 = b*LSEQ + chunk*CH;
    for (int g = 0; g < CH; g += 8) {
        float dtv[8], xcv[8], Bv[8];
        #pragma unroll
        for (int u=0;u<8;u++){
            int t = t0 + g + u;
            dtv[u] = g_dt[(size_t)t*256 + d];
            xcv[u] = g_xc[(size_t)t*256 + d];
            Bv[u]  = g_dbl[(size_t)t*40 + 8 + s];
        }
        #pragma unroll
        for (int u=0;u<8;u++){
            sd += dtv[u];
            float a = __expf(dtv[u]*Aval);
            h = a*h + dtv[u]*Bv[u]*xcv[u];
        }
    }
    size_t hidx = ((size_t)(b*NCH + chunk)*256 + d)*16 + s;
    g_hend[hidx] = h;
    if (s == 0) g_sumdt[(b*NCH + chunk)*256 + d] = sd;
}

__global__ __launch_bounds__(256) void scan_phase2(const float* __restrict__ A_log){
    int gw = (blockIdx.x*blockDim.x + threadIdx.x) >> 5;
    int lane = threadIdx.x & 31;
    int b = gw >> 7;
    int dpair = gw & 127;
    int d = dpair*2 + (lane >> 4);
    int s = lane & 15;
    float Aval = -__expf(A_log[d*16 + s]);
    float h = 0.f;
    for (int c = 0; c < NCH; c++) {
        size_t hidx = ((size_t)(b*NCH + c)*256 + d)*16 + s;
        g_hin[hidx] = h;
        float sd = g_sumdt[(b*NCH + c)*256 + d];
        h = __expf(Aval*sd)*h + g_hend[hidx];
    }
}

__global__ __launch_bounds__(256) void scan_phase3(const float* __restrict__ A_log,
                                                   const float* __restrict__ Dp){
    __shared__ float part[8*32*33];
    int warp = threadIdx.x >> 5, lane = threadIdx.x & 31;
    int gw = blockIdx.x * 8 + warp;
    int dpair = gw & 127;
    int chunk = (gw >> 7) % NCH;
    int b = gw / (128*NCH);
    int dbase = dpair*2;
    int d = dbase + (lane >> 4);
    int s = lane & 15;
    float Aval = -__expf(A_log[d*16 + s]);
    float dp0 = Dp[dbase], dp1 = Dp[dbase+1];
    size_t hidx = ((size_t)(b*NCH + chunk)*256 + d)*16 + s;
    float h = g_hin[hidx];
    float* pp = part + warp*32*33 + lane*33;
    float* wp = part + warp*32*33;
    int tb = b*LSEQ + chunk*CH;
    #pragma unroll 1
    for (int half = 0; half < 2; half++) {
        int base = half*32;
        #pragma unroll 1
        for (int g = 0; g < 32; g += 8) {
            float dtv[8], xcv[8], Bv[8], Cv[8];
            #pragma unroll
            for (int u=0;u<8;u++){
                int t = tb + base + g + u;
                dtv[u] = g_dt[(size_t)t*256 + d];
                xcv[u] = g_xc[(size_t)t*256 + d];
                Bv[u]  = g_dbl[(size_t)t*40 + 8 + s];
                Cv[u]  = g_dbl[(size_t)t*40 + 24 + s];
            }
            #pragma unroll
            for (int u=0;u<8;u++){
                float a = __expf(dtv[u]*Aval);
                h = a*h + dtv[u]*Bv[u]*xcv[u];
                pp[g+u] = h * Cv[u];
            }
        }
        __syncwarp();
        {
            int lu = lane;
            int t = tb + base + lu;
            #pragma unroll
            for (int c2=0;c2<2;c2++){
                float ys = 0.f;
                #pragma unroll
                for (int ss=0; ss<16; ss++) ys += wp[(c2*16+ss)*33 + lu];
                int d2 = dbase + c2;
                float xcv2 = g_xc[(size_t)t*256 + d2];
                float zv = g_xz[(size_t)t*512 + 256 + d2];
                float yv = ys + xcv2 * (c2 ? dp1 : dp0);
                float sg = 1.f/(1.f+__expf(-zv));
                g_y[(size_t)t*256 + d2] = yv * zv * sg;
            }
        }
        __syncwarp();
    }
}

// ---------------- launch ----------------
extern "C" void kernel_launch(void* const* d_in, const int* in_sizes, int n_in,
                              void* d_out, int out_size) {
    const float* x        = (const float*)d_in[0];
    const float* ln1_g    = (const float*)d_in[1];
    const float* ln1_b    = (const float*)d_in[2];
    const float* qkv_w    = (const float*)d_in[3];
    const float* qkv_b    = (const float*)d_in[4];
    const float* rpb      = (const float*)d_in[5];
    const float* proj_w   = (const float*)d_in[6];
    const float* proj_b   = (const float*)d_in[7];
    const float* in_w     = (const float*)d_in[8];
    const float* in_b     = (const float*)d_in[9];
    const float* conv_w   = (const float*)d_in[10];
    const float* conv_b   = (const float*)d_in[11];
    const float* xproj_w  = (const float*)d_in[12];
    const float* dtw      = (const float*)d_in[13];
    const float* dtb      = (const float*)d_in[14];
    const float* A_log    = (const float*)d_in[15];
    const float* Dp       = (const float*)d_in[16];
    const float* out_w    = (const float*)d_in[17];
    const float* out_b    = (const float*)d_in[18];
    const float* gate_w   = (const float*)d_in[19];
    const float* gate_b   = (const float*)d_in[20];
    const float* ln2_g    = (const float*)d_in[21];
    const float* ln2_b    = (const float*)d_in[22];
    const float* mlp_w1   = (const float*)d_in[23];
    const float* mlp_b1   = (const float*)d_in[24];
    const float* mlp_w2   = (const float*)d_in[25];
    const float* mlp_b2   = (const float*)d_in[26];
    float* out = (float*)d_out;

    float *xn, *qkv, *awb, *attn, *xz, *y, *mamba, *x1, *h2, *hid, *xc, *dbl;
    cudaGetSymbolAddress((void**)&xn,    g_xn);
    cudaGetSymbolAddress((void**)&qkv,   g_qkv);
    cudaGetSymbolAddress((void**)&awb,   g_awb);
    cudaGetSymbolAddress((void**)&attn,  g_attn);
    cudaGetSymbolAddress((void**)&xz,    g_xz);
    cudaGetSymbolAddress((void**)&y,     g_y);
    cudaGetSymbolAddress((void**)&mamba, g_mamba);
    cudaGetSymbolAddress((void**)&x1,    g_x1);
    cudaGetSymbolAddress((void**)&h2,    g_h2);
    cudaGetSymbolAddress((void**)&hid,   g_hid);
    cudaGetSymbolAddress((void**)&xc,    g_xc);
    cudaGetSymbolAddress((void**)&dbl,   g_dbl);

    const int SM64  = 2*(2048 + 64*32)*4;    // 32 KB
    const int SM128 = 2*(2048 + 128*32)*4;   // 48 KB
    cudaFuncSetAttribute(mma_gemm<128,0,0,0>, cudaFuncAttributeMaxDynamicSharedMemorySize, SM128);
    cudaFuncSetAttribute(mma_gemm<128,1,0,0>, cudaFuncAttributeMaxDynamicSharedMemorySize, SM128);
    cudaFuncSetAttribute(mma_gemm<64,0,0,0>,  cudaFuncAttributeMaxDynamicSharedMemorySize, SM64);
    cudaFuncSetAttribute(mma_gemm<64,0,0,1>,  cudaFuncAttributeMaxDynamicSharedMemorySize, SM64);
    cudaFuncSetAttribute(mma_gemm<64,2,1,0>,  cudaFuncAttributeMaxDynamicSharedMemorySize, SM64);
    cudaFuncSetAttribute(mma_gemm<64,3,0,0>,  cudaFuncAttributeMaxDynamicSharedMemorySize, SM64);

    // LN1
    ln_kernel<<<TOK/8, 256>>>(x, ln1_g, ln1_b, xn);
    // qkv GEMM (N=384, K=128)
    mma_gemm<128,0,0,0><<<dim3(3,196), 256, SM128>>>(xn, qkv_w, qkv_b, qkv, 384, 128, nullptr, nullptr, nullptr);
    // window attention
    attn_kernel<<<NWIN*4, 128>>>(rpb);
    // proj GEMM (N=128, K=128) -> attn_out
    mma_gemm<64,0,0,0><<<dim3(2,196), 256, SM64>>>(awb, proj_w, proj_b, attn, 128, 128, nullptr, nullptr, nullptr);
    // in_proj GEMM (N=512, K=128) -> xz
    mma_gemm<128,0,0,0><<<dim3(4,196), 256, SM128>>>(xn, in_w, in_b, xz, 512, 128, nullptr, nullptr, nullptr);
    // causal conv + silu -> xc
    conv_kernel<<<TOK, 256>>>(conv_w, conv_b);
    // x_proj GEMM (N=40 pad 64, K=256) -> dbl
    mma_gemm<64,0,0,1><<<dim3(1,196), 256, SM64>>>(xc, xproj_w, nullptr, dbl, 40, 256, nullptr, nullptr, nullptr);
    // dt_proj + softplus -> dt
    dtproj_kernel<<<TOK, 256>>>(dtw, dtb);
    // chunk-parallel selective scan
    scan_phase1<<<(BATCH*NCH*128)/8, 256>>>(A_log);
    scan_phase2<<<64, 256>>>(A_log);
    scan_phase3<<<(BATCH*NCH*128)/8, 256>>>(A_log, Dp);
    // out_proj GEMM (N=128, K=256) -> mamba
    mma_gemm<64,0,0,0><<<dim3(2,196), 256, SM64>>>(y, out_w, out_b, mamba, 128, 256, nullptr, nullptr, nullptr);
    // gate GEMM (A=[attn|mamba], K=256) + fused blend + residual -> x1
    mma_gemm<64,2,1,0><<<dim3(2,196), 256, SM64>>>(nullptr, gate_w, gate_b, x1, 128, 256, x, attn, mamba);
    // LN2
    ln_kernel<<<TOK/8, 256>>>(x1, ln2_g, ln2_b, h2);
    // MLP1 + gelu (N=512, K=128)
    mma_gemm<128,1,0,0><<<dim3(4,196), 256, SM128>>>(h2, mlp_w1, mlp_b1, hid, 512, 128, nullptr, nullptr, nullptr);
    // MLP2 + residual (N=128, K=512) -> out
    mma_gemm<64,3,0,0><<<dim3(2,196), 256, SM64>>>(hid, mlp_w2, mlp_b2, out, 128, 512, x1, nullptr, nullptr);

    (void)in_sizes; (void)n_in; (void)out_size;
}

// round 7
// speedup vs baseline: 1.8320x; 1.1975x over previous
#include <cuda_runtime.h>
#include <math.h>
#include <stdint.h>

#define TOK   12544
#define BATCH 4
#define LSEQ  3136
#define NWIN  256
#define NCH   49
#define CH    64

// ---------------- scratch ----------------
__device__ float g_xn[TOK*128];
__device__ float g_qkv[TOK*384];
__device__ float g_awb[TOK*128];
__device__ float g_attn[TOK*128];
__device__ float g_xz[TOK*512];
__device__ float g_xc[TOK*256];
__device__ float g_dbl[TOK*40];
__device__ float g_dt[TOK*256];
__device__ float g_y[TOK*256];
__device__ float g_mamba[TOK*128];
__device__ float g_x1[TOK*128];
__device__ float g_h2[TOK*128];
__device__ float g_hid[TOK*512];
__device__ float g_hend[BATCH*NCH*256*16];
__device__ float g_hin[BATCH*NCH*256*16];
__device__ float g_sumdt[BATCH*NCH*256];

__device__ __forceinline__ float gelu_f(float x){ return 0.5f*x*(1.f+erff(x*0.70710678118f)); }
__device__ __forceinline__ uint32_t smem_u32(const void* p){
    uint32_t a; asm("{ .reg .u64 t; cvta.to.shared.u64 t, %1; cvt.u32.u64 %0, t; }" : "=r"(a) : "l"(p)); return a;
}
__device__ __forceinline__ void cpa16(uint32_t dst, const void* src){
    asm volatile("cp.async.cg.shared.global [%0], [%1], 16;" :: "r"(dst), "l"(src));
}
__device__ __forceinline__ void cpa16z(uint32_t dst, const void* src){
    asm volatile("cp.async.cg.shared.global [%0], [%1], 16, 0;" :: "r"(dst), "l"(src));
}
__device__ __forceinline__ void mma8(float* c, const uint32_t* a, const uint32_t* b){
    asm volatile("mma.sync.aligned.m16n8k8.row.col.f32.tf32.tf32.f32 "
        "{%0,%1,%2,%3}, {%4,%5,%6,%7}, {%8,%9}, {%0,%1,%2,%3};"
        : "+f"(c[0]),"+f"(c[1]),"+f"(c[2]),"+f"(c[3])
        : "r"(a[0]),"r"(a[1]),"r"(a[2]),"r"(a[3]), "r"(b[0]),"r"(b[1]));
}

// ================= cp.async pipelined tf32 mma GEMM =================
// C[M,Nout] = A[M,K] @ W[Nout,K]^T (+bias, epilogue). CTA tile 64 x NT, Ktile 32.
// 256 threads / 8 warps. 3-stage cp.async pipeline, XOR-swizzled smem.
// EPI: 0 none, 1 gelu, 2 gate-fuse (e0=x,e1=attn,e2=mamba), 3 residual(e0)
// AG: A gathered as [e1|e2] (K==256). NP: W rows / C cols >= Nout zero/skipped.
template<int NT, int EPI, int AG, int NP>
__global__ __launch_bounds__(256)
void mma_gemm(const float* __restrict__ A, const float* __restrict__ W,
              const float* __restrict__ bias, float* __restrict__ C,
              int Nout, int K,
              const float* __restrict__ e0, const float* __restrict__ e1,
              const float* __restrict__ e2)
{
    extern __shared__ float sm[];
    const int NW  = NT/32;            // warps along N
    const int MW  = 8/NW;             // warps along M
    const int MT  = 64/(16*MW);       // m16 frags per warp
    const int STG = 2048 + NT*32;     // floats per stage
    const int BCH = (NT*8)/256;       // B 16B-chunks per thread
    uint32_t sbase = smem_u32(sm);
    int tid = threadIdx.x, wid = tid>>5, lane = tid&31;
    int warp_n = wid % NW, warp_m = wid / NW;
    int bm = blockIdx.y*64, bn = blockIdx.x*NT;
    int m0 = warp_m * MT * 16;

    float acc[MT][4][4];
    #pragma unroll
    for (int i=0;i<MT;i++)
        #pragma unroll
        for (int j=0;j<4;j++)
            #pragma unroll
            for (int q=0;q<4;q++) acc[i][j][q]=0.f;

    auto issue = [&](int kt){
        int st = kt % 3;
        uint32_t abase = sbase + (uint32_t)st*STG*4;
        uint32_t bbase = abase + 2048*4;
        int kc = kt*32;
        #pragma unroll
        for (int i=0;i<2;i++){
            int ch = tid + i*256;
            int row = ch>>3, col = (ch&7)*4;
            uint32_t dst = abase + (uint32_t)(row*32 + (col ^ ((row&7)<<2)))*4;
            const float* src;
            if (AG){
                int kg = kc + col;
                src = (kg<128) ? e1 + (size_t)(bm+row)*128 + kg
                               : e2 + (size_t)(bm+row)*128 + (kg-128);
            } else {
                src = A + (size_t)(bm+row)*K + kc + col;
            }
            cpa16(dst, src);
        }
        #pragma unroll
        for (int i=0;i<BCH;i++){
            int ch = tid + i*256;
            int row = ch>>3, col = (ch&7)*4;
            uint32_t dst = bbase + (uint32_t)(row*32 + (col ^ ((row&7)<<2)))*4;
            if (NP && (bn+row) >= Nout) cpa16z(dst, W);
            else cpa16(dst, W + (size_t)(bn+row)*K + kc + col);
        }
        asm volatile("cp.async.commit_group;" ::: "memory");
    };

    int KT = K >> 5;
    issue(0);
    issue(1);

    for (int kt=0; kt<KT; kt++){
        if (kt == KT-1) asm volatile("cp.async.wait_group 0;" ::: "memory");
        else            asm volatile("cp.async.wait_group 1;" ::: "memory");
        __syncthreads();
        if (kt+2 < KT) issue(kt+2);

        const float* As = sm + (kt%3)*STG;
        const float* Bs = As + 2048;
        #pragma unroll
        for (int ks=0; ks<4; ks++){
            uint32_t af[MT][4];
            #pragma unroll
            for (int i=0;i<MT;i++){
                int r0 = m0 + i*16 + (lane>>2);
                int sw = (r0&7)<<2;
                int c0 = ks*8 + (lane&3);
                af[i][0] = __float_as_uint(As[r0*32     + (c0^sw)]);
                af[i][1] = __float_as_uint(As[(r0+8)*32 + (c0^sw)]);
                af[i][2] = __float_as_uint(As[r0*32     + ((c0+4)^sw)]);
                af[i][3] = __float_as_uint(As[(r0+8)*32 + ((c0+4)^sw)]);
            }
            uint32_t bf[4][2];
            #pragma unroll
            for (int j=0;j<4;j++){
                int n = warp_n*32 + j*8 + (lane>>2);
                int sw = (n&7)<<2;
                int k0 = ks*8 + (lane&3);
                bf[j][0] = __float_as_uint(Bs[n*32 + (k0^sw)]);
                bf[j][1] = __float_as_uint(Bs[n*32 + ((k0+4)^sw)]);
            }
            #pragma unroll
            for (int i=0;i<MT;i++)
                #pragma unroll
                for (int j=0;j<4;j++) mma8(acc[i][j], af[i], bf[j]);
        }
    }

    // ---- epilogue ----
    #pragma unroll
    for (int i=0;i<MT;i++){
        #pragma unroll
        for (int j=0;j<4;j++){
            int n = bn + warp_n*32 + j*8 + 2*(lane&3);
            if (NP && n >= Nout) continue;
            float2 bv = bias ? *(const float2*)(bias + n) : make_float2(0.f,0.f);
            #pragma unroll
            for (int half=0; half<2; half++){
                int m = bm + m0 + i*16 + (lane>>2) + half*8;
                float vx = acc[i][j][half*2+0] + bv.x;
                float vy = acc[i][j][half*2+1] + bv.y;
                size_t idx = (size_t)m*Nout + n;
                if (EPI == 1){
                    vx = gelu_f(vx); vy = gelu_f(vy);
                } else if (EPI == 2){
                    float2 r0 = *(const float2*)(e0 + idx);
                    float2 r1 = *(const float2*)(e1 + idx);
                    float2 r2 = *(const float2*)(e2 + idx);
                    float gx = 1.f/(1.f+__expf(-vx));
                    float gy = 1.f/(1.f+__expf(-vy));
                    vx = r0.x + gx*r1.x + (1.f-gx)*r2.x;
                    vy = r0.y + gy*r1.y + (1.f-gy)*r2.y;
                } else if (EPI == 3){
                    float2 r0 = *(const float2*)(e0 + idx);
                    vx += r0.x; vy += r0.y;
                }
                *(float2*)(C + idx) = make_float2(vx, vy);
            }
        }
    }
}

// ---------------- LayerNorm ----------------
__global__ void ln_kernel(const float* __restrict__ in, const float* __restrict__ g,
                          const float* __restrict__ b, float* __restrict__ out) {
    int warp = (blockIdx.x * blockDim.x + threadIdx.x) >> 5;
    int lane = threadIdx.x & 31;
    if (warp >= TOK) return;
    float4 v = ((const float4*)(in + (size_t)warp*128))[lane];
    float s = v.x+v.y+v.z+v.w;
    #pragma unroll
    for (int o=16;o;o>>=1) s += __shfl_xor_sync(~0u, s, o);
    float mean = s * (1.f/128.f);
    float dx=v.x-mean, dy=v.y-mean, dz=v.z-mean, dw=v.w-mean;
    float q = dx*dx+dy*dy+dz*dz+dw*dw;
    #pragma unroll
    for (int o=16;o;o>>=1) q += __shfl_xor_sync(~0u, q, o);
    float rstd = rsqrtf(q*(1.f/128.f) + 1e-5f);
    float4 gv = ((const float4*)g)[lane];
    float4 bv = ((const float4*)b)[lane];
    float4 ov;
    ov.x = dx*rstd*gv.x + bv.x;
    ov.y = dy*rstd*gv.y + bv.y;
    ov.z = dz*rstd*gv.z + bv.z;
    ov.w = dw*rstd*gv.w + bv.w;
    ((float4*)(out + (size_t)warp*128))[lane] = ov;
}

// ---------------- window attention ----------------
__global__ void attn_kernel(const float* __restrict__ rpb) {
    int w = blockIdx.x >> 2;
    int head = blockIdx.x & 3;
    int b = w >> 6, wh = (w >> 3) & 7, ww = w & 7;
    __shared__ float qs[49][32], ks[49][32], vs[49][32];
    __shared__ float sc[49][49];
    int tid = threadIdx.x;
    const float scale = 0.17677669529663689f;
    for (int i = tid; i < 49*32; i += 128) {
        int n = i >> 5, d = i & 31;
        int t = ((b*56 + wh*7 + n/7)*56 + ww*7 + n%7);
        const float* base = g_qkv + (size_t)t*384 + head*32 + d;
        qs[n][d] = base[0] * scale;
        ks[n][d] = base[128];
        vs[n][d] = base[256];
    }
    __syncthreads();
    for (int idx = tid; idx < 49*49; idx += 128) {
        int i = idx/49, j = idx%49;
        float s = 0.f;
        const float4* qp = (const float4*)qs[i];
        const float4* kp = (const float4*)ks[j];
        #pragma unroll
        for (int k=0;k<8;k++){ float4 a=qp[k], c=kp[k]; s += a.x*c.x+a.y*c.y+a.z*c.z+a.w*c.w; }
        int dr = i/7 - j/7 + 6, dc = i%7 - j%7 + 6;
        sc[i][j] = s + rpb[(dr*13+dc)*4 + head];
    }
    __syncthreads();
    if (tid < 49) {
        int i = tid;
        float m = -1e30f;
        for (int j=0;j<49;j++) m = fmaxf(m, sc[i][j]);
        float sum = 0.f;
        for (int j=0;j<49;j++){ float e=__expf(sc[i][j]-m); sc[i][j]=e; sum+=e; }
        float inv = 1.f/sum;
        for (int j=0;j<49;j++) sc[i][j] *= inv;
    }
    __syncthreads();
    for (int idx = tid; idx < 49*32; idx += 128) {
        int i = idx >> 5, d = idx & 31;
        float o = 0.f;
        for (int j=0;j<49;j++) o += sc[i][j]*vs[j][d];
        int t = ((b*56 + wh*7 + i/7)*56 + ww*7 + i%7);
        g_awb[(size_t)t*128 + head*32 + d] = o;
    }
}

// ---------------- causal depthwise conv + SiLU ----------------
__global__ void conv_kernel(const float* __restrict__ cw, const float* __restrict__ cb) {
    int idx = blockIdx.x*blockDim.x + threadIdx.x;
    if (idx >= TOK*256) return;
    int t = idx >> 8, d = idx & 255;
    int b = t / LSEQ, l = t % LSEQ;
    float acc = cb[d];
    #pragma unroll
    for (int j=0;j<4;j++){
        int ll = l - 3 + j;
        if (ll >= 0) acc = fmaf(cw[d*4+j], g_xz[((size_t)(b*LSEQ+ll))*512 + d], acc);
    }
    float sg = 1.f/(1.f+__expf(-acc));
    g_xc[idx] = acc * sg;
}

// ---------------- dt_proj + softplus ----------------
__global__ void dtproj_kernel(const float* __restrict__ wt, const float* __restrict__ bias){
    int idx = blockIdx.x*blockDim.x + threadIdx.x;
    if (idx >= TOK*256) return;
    int t = idx >> 8, d = idx & 255;
    float acc = bias[d];
    const float* r = g_dbl + (size_t)t*40;
    const float* wr = wt + d*8;
    #pragma unroll
    for (int k=0;k<8;k++) acc = fmaf(r[k], wr[k], acc);
    float sp = (acc > 20.f) ? acc : log1pf(__expf(acc));
    g_dt[idx] = sp;
}

// ============ chunk-parallel selective scan ============
__global__ __launch_bounds__(256) void scan_phase1(const float* __restrict__ A_log){
    int gw = (blockIdx.x*blockDim.x + threadIdx.x) >> 5;
    int lane = threadIdx.x & 31;
    int dpair = gw & 127;
    int chunk = (gw >> 7) % NCH;
    int b = gw / (128*NCH);
    int d = dpair*2 + (lane >> 4);
    int s = lane & 15;
    float Aval = -__expf(A_log[d*16 + s]);
    float h = 0.f, sd = 0.f;
    int t0 = b*LSEQ + chunk*CH;
    for (int g = 0; g < CH; g += 8) {
        float dtv[8], xcv[8], Bv[8];
        #pragma unroll
        for (int u=0;u<8;u++){
            int t = t0 + g + u;
            dtv[u] = g_dt[(size_t)t*256 + d];
            xcv[u] = g_xc[(size_t)t*256 + d];
            Bv[u]  = g_dbl[(size_t)t*40 + 8 + s];
        }
        #pragma unroll
        for (int u=0;u<8;u++){
            sd += dtv[u];
            float a = __expf(dtv[u]*Aval);
            h = a*h + dtv[u]*Bv[u]*xcv[u];
        }
    }
    size_t hidx = ((size_t)(b*NCH + chunk)*256 + d)*16 + s;
    g_hend[hidx] = h;
    if (s == 0) g_sumdt[(b*NCH + chunk)*256 + d] = sd;
}

__global__ __launch_bounds__(256) void scan_phase2(const float* __restrict__ A_log){
    int gw = (blockIdx.x*blockDim.x + threadIdx.x) >> 5;
    int lane = threadIdx.x & 31;
    int b = gw >> 7;
    int dpair = gw & 127;
    int d = dpair*2 + (lane >> 4);
    int s = lane & 15;
    float Aval = -__expf(A_log[d*16 + s]);
    float h = 0.f;
    for (int c = 0; c < NCH; c++) {
        size_t hidx = ((size_t)(b*NCH + c)*256 + d)*16 + s;
        g_hin[hidx] = h;
        float sd = g_sumdt[(b*NCH + c)*256 + d];
        h = __expf(Aval*sd)*h + g_hend[hidx];
    }
}

__global__ __launch_bounds__(256) void scan_phase3(const float* __restrict__ A_log,
                                                   const float* __restrict__ Dp){
    __shared__ float part[8*32*33];
    int warp = threadIdx.x >> 5, lane = threadIdx.x & 31;
    int gw = blockIdx.x * 8 + warp;
    int dpair = gw & 127;
    int chunk = (gw >> 7) % NCH;
    int b = gw / (128*NCH);
    int dbase = dpair*2;
    int d = dbase + (lane >> 4);
    int s = lane & 15;
    float Aval = -__expf(A_log[d*16 + s]);
    float dp0 = Dp[dbase], dp1 = Dp[dbase+1];
    size_t hidx = ((size_t)(b*NCH + chunk)*256 + d)*16 + s;
    float h = g_hin[hidx];
    float* pp = part + warp*32*33 + lane*33;
    float* wp = part + warp*32*33;
    int tb = b*LSEQ + chunk*CH;
    #pragma unroll 1
    for (int half = 0; half < 2; half++) {
        int base = half*32;
        #pragma unroll 1
        for (int g = 0; g < 32; g += 8) {
            float dtv[8], xcv[8], Bv[8], Cv[8];
            #pragma unroll
            for (int u=0;u<8;u++){
                int t = tb + base + g + u;
                dtv[u] = g_dt[(size_t)t*256 + d];
                xcv[u] = g_xc[(size_t)t*256 + d];
                Bv[u]  = g_dbl[(size_t)t*40 + 8 + s];
                Cv[u]  = g_dbl[(size_t)t*40 + 24 + s];
            }
            #pragma unroll
            for (int u=0;u<8;u++){
                float a = __expf(dtv[u]*Aval);
                h = a*h + dtv[u]*Bv[u]*xcv[u];
                pp[g+u] = h * Cv[u];
            }
        }
        __syncwarp();
        {
            int lu = lane;
            int t = tb + base + lu;
            #pragma unroll
            for (int c2=0;c2<2;c2++){
                float ys = 0.f;
                #pragma unroll
                for (int ss=0; ss<16; ss++) ys += wp[(c2*16+ss)*33 + lu];
                int d2 = dbase + c2;
                float xcv2 = g_xc[(size_t)t*256 + d2];
                float zv = g_xz[(size_t)t*512 + 256 + d2];
                float yv = ys + xcv2 * (c2 ? dp1 : dp0);
                float sg = 1.f/(1.f+__expf(-zv));
                g_y[(size_t)t*256 + d2] = yv * zv * sg;
            }
        }
        __syncwarp();
    }
}

// ---------------- launch ----------------
extern "C" void kernel_launch(void* const* d_in, const int* in_sizes, int n_in,
                              void* d_out, int out_size) {
    const float* x        = (const float*)d_in[0];
    const float* ln1_g    = (const float*)d_in[1];
    const float* ln1_b    = (const float*)d_in[2];
    const float* qkv_w    = (const float*)d_in[3];
    const float* qkv_b    = (const float*)d_in[4];
    const float* rpb      = (const float*)d_in[5];
    const float* proj_w   = (const float*)d_in[6];
    const float* proj_b   = (const float*)d_in[7];
    const float* in_w     = (const float*)d_in[8];
    const float* in_b     = (const float*)d_in[9];
    const float* conv_w   = (const float*)d_in[10];
    const float* conv_b   = (const float*)d_in[11];
    const float* xproj_w  = (const float*)d_in[12];
    const float* dtw      = (const float*)d_in[13];
    const float* dtb      = (const float*)d_in[14];
    const float* A_log    = (const float*)d_in[15];
    const float* Dp       = (const float*)d_in[16];
    const float* out_w    = (const float*)d_in[17];
    const float* out_b    = (const float*)d_in[18];
    const float* gate_w   = (const float*)d_in[19];
    const float* gate_b   = (const float*)d_in[20];
    const float* ln2_g    = (const float*)d_in[21];
    const float* ln2_b    = (const float*)d_in[22];
    const float* mlp_w1   = (const float*)d_in[23];
    const float* mlp_b1   = (const float*)d_in[24];
    const float* mlp_w2   = (const float*)d_in[25];
    const float* mlp_b2   = (const float*)d_in[26];
    float* out = (float*)d_out;

    float *xn, *qkv, *awb, *attn, *xz, *y, *mamba, *x1, *h2, *hid, *xc, *dbl;
    cudaGetSymbolAddress((void**)&xn,    g_xn);
    cudaGetSymbolAddress((void**)&qkv,   g_qkv);
    cudaGetSymbolAddress((void**)&awb,   g_awb);
    cudaGetSymbolAddress((void**)&attn,  g_attn);
    cudaGetSymbolAddress((void**)&xz,    g_xz);
    cudaGetSymbolAddress((void**)&y,     g_y);
    cudaGetSymbolAddress((void**)&mamba, g_mamba);
    cudaGetSymbolAddress((void**)&x1,    g_x1);
    cudaGetSymbolAddress((void**)&h2,    g_h2);
    cudaGetSymbolAddress((void**)&hid,   g_hid);
    cudaGetSymbolAddress((void**)&xc,    g_xc);
    cudaGetSymbolAddress((void**)&dbl,   g_dbl);

    const int SM64  = 3*(2048 + 64*32)*4;    // 48 KB
    const int SM128 = 3*(2048 + 128*32)*4;   // 72 KB
    cudaFuncSetAttribute(mma_gemm<128,0,0,0>, cudaFuncAttributeMaxDynamicSharedMemorySize, SM128);
    cudaFuncSetAttribute(mma_gemm<128,1,0,0>, cudaFuncAttributeMaxDynamicSharedMemorySize, SM128);
    cudaFuncSetAttribute(mma_gemm<64,0,0,0>,  cudaFuncAttributeMaxDynamicSharedMemorySize, SM64);
    cudaFuncSetAttribute(mma_gemm<64,0,0,1>,  cudaFuncAttributeMaxDynamicSharedMemorySize, SM64);
    cudaFuncSetAttribute(mma_gemm<64,2,1,0>,  cudaFuncAttributeMaxDynamicSharedMemorySize, SM64);
    cudaFuncSetAttribute(mma_gemm<64,3,0,0>,  cudaFuncAttributeMaxDynamicSharedMemorySize, SM64);

    // LN1
    ln_kernel<<<TOK/8, 256>>>(x, ln1_g, ln1_b, xn);
    // qkv GEMM (N=384, K=128)
    mma_gemm<128,0,0,0><<<dim3(3,196), 256, SM128>>>(xn, qkv_w, qkv_b, qkv, 384, 128, nullptr, nullptr, nullptr);
    // window attention
    attn_kernel<<<NWIN*4, 128>>>(rpb);
    // proj GEMM (N=128, K=128) -> attn_out
    mma_gemm<64,0,0,0><<<dim3(2,196), 256, SM64>>>(awb, proj_w, proj_b, attn, 128, 128, nullptr, nullptr, nullptr);
    // in_proj GEMM (N=512, K=128) -> xz
    mma_gemm<128,0,0,0><<<dim3(4,196), 256, SM128>>>(xn, in_w, in_b, xz, 512, 128, nullptr, nullptr, nullptr);
    // causal conv + silu -> xc
    conv_kernel<<<TOK, 256>>>(conv_w, conv_b);
    // x_proj GEMM (N=40 pad 64, K=256) -> dbl
    mma_gemm<64,0,0,1><<<dim3(1,196), 256, SM64>>>(xc, xproj_w, nullptr, dbl, 40, 256, nullptr, nullptr, nullptr);
    // dt_proj + softplus -> dt
    dtproj_kernel<<<TOK, 256>>>(dtw, dtb);
    // chunk-parallel selective scan
    scan_phase1<<<(BATCH*NCH*128)/8, 256>>>(A_log);
    scan_phase2<<<64, 256>>>(A_log);
    scan_phase3<<<(BATCH*NCH*128)/8, 256>>>(A_log, Dp);
    // out_proj GEMM (N=128, K=256) -> mamba
    mma_gemm<64,0,0,0><<<dim3(2,196), 256, SM64>>>(y, out_w, out_b, mamba, 128, 256, nullptr, nullptr, nullptr);
    // gate GEMM (A=[attn|mamba], K=256) + fused blend + residual -> x1
    mma_gemm<64,2,1,0><<<dim3(2,196), 256, SM64>>>(nullptr, gate_w, gate_b, x1, 128, 256, x, attn, mamba);
    // LN2
    ln_kernel<<<TOK/8, 256>>>(x1, ln2_g, ln2_b, h2);
    // MLP1 + gelu (N=512, K=128)
    mma_gemm<128,1,0,0><<<dim3(4,196), 256, SM128>>>(h2, mlp_w1, mlp_b1, hid, 512, 128, nullptr, nullptr, nullptr);
    // MLP2 + residual (N=128, K=512) -> out
    mma_gemm<64,3,0,0><<<dim3(2,196), 256, SM64>>>(hid, mlp_w2, mlp_b2, out, 128, 512, x1, nullptr, nullptr);

    (void)in_sizes; (void)n_in; (void)out_size;
}

// round 9
// speedup vs baseline: 1.8448x; 1.0070x over previous
#include <cuda_runtime.h>
#include <math.h>
#include <stdint.h>

#define TOK   12544
#define BATCH 4
#define LSEQ  3136
#define NWIN  256
#define NCH   49
#define CH    64

// ---------------- scratch ----------------
__device__ float g_xn[TOK*128];
__device__ float g_qkv[TOK*384];
__device__ float g_awb[TOK*128];
__device__ float g_attn[TOK*128];
__device__ float g_xz[TOK*512];
__device__ float g_xc[TOK*256];
__device__ float g_dbl[TOK*40];
__device__ float g_dt[TOK*256];
__device__ float g_y[TOK*256];
__device__ float g_mamba[TOK*128];
__device__ float g_x1[TOK*128];
__device__ float g_h2[TOK*128];
__device__ float g_hid[TOK*512];
__device__ float g_hend[BATCH*NCH*256*16];
__device__ float g_hin[BATCH*NCH*256*16];
__device__ float g_sumdt[BATCH*NCH*256];

__device__ __forceinline__ float gelu_f(float x){ return 0.5f*x*(1.f+erff(x*0.70710678118f)); }
__device__ __forceinline__ uint32_t smem_u32(const void* p){
    uint32_t a; asm("{ .reg .u64 t; cvta.to.shared.u64 t, %1; cvt.u32.u64 %0, t; }" : "=r"(a) : "l"(p)); return a;
}
__device__ __forceinline__ void cpa16(uint32_t dst, const void* src){
    asm volatile("cp.async.cg.shared.global [%0], [%1], 16;" :: "r"(dst), "l"(src));
}
__device__ __forceinline__ void cpa16z(uint32_t dst, const void* src){
    asm volatile("cp.async.cg.shared.global [%0], [%1], 16, 0;" :: "r"(dst), "l"(src));
}
__device__ __forceinline__ void ldsm4(uint32_t* d, uint32_t addr){
    asm volatile("ldmatrix.sync.aligned.m8n8.x4.shared.b16 {%0,%1,%2,%3}, [%4];"
        : "=r"(d[0]),"=r"(d[1]),"=r"(d[2]),"=r"(d[3]) : "r"(addr));
}
__device__ __forceinline__ void mma8(float* c, const uint32_t* a, const uint32_t* b){
    asm volatile("mma.sync.aligned.m16n8k8.row.col.f32.tf32.tf32.f32 "
        "{%0,%1,%2,%3}, {%4,%5,%6,%7}, {%8,%9}, {%0,%1,%2,%3};"
        : "+f"(c[0]),"+f"(c[1]),"+f"(c[2]),"+f"(c[3])
        : "r"(a[0]),"r"(a[1]),"r"(a[2]),"r"(a[3]), "r"(b[0]),"r"(b[1]));
}

// ================= cp.async + ldmatrix tf32 mma GEMM =================
// C[M,Nout] = A[M,K] @ W[Nout,K]^T (+bias, epilogue). CTA tile 64 x NT, Ktile 32.
// 256 threads / 8 warps. 3-stage cp.async pipeline, XOR-swizzled smem, LDSM frags.
// EPI: 0 none, 1 gelu, 2 gate-fuse (e0=x,e1=attn,e2=mamba), 3 residual(e0)
// AG: A gathered as [e1|e2] (K==256). NP: W rows / C cols >= Nout zero/skipped.
// QI: merged qkv+in_proj. W=qkv_w,bias=qkv_b,C=qkv(ld 384); e1=in_w,e2=in_b,e0=xz out(ld 512).
template<int NT, int EPI, int AG, int NP, int QI>
__global__ __launch_bounds__(256)
void mma_gemm(const float* __restrict__ A, const float* __restrict__ W,
              const float* __restrict__ bias, float* __restrict__ C,
              int Nout, int K,
              const float* __restrict__ e0, const float* __restrict__ e1,
              const float* __restrict__ e2)
{
    extern __shared__ float sm[];
    const int NW  = NT/32;            // warps along N
    const int MW  = 8/NW;             // warps along M
    const int MT  = 64/(16*MW);       // m16 frags per warp
    const int STG = 2048 + NT*32;     // floats per stage
    const int BCH = (NT*8)/256;       // B 16B-chunks per thread
    uint32_t sbase = smem_u32(sm);
    int tid = threadIdx.x, wid = tid>>5, lane = tid&31;
    int warp_n = wid % NW, warp_m = wid / NW;
    int bm = blockIdx.y*64, bn = blockIdx.x*NT;
    int m0 = warp_m * MT * 16;

    float acc[MT][4][4];
    #pragma unroll
    for (int i=0;i<MT;i++)
        #pragma unroll
        for (int j=0;j<4;j++)
            #pragma unroll
            for (int q=0;q<4;q++) acc[i][j][q]=0.f;

    auto issue = [&](int kt){
        int st = kt % 3;
        uint32_t abase = sbase + (uint32_t)st*STG*4;
        uint32_t bbase = abase + 2048*4;
        int kc = kt*32;
        #pragma unroll
        for (int i=0;i<2;i++){
            int ch = tid + i*256;
            int row = ch>>3, col = (ch&7)*4;
            uint32_t dst = abase + (uint32_t)(row*32 + (col ^ ((row&7)<<2)))*4;
            const float* src;
            if (AG){
                int kg = kc + col;
                src = (kg<128) ? e1 + (size_t)(bm+row)*128 + kg
                               : e2 + (size_t)(bm+row)*128 + (kg-128);
            } else {
                src = A + (size_t)(bm+row)*K + kc + col;
            }
            cpa16(dst, src);
        }
        #pragma unroll
        for (int i=0;i<BCH;i++){
            int ch = tid + i*256;
            int row = ch>>3, col = (ch&7)*4;
            uint32_t dst = bbase + (uint32_t)(row*32 + (col ^ ((row&7)<<2)))*4;
            if (QI){
                int rw = bn + row;
                const float* src = (rw < 384) ? W + (size_t)rw*K + kc + col
                                              : e1 + (size_t)(rw-384)*K + kc + col;
                cpa16(dst, src);
            } else if (NP && (bn+row) >= Nout) {
                cpa16z(dst, W);
            } else {
                cpa16(dst, W + (size_t)(bn+row)*K + kc + col);
            }
        }
        asm volatile("cp.async.commit_group;" ::: "memory");
    };

    int KT = K >> 5;
    issue(0);
    issue(1);

    // lane-invariant ldmatrix addressing
    int a_r  = m0 + (lane&7) + ((lane>>3)&1)*8;   // + i*16
    int a_cq = (lane>>4)*4;
    int b_nb = warp_n*32 + ((lane>>4))*8 + (lane&7);  // + j2*16
    int b_kq = ((lane>>3)&1)*4;

    for (int kt=0; kt<KT; kt++){
        if (kt == KT-1) asm volatile("cp.async.wait_group 0;" ::: "memory");
        else            asm volatile("cp.async.wait_group 1;" ::: "memory");
        __syncthreads();
        if (kt+2 < KT) issue(kt+2);

        uint32_t abase = sbase + (uint32_t)((kt%3)*STG)*4;
        uint32_t bbase = abase + 2048*4;
        #pragma unroll
        for (int ks=0; ks<4; ks++){
            uint32_t af[MT][4];
            #pragma unroll
            for (int i=0;i<MT;i++){
                int r = a_r + i*16;
                int c = (ks*8 + a_cq) ^ ((r&7)<<2);
                ldsm4(af[i], abase + (uint32_t)(r*32 + c)*4);
            }
            uint32_t bf[2][4];
            #pragma unroll
            for (int j2=0;j2<2;j2++){
                int n = b_nb + j2*16;
                int c = (ks*8 + b_kq) ^ ((n&7)<<2);
                ldsm4(bf[j2], bbase + (uint32_t)(n*32 + c)*4);
            }
            #pragma unroll
            for (int i=0;i<MT;i++)
                #pragma unroll
                for (int j2=0;j2<2;j2++)
                    #pragma unroll
                    for (int jj=0;jj<2;jj++)
                        mma8(acc[i][2*j2+jj], af[i], &bf[j2][2*jj]);
        }
    }

    // ---- epilogue ----
    #pragma unroll
    for (int i=0;i<MT;i++){
        #pragma unroll
        for (int j=0;j<4;j++){
            int n = bn + warp_n*32 + j*8 + 2*(lane&3);
            if (NP && n >= Nout) continue;
            #pragma unroll
            for (int half=0; half<2; half++){
                int m = bm + m0 + i*16 + (lane>>2) + half*8;
                float vx = acc[i][j][half*2+0];
                float vy = acc[i][j][half*2+1];
                if (QI){
                    if (bn < 384){
                        float2 bv = *(const float2*)(bias + n);
                        vx += bv.x; vy += bv.y;
                        *(float2*)(C + (size_t)m*384 + n) = make_float2(vx, vy);
                    } else {
                        int n2 = n - 384;
                        float2 bv = *(const float2*)(e2 + n2);
                        vx += bv.x; vy += bv.y;
                        *(float2*)((float*)e0 + (size_t)m*512 + n2) = make_float2(vx, vy);
                    }
                    continue;
                }
                float2 bv = bias ? *(const float2*)(bias + n) : make_float2(0.f,0.f);
                vx += bv.x; vy += bv.y;
                size_t idx = (size_t)m*Nout + n;
                if (EPI == 1){
                    vx = gelu_f(vx); vy = gelu_f(vy);
                } else if (EPI == 2){
                    float2 r0 = *(const float2*)(e0 + idx);
                    float2 r1 = *(const float2*)(e1 + idx);
                    float2 r2 = *(const float2*)(e2 + idx);
                    float gx = 1.f/(1.f+__expf(-vx));
                    float gy = 1.f/(1.f+__expf(-vy));
                    vx = r0.x + gx*r1.x + (1.f-gx)*r2.x;
                    vy = r0.y + gy*r1.y + (1.f-gy)*r2.y;
                } else if (EPI == 3){
                    float2 r0 = *(const float2*)(e0 + idx);
                    vx += r0.x; vy += r0.y;
                }
                *(float2*)(C + idx) = make_float2(vx, vy);
            }
        }
    }
}

// ---------------- LayerNorm ----------------
__global__ void ln_kernel(const float* __restrict__ in, const float* __restrict__ g,
                          const float* __restrict__ b, float* __restrict__ out) {
    int warp = (blockIdx.x * blockDim.x + threadIdx.x) >> 5;
    int lane = threadIdx.x & 31;
    if (warp >= TOK) return;
    float4 v = ((const float4*)(in + (size_t)warp*128))[lane];
    float s = v.x+v.y+v.z+v.w;
    #pragma unroll
    for (int o=16;o;o>>=1) s += __shfl_xor_sync(~0u, s, o);
    float mean = s * (1.f/128.f);
    float dx=v.x-mean, dy=v.y-mean, dz=v.z-mean, dw=v.w-mean;
    float q = dx*dx+dy*dy+dz*dz+dw*dw;
    #pragma unroll
    for (int o=16;o;o>>=1) q += __shfl_xor_sync(~0u, q, o);
    float rstd = rsqrtf(q*(1.f/128.f) + 1e-5f);
    float4 gv = ((const float4*)g)[lane];
    float4 bv = ((const float4*)b)[lane];
    float4 ov;
    ov.x = dx*rstd*gv.x + bv.x;
    ov.y = dy*rstd*gv.y + bv.y;
    ov.z = dz*rstd*gv.z + bv.z;
    ov.w = dw*rstd*gv.w + bv.w;
    ((float4*)(out + (size_t)warp*128))[lane] = ov;
}

// ---------------- window attention ----------------
__global__ void attn_kernel(const float* __restrict__ rpb) {
    int w = blockIdx.x >> 2;
    int head = blockIdx.x & 3;
    int b = w >> 6, wh = (w >> 3) & 7, ww = w & 7;
    __shared__ float qs[49][32], ks[49][32], vs[49][32];
    __shared__ float sc[49][49];
    int tid = threadIdx.x;
    const float scale = 0.17677669529663689f;
    for (int i = tid; i < 49*32; i += 128) {
        int n = i >> 5, d = i & 31;
        int t = ((b*56 + wh*7 + n/7)*56 + ww*7 + n%7);
        const float* base = g_qkv + (size_t)t*384 + head*32 + d;
        qs[n][d] = base[0] * scale;
        ks[n][d] = base[128];
        vs[n][d] = base[256];
    }
    __syncthreads();
    for (int idx = tid; idx < 49*49; idx += 128) {
        int i = idx/49, j = idx%49;
        float s = 0.f;
        const float4* qp = (const float4*)qs[i];
        const float4* kp = (const float4*)ks[j];
        #pragma unroll
        for (int k=0;k<8;k++){ float4 a=qp[k], c=kp[k]; s += a.x*c.x+a.y*c.y+a.z*c.z+a.w*c.w; }
        int dr = i/7 - j/7 + 6, dc = i%7 - j%7 + 6;
        sc[i][j] = s + rpb[(dr*13+dc)*4 + head];
    }
    __syncthreads();
    if (tid < 49) {
        int i = tid;
        float m = -1e30f;
        for (int j=0;j<49;j++) m = fmaxf(m, sc[i][j]);
        float sum = 0.f;
        for (int j=0;j<49;j++){ float e=__expf(sc[i][j]-m); sc[i][j]=e; sum+=e; }
        float inv = 1.f/sum;
        for (int j=0;j<49;j++) sc[i][j] *= inv;
    }
    __syncthreads();
    for (int idx = tid; idx < 49*32; idx += 128) {
        int i = idx >> 5, d = idx & 31;
        float o = 0.f;
        for (int j=0;j<49;j++) o += sc[i][j]*vs[j][d];
        int t = ((b*56 + wh*7 + i/7)*56 + ww*7 + i%7);
        g_awb[(size_t)t*128 + head*32 + d] = o;
    }
}

// ---------------- causal depthwise conv + SiLU ----------------
__global__ void conv_kernel(const float* __restrict__ cw, const float* __restrict__ cb) {
    int idx = blockIdx.x*blockDim.x + threadIdx.x;
    if (idx >= TOK*256) return;
    int t = idx >> 8, d = idx & 255;
    int b = t / LSEQ, l = t % LSEQ;
    float acc = cb[d];
    #pragma unroll
    for (int j=0;j<4;j++){
        int ll = l - 3 + j;
        if (ll >= 0) acc = fmaf(cw[d*4+j], g_xz[((size_t)(b*LSEQ+ll))*512 + d], acc);
    }
    float sg = 1.f/(1.f+__expf(-acc));
    g_xc[idx] = acc * sg;
}

// ---------------- dt_proj + softplus ----------------
__global__ void dtproj_kernel(const float* __restrict__ wt, const float* __restrict__ bias){
    int idx = blockIdx.x*blockDim.x + threadIdx.x;
    if (idx >= TOK*256) return;
    int t = idx >> 8, d = idx & 255;
    float acc = bias[d];
    const float* r = g_dbl + (size_t)t*40;
    const float* wr = wt + d*8;
    #pragma unroll
    for (int k=0;k<8;k++) acc = fmaf(r[k], wr[k], acc);
    float sp = (acc > 20.f) ? acc : log1pf(__expf(acc));
    g_dt[idx] = sp;
}

// ============ chunk-parallel selective scan ============
__global__ __launch_bounds__(256) void scan_phase1(const float* __restrict__ A_log){
    int gw = (blockIdx.x*blockDim.x + threadIdx.x) >> 5;
    int lane = threadIdx.x & 31;
    int dpair = gw & 127;
    int chunk = (gw >> 7) % NCH;
    int b = gw / (128*NCH);
    int d = dpair*2 + (lane >> 4);
    int s = lane & 15;
    float Aval = -__expf(A_log[d*16 + s]);
    float h = 0.f, sd = 0.f;
    int t0 = b*LSEQ + chunk*CH;
    for (int g = 0; g < CH; g += 8) {
        float dtv[8], xcv[8], Bv[8];
        #pragma unroll
        for (int u=0;u<8;u++){
            int t = t0 + g + u;
            dtv[u] = g_dt[(size_t)t*256 + d];
            xcv[u] = g_xc[(size_t)t*256 + d];
            Bv[u]  = g_dbl[(size_t)t*40 + 8 + s];
        }
        #pragma unroll
        for (int u=0;u<8;u++){
            sd += dtv[u];
            float a = __expf(dtv[u]*Aval);
            h = a*h + dtv[u]*Bv[u]*xcv[u];
        }
    }
    size_t hidx = ((size_t)(b*NCH + chunk)*256 + d)*16 + s;
    g_hend[hidx] = h;
    if (s == 0) g_sumdt[(b*NCH + chunk)*256 + d] = sd;
}

__global__ __launch_bounds__(256) void scan_phase2(const float* __restrict__ A_log){
    int gw = (blockIdx.x*blockDim.x + threadIdx.x) >> 5;
    int lane = threadIdx.x & 31;
    int b = gw >> 7;
    int dpair = gw & 127;
    int d = dpair*2 + (lane >> 4);
    int s = lane & 15;
    float Aval = -__expf(A_log[d*16 + s]);
    float h = 0.f;
    for (int c = 0; c < NCH; c++) {
        size_t hidx = ((size_t)(b*NCH + c)*256 + d)*16 + s;
        g_hin[hidx] = h;
        float sd = g_sumdt[(b*NCH + c)*256 + d];
        h = __expf(Aval*sd)*h + g_hend[hidx];
    }
}

__global__ __launch_bounds__(256) void scan_phase3(const float* __restrict__ A_log,
                                                   const float* __restrict__ Dp){
    __shared__ float part[8*32*33];
    int warp = threadIdx.x >> 5, lane = threadIdx.x & 31;
    int gw = blockIdx.x * 8 + warp;
    int dpair = gw & 127;
    int chunk = (gw >> 7) % NCH;
    int b = gw / (128*NCH);
    int dbase = dpair*2;
    int d = dbase + (lane >> 4);
    int s = lane & 15;
    float Aval = -__expf(A_log[d*16 + s]);
    float dp0 = Dp[dbase], dp1 = Dp[dbase+1];
    size_t hidx = ((size_t)(b*NCH + chunk)*256 + d)*16 + s;
    float h = g_hin[hidx];
    float* pp = part + warp*32*33 + lane*33;
    float* wp = part + warp*32*33;
    int tb = b*LSEQ + chunk*CH;
    #pragma unroll 1
    for (int half = 0; half < 2; half++) {
        int base = half*32;
        #pragma unroll 1
        for (int g = 0; g < 32; g += 8) {
            float dtv[8], xcv[8], Bv[8], Cv[8];
            #pragma unroll
            for (int u=0;u<8;u++){
                int t = tb + base + g + u;
                dtv[u] = g_dt[(size_t)t*256 + d];
                xcv[u] = g_xc[(size_t)t*256 + d];
                Bv[u]  = g_dbl[(size_t)t*40 + 8 + s];
                Cv[u]  = g_dbl[(size_t)t*40 + 24 + s];
            }
            #pragma unroll
            for (int u=0;u<8;u++){
                float a = __expf(dtv[u]*Aval);
                h = a*h + dtv[u]*Bv[u]*xcv[u];
                pp[g+u] = h * Cv[u];
            }
        }
        __syncwarp();
        {
            int lu = lane;
            int t = tb + base + lu;
            #pragma unroll
            for (int c2=0;c2<2;c2++){
                float ys = 0.f;
                #pragma unroll
                for (int ss=0; ss<16; ss++) ys += wp[(c2*16+ss)*33 + lu];
                int d2 = dbase + c2;
                float xcv2 = g_xc[(size_t)t*256 + d2];
                float zv = g_xz[(size_t)t*512 + 256 + d2];
                float yv = ys + xcv2 * (c2 ? dp1 : dp0);
                float sg = 1.f/(1.f+__expf(-zv));
                g_y[(size_t)t*256 + d2] = yv * zv * sg;
            }
        }
        __syncwarp();
    }
}

// ---------------- launch ----------------
extern "C" void kernel_launch(void* const* d_in, const int* in_sizes, int n_in,
                              void* d_out, int out_size) {
    const float* x        = (const float*)d_in[0];
    const float* ln1_g    = (const float*)d_in[1];
    const float* ln1_b    = (const float*)d_in[2];
    const float* qkv_w    = (const float*)d_in[3];
    const float* qkv_b    = (const float*)d_in[4];
    const float* rpb      = (const float*)d_in[5];
    const float* proj_w   = (const float*)d_in[6];
    const float* proj_b   = (const float*)d_in[7];
    const float* in_w     = (const float*)d_in[8];
    const float* in_b     = (const float*)d_in[9];
    const float* conv_w   = (const float*)d_in[10];
    const float* conv_b   = (const float*)d_in[11];
    const float* xproj_w  = (const float*)d_in[12];
    const float* dtw      = (const float*)d_in[13];
    const float* dtb      = (const float*)d_in[14];
    const float* A_log    = (const float*)d_in[15];
    const float* Dp       = (const float*)d_in[16];
    const float* out_w    = (const float*)d_in[17];
    const float* out_b    = (const float*)d_in[18];
    const float* gate_w   = (const float*)d_in[19];
    const float* gate_b   = (const float*)d_in[20];
    const float* ln2_g    = (const float*)d_in[21];
    const float* ln2_b    = (const float*)d_in[22];
    const float* mlp_w1   = (const float*)d_in[23];
    const float* mlp_b1   = (const float*)d_in[24];
    const float* mlp_w2   = (const float*)d_in[25];
    const float* mlp_b2   = (const float*)d_in[26];
    float* out = (float*)d_out;

    float *xn, *qkv, *awb, *attn, *xz, *y, *mamba, *x1, *h2, *hid, *xc, *dbl;
    cudaGetSymbolAddress((void**)&xn,    g_xn);
    cudaGetSymbolAddress((void**)&qkv,   g_qkv);
    cudaGetSymbolAddress((void**)&awb,   g_awb);
    cudaGetSymbolAddress((void**)&attn,  g_attn);
    cudaGetSymbolAddress((void**)&xz,    g_xz);
    cudaGetSymbolAddress((void**)&y,     g_y);
    cudaGetSymbolAddress((void**)&mamba, g_mamba);
    cudaGetSymbolAddress((void**)&x1,    g_x1);
    cudaGetSymbolAddress((void**)&h2,    g_h2);
    cudaGetSymbolAddress((void**)&hid,   g_hid);
    cudaGetSymbolAddress((void**)&xc,    g_xc);
    cudaGetSymbolAddress((void**)&dbl,   g_dbl);

    const int SM64  = 3*(2048 + 64*32)*4;    // 48 KB
    const int SM128 = 3*(2048 + 128*32)*4;   // 72 KB
    cudaFuncSetAttribute(mma_gemm<128,0,0,0,1>, cudaFuncAttributeMaxDynamicSharedMemorySize, SM128);
    cudaFuncSetAttribute(mma_gemm<128,1,0,0,0>, cudaFuncAttributeMaxDynamicSharedMemorySize, SM128);
    cudaFuncSetAttribute(mma_gemm<64,0,0,0,0>,  cudaFuncAttributeMaxDynamicSharedMemorySize, SM64);
    cudaFuncSetAttribute(mma_gemm<64,0,0,1,0>,  cudaFuncAttributeMaxDynamicSharedMemorySize, SM64);
    cudaFuncSetAttribute(mma_gemm<64,2,1,0,0>,  cudaFuncAttributeMaxDynamicSharedMemorySize, SM64);
    cudaFuncSetAttribute(mma_gemm<64,3,0,0,0>,  cudaFuncAttributeMaxDynamicSharedMemorySize, SM64);

    // LN1
    ln_kernel<<<TOK/8, 256>>>(x, ln1_g, ln1_b, xn);
    // merged qkv + in_proj GEMM (N=896, K=128): n<384 -> qkv, else -> xz
    mma_gemm<128,0,0,0,1><<<dim3(7,196), 256, SM128>>>(xn, qkv_w, qkv_b, qkv, 384, 128, xz, in_w, in_b);
    // window attention
    attn_kernel<<<NWIN*4, 128>>>(rpb);
    // proj GEMM (N=128, K=128) -> attn_out
    mma_gemm<64,0,0,0,0><<<dim3(2,196), 256, SM64>>>(awb, proj_w, proj_b, attn, 128, 128, nullptr, nullptr, nullptr);
    // causal conv + silu -> xc
    conv_kernel<<<TOK, 256>>>(conv_w, conv_b);
    // x_proj GEMM (N=40 pad 64, K=256) -> dbl
    mma_gemm<64,0,0,1,0><<<dim3(1,196), 256, SM64>>>(xc, xproj_w, nullptr, dbl, 40, 256, nullptr, nullptr, nullptr);
    // dt_proj + softplus -> dt
    dtproj_kernel<<<TOK, 256>>>(dtw, dtb);
    // chunk-parallel selective scan
    scan_phase1<<<(BATCH*NCH*128)/8, 256>>>(A_log);
    scan_phase2<<<64, 256>>>(A_log);
    scan_phase3<<<(BATCH*NCH*128)/8, 256>>>(A_log, Dp);
    // out_proj GEMM (N=128, K=256) -> mamba
    mma_gemm<64,0,0,0,0><<<dim3(2,196), 256, SM64>>>(y, out_w, out_b, mamba, 128, 256, nullptr, nullptr, nullptr);
    // gate GEMM (A=[attn|mamba], K=256) + fused blend + residual -> x1
    mma_gemm<64,2,1,0,0><<<dim3(2,196), 256, SM64>>>(nullptr, gate_w, gate_b, x1, 128, 256, x, attn, mamba);
    // LN2
    ln_kernel<<<TOK/8, 256>>>(x1, ln2_g, ln2_b, h2);
    // MLP1 + gelu (N=512, K=128)
    mma_gemm<128,1,0,0,0><<<dim3(4,196), 256, SM128>>>(h2, mlp_w1, mlp_b1, hid, 512, 128, nullptr, nullptr, nullptr);
    // MLP2 + residual (N=128, K=512) -> out
    mma_gemm<64,3,0,0,0><<<dim3(2,196), 256, SM64>>>(hid, mlp_w2, mlp_b2, out, 128, 512, x1, nullptr, nullptr);

    (void)in_sizes; (void)n_in; (void)out_size;
}

// round 11
// speedup vs baseline: 1.9547x; 1.0595x over previous
#include <cuda_runtime.h>
#include <math.h>
#include <stdint.h>

#define TOK   12544
#define BATCH 4
#define LSEQ  3136
#define NWIN  256
#define NCH   49
#define CH    64

// ---------------- scratch ----------------
__device__ float g_xn[TOK*128];
__device__ float g_qkv[TOK*384];
__device__ float g_awb[TOK*128];
__device__ float g_attn[TOK*128];
__device__ float g_xz[TOK*512];
__device__ float g_xc[TOK*256];
__device__ float g_dbl[TOK*40];
__device__ float g_dt[TOK*256];
__device__ float g_y[TOK*256];
__device__ float g_mamba[TOK*128];
__device__ float g_x1[TOK*128];
__device__ float g_h2[TOK*128];
__device__ float g_hid[TOK*512];
__device__ float g_hend[BATCH*NCH*256*16];
__device__ float g_hin[BATCH*NCH*256*16];
__device__ float g_sumdt[BATCH*NCH*256];

__device__ __forceinline__ float gelu_f(float x){ return 0.5f*x*(1.f+erff(x*0.70710678118f)); }
__device__ __forceinline__ uint32_t smem_u32(const void* p){
    uint32_t a; asm("{ .reg .u64 t; cvta.to.shared.u64 t, %1; cvt.u32.u64 %0, t; }" : "=r"(a) : "l"(p)); return a;
}
__device__ __forceinline__ void cpa16(uint32_t dst, const void* src){
    asm volatile("cp.async.cg.shared.global [%0], [%1], 16;" :: "r"(dst), "l"(src));
}
__device__ __forceinline__ void cpa16z(uint32_t dst, const void* src){
    asm volatile("cp.async.cg.shared.global [%0], [%1], 16, 0;" :: "r"(dst), "l"(src));
}
__device__ __forceinline__ void ldsm4(uint32_t* d, uint32_t addr){
    asm volatile("ldmatrix.sync.aligned.m8n8.x4.shared.b16 {%0,%1,%2,%3}, [%4];"
        : "=r"(d[0]),"=r"(d[1]),"=r"(d[2]),"=r"(d[3]) : "r"(addr));
}
__device__ __forceinline__ void mma8(float* c, const uint32_t* a, const uint32_t* b){
    asm volatile("mma.sync.aligned.m16n8k8.row.col.f32.tf32.tf32.f32 "
        "{%0,%1,%2,%3}, {%4,%5,%6,%7}, {%8,%9}, {%0,%1,%2,%3};"
        : "+f"(c[0]),"+f"(c[1]),"+f"(c[2]),"+f"(c[3])
        : "r"(a[0]),"r"(a[1]),"r"(a[2]),"r"(a[3]), "r"(b[0]),"r"(b[1]));
}

// ================= cp.async + ldmatrix tf32 mma GEMM =================
// C[M,Nout] = A[M,K] @ W[Nout,K]^T (+bias, epilogue). CTA tile 64 x NT, Ktile 32.
// EPI: 0 none, 1 gelu, 2 gate-fuse (e0=x,e1=attn,e2=mamba), 3 residual(e0)
// AG: A gathered as [e1|e2] (K==256). NP: pad. QI: merged qkv+in_proj.
template<int NT, int EPI, int AG, int NP, int QI>
__global__ __launch_bounds__(256)
void mma_gemm(const float* __restrict__ A, const float* __restrict__ W,
              const float* __restrict__ bias, float* __restrict__ C,
              int Nout, int K,
              const float* __restrict__ e0, const float* __restrict__ e1,
              const float* __restrict__ e2)
{
    extern __shared__ float sm[];
    const int NW  = NT/32;
    const int MW  = 8/NW;
    const int MT  = 64/(16*MW);
    const int STG = 2048 + NT*32;
    const int BCH = (NT*8)/256;
    uint32_t sbase = smem_u32(sm);
    int tid = threadIdx.x, wid = tid>>5, lane = tid&31;
    int warp_n = wid % NW, warp_m = wid / NW;
    int bm = blockIdx.y*64, bn = blockIdx.x*NT;
    int m0 = warp_m * MT * 16;

    float acc[MT][4][4];
    #pragma unroll
    for (int i=0;i<MT;i++)
        #pragma unroll
        for (int j=0;j<4;j++)
            #pragma unroll
            for (int q=0;q<4;q++) acc[i][j][q]=0.f;

    auto issue = [&](int kt){
        int st = kt % 3;
        uint32_t abase = sbase + (uint32_t)st*STG*4;
        uint32_t bbase = abase + 2048*4;
        int kc = kt*32;
        #pragma unroll
        for (int i=0;i<2;i++){
            int ch = tid + i*256;
            int row = ch>>3, col = (ch&7)*4;
            uint32_t dst = abase + (uint32_t)(row*32 + (col ^ ((row&7)<<2)))*4;
            const float* src;
            if (AG){
                int kg = kc + col;
                src = (kg<128) ? e1 + (size_t)(bm+row)*128 + kg
                               : e2 + (size_t)(bm+row)*128 + (kg-128);
            } else {
                src = A + (size_t)(bm+row)*K + kc + col;
            }
            cpa16(dst, src);
        }
        #pragma unroll
        for (int i=0;i<BCH;i++){
            int ch = tid + i*256;
            int row = ch>>3, col = (ch&7)*4;
            uint32_t dst = bbase + (uint32_t)(row*32 + (col ^ ((row&7)<<2)))*4;
            if (QI){
                int rw = bn + row;
                const float* src = (rw < 384) ? W + (size_t)rw*K + kc + col
                                              : e1 + (size_t)(rw-384)*K + kc + col;
                cpa16(dst, src);
            } else if (NP && (bn+row) >= Nout) {
                cpa16z(dst, W);
            } else {
                cpa16(dst, W + (size_t)(bn+row)*K + kc + col);
            }
        }
        asm volatile("cp.async.commit_group;" ::: "memory");
    };

    int KT = K >> 5;
    issue(0);
    issue(1);

    int a_r  = m0 + (lane&7) + ((lane>>3)&1)*8;
    int a_cq = (lane>>4)*4;
    int b_nb = warp_n*32 + ((lane>>4))*8 + (lane&7);
    int b_kq = ((lane>>3)&1)*4;

    for (int kt=0; kt<KT; kt++){
        if (kt == KT-1) asm volatile("cp.async.wait_group 0;" ::: "memory");
        else            asm volatile("cp.async.wait_group 1;" ::: "memory");
        __syncthreads();
        if (kt+2 < KT) issue(kt+2);

        uint32_t abase = sbase + (uint32_t)((kt%3)*STG)*4;
        uint32_t bbase = abase + 2048*4;
        #pragma unroll
        for (int ks=0; ks<4; ks++){
            uint32_t af[MT][4];
            #pragma unroll
            for (int i=0;i<MT;i++){
                int r = a_r + i*16;
                int c = (ks*8 + a_cq) ^ ((r&7)<<2);
                ldsm4(af[i], abase + (uint32_t)(r*32 + c)*4);
            }
            uint32_t bf[2][4];
            #pragma unroll
            for (int j2=0;j2<2;j2++){
                int n = b_nb + j2*16;
                int c = (ks*8 + b_kq) ^ ((n&7)<<2);
                ldsm4(bf[j2], bbase + (uint32_t)(n*32 + c)*4);
            }
            #pragma unroll
            for (int i=0;i<MT;i++)
                #pragma unroll
                for (int j2=0;j2<2;j2++)
                    #pragma unroll
                    for (int jj=0;jj<2;jj++)
                        mma8(acc[i][2*j2+jj], af[i], &bf[j2][2*jj]);
        }
    }

    #pragma unroll
    for (int i=0;i<MT;i++){
        #pragma unroll
        for (int j=0;j<4;j++){
            int n = bn + warp_n*32 + j*8 + 2*(lane&3);
            if (NP && n >= Nout) continue;
            #pragma unroll
            for (int half=0; half<2; half++){
                int m = bm + m0 + i*16 + (lane>>2) + half*8;
                float vx = acc[i][j][half*2+0];
                float vy = acc[i][j][half*2+1];
                if (QI){
                    if (bn < 384){
                        float2 bv = *(const float2*)(bias + n);
                        vx += bv.x; vy += bv.y;
                        *(float2*)(C + (size_t)m*384 + n) = make_float2(vx, vy);
                    } else {
                        int n2 = n - 384;
                        float2 bv = *(const float2*)(e2 + n2);
                        vx += bv.x; vy += bv.y;
                        *(float2*)((float*)e0 + (size_t)m*512 + n2) = make_float2(vx, vy);
                    }
                    continue;
                }
                float2 bv = bias ? *(const float2*)(bias + n) : make_float2(0.f,0.f);
                vx += bv.x; vy += bv.y;
                size_t idx = (size_t)m*Nout + n;
                if (EPI == 1){
                    vx = gelu_f(vx); vy = gelu_f(vy);
                } else if (EPI == 2){
                    float2 r0 = *(const float2*)(e0 + idx);
                    float2 r1 = *(const float2*)(e1 + idx);
                    float2 r2 = *(const float2*)(e2 + idx);
                    float gx = 1.f/(1.f+__expf(-vx));
                    float gy = 1.f/(1.f+__expf(-vy));
                    vx = r0.x + gx*r1.x + (1.f-gx)*r2.x;
                    vy = r0.y + gy*r1.y + (1.f-gy)*r2.y;
                } else if (EPI == 3){
                    float2 r0 = *(const float2*)(e0 + idx);
                    vx += r0.x; vy += r0.y;
                }
                *(float2*)(C + idx) = make_float2(vx, vy);
            }
        }
    }
}

// ---------------- LayerNorm ----------------
__global__ void ln_kernel(const float* __restrict__ in, const float* __restrict__ g,
                          const float* __restrict__ b, float* __restrict__ out) {
    int warp = (blockIdx.x * blockDim.x + threadIdx.x) >> 5;
    int lane = threadIdx.x & 31;
    if (warp >= TOK) return;
    float4 v = ((const float4*)(in + (size_t)warp*128))[lane];
    float s = v.x+v.y+v.z+v.w;
    #pragma unroll
    for (int o=16;o;o>>=1) s += __shfl_xor_sync(~0u, s, o);
    float mean = s * (1.f/128.f);
    float dx=v.x-mean, dy=v.y-mean, dz=v.z-mean, dw=v.w-mean;
    float q = dx*dx+dy*dy+dz*dz+dw*dw;
    #pragma unroll
    for (int o=16;o;o>>=1) q += __shfl_xor_sync(~0u, q, o);
    float rstd = rsqrtf(q*(1.f/128.f) + 1e-5f);
    float4 gv = ((const float4*)g)[lane];
    float4 bv = ((const float4*)b)[lane];
    float4 ov;
    ov.x = dx*rstd*gv.x + bv.x;
    ov.y = dy*rstd*gv.y + bv.y;
    ov.z = dz*rstd*gv.z + bv.z;
    ov.w = dw*rstd*gv.w + bv.w;
    ((float4*)(out + (size_t)warp*128))[lane] = ov;
}

// ---------------- window attention ----------------
__global__ void attn_kernel(const float* __restrict__ rpb) {
    int w = blockIdx.x >> 2;
    int head = blockIdx.x & 3;
    int b = w >> 6, wh = (w >> 3) & 7, ww = w & 7;
    __shared__ float qs[49][32], ks[49][32], vs[49][32];
    __shared__ float sc[49][49];
    int tid = threadIdx.x;
    const float scale = 0.17677669529663689f;
    for (int i = tid; i < 49*32; i += 128) {
        int n = i >> 5, d = i & 31;
        int t = ((b*56 + wh*7 + n/7)*56 + ww*7 + n%7);
        const float* base = g_qkv + (size_t)t*384 + head*32 + d;
        qs[n][d] = base[0] * scale;
        ks[n][d] = base[128];
        vs[n][d] = base[256];
    }
    __syncthreads();
    for (int idx = tid; idx < 49*49; idx += 128) {
        int i = idx/49, j = idx%49;
        float s = 0.f;
        const float4* qp = (const float4*)qs[i];
        const float4* kp = (const float4*)ks[j];
        #pragma unroll
        for (int k=0;k<8;k++){ float4 a=qp[k], c=kp[k]; s += a.x*c.x+a.y*c.y+a.z*c.z+a.w*c.w; }
        int dr = i/7 - j/7 + 6, dc = i%7 - j%7 + 6;
        sc[i][j] = s + rpb[(dr*13+dc)*4 + head];
    }
    __syncthreads();
    if (tid < 49) {
        int i = tid;
        float m = -1e30f;
        for (int j=0;j<49;j++) m = fmaxf(m, sc[i][j]);
        float sum = 0.f;
        for (int j=0;j<49;j++){ float e=__expf(sc[i][j]-m); sc[i][j]=e; sum+=e; }
        float inv = 1.f/sum;
        for (int j=0;j<49;j++) sc[i][j] *= inv;
    }
    __syncthreads();
    for (int idx = tid; idx < 49*32; idx += 128) {
        int i = idx >> 5, d = idx & 31;
        float o = 0.f;
        for (int j=0;j<49;j++) o += sc[i][j]*vs[j][d];
        int t = ((b*56 + wh*7 + i/7)*56 + ww*7 + i%7);
        g_awb[(size_t)t*128 + head*32 + d] = o;
    }
}

// ---------------- tiled causal depthwise conv (k=4) + SiLU ----------------
// block = 32 timesteps x 256 channels; smem tile of 35 rows reused across taps
__global__ __launch_bounds__(256) void conv_kernel(const float* __restrict__ cw,
                                                   const float* __restrict__ cb) {
    __shared__ float tile[35][256];
    int blk = blockIdx.x;                 // BATCH*98
    int b = blk / 98;
    int t0 = (blk % 98) * 32;
    int tid = threadIdx.x;
    for (int idx = tid; idx < 35*256; idx += 256){
        int row = idx >> 8, col = idx & 255;
        int tg = t0 + row - 3;
        tile[row][col] = (tg >= 0) ? g_xz[((size_t)(b*LSEQ + tg))*512 + col] : 0.f;
    }
    __syncthreads();
    int d = tid;
    float w0 = cw[d*4+0], w1 = cw[d*4+1], w2 = cw[d*4+2], w3 = cw[d*4+3];
    float bb = cb[d];
    #pragma unroll 4
    for (int tt = 0; tt < 32; tt++){
        float acc = bb
            + w0*tile[tt+0][d] + w1*tile[tt+1][d]
            + w2*tile[tt+2][d] + w3*tile[tt+3][d];
        float sg = 1.f/(1.f+__expf(-acc));
        g_xc[((size_t)(b*LSEQ + t0 + tt))*256 + d] = acc * sg;
    }
}

// ---------------- dt_proj + softplus ----------------
__global__ void dtproj_kernel(const float* __restrict__ wt, const float* __restrict__ bias){
    int idx = blockIdx.x*blockDim.x + threadIdx.x;
    if (idx >= TOK*256) return;
    int t = idx >> 8, d = idx & 255;
    float acc = bias[d];
    const float* r = g_dbl + (size_t)t*40;
    const float* wr = wt + d*8;
    #pragma unroll
    for (int k=0;k<8;k++) acc = fmaf(r[k], wr[k], acc);
    float sp = (acc > 20.f) ? acc : log1pf(__expf(acc));
    g_dt[idx] = sp;
}

// ============ chunk-parallel selective scan ============
__global__ __launch_bounds__(256) void scan_phase1(const float* __restrict__ A_log){
    int gw = (blockIdx.x*blockDim.x + threadIdx.x) >> 5;
    int lane = threadIdx.x & 31;
    int dpair = gw & 127;
    int chunk = (gw >> 7) % NCH;
    int b = gw / (128*NCH);
    int d = dpair*2 + (lane >> 4);
    int s = lane & 15;
    float Aval = -__expf(A_log[d*16 + s]);
    float h = 0.f, sd = 0.f;
    int t0 = b*LSEQ + chunk*CH;
    for (int g = 0; g < CH; g += 8) {
        float dtv[8], xcv[8], Bv[8];
        #pragma unroll
        for (int u=0;u<8;u++){
            int t = t0 + g + u;
            dtv[u] = g_dt[(size_t)t*256 + d];
            xcv[u] = g_xc[(size_t)t*256 + d];
            Bv[u]  = g_dbl[(size_t)t*40 + 8 + s];
        }
        #pragma unroll
        for (int u=0;u<8;u++){
            sd += dtv[u];
            float a = __expf(dtv[u]*Aval);
            h = a*h + dtv[u]*Bv[u]*xcv[u];
        }
    }
    size_t hidx = ((size_t)(b*NCH + chunk)*256 + d)*16 + s;
    g_hend[hidx] = h;
    if (s == 0) g_sumdt[(b*NCH + chunk)*256 + d] = sd;
}

// Phase 2: serial chain, batched prefetch of 8 chunks
__global__ __launch_bounds__(256) void scan_phase2(const float* __restrict__ A_log){
    int gw = (blockIdx.x*blockDim.x + threadIdx.x) >> 5;
    int lane = threadIdx.x & 31;
    int b = gw >> 7;
    int dpair = gw & 127;
    int d = dpair*2 + (lane >> 4);
    int s = lane & 15;
    float Aval = -__expf(A_log[d*16 + s]);
    float h = 0.f;
    size_t hb = ((size_t)(b*NCH)*256 + d)*16 + s;      // + c*4096
    int    sb = (b*NCH)*256 + d;                        // + c*256
    #pragma unroll 1
    for (int c0 = 0; c0 < 48; c0 += 8){
        float sd[8], he[8];
        #pragma unroll
        for (int u=0;u<8;u++){
            sd[u] = g_sumdt[sb + (c0+u)*256];
            he[u] = g_hend[hb + (size_t)(c0+u)*4096];
        }
        float dec[8];
        #pragma unroll
        for (int u=0;u<8;u++) dec[u] = __expf(Aval*sd[u]);
        #pragma unroll
        for (int u=0;u<8;u++){
            g_hin[hb + (size_t)(c0+u)*4096] = h;
            h = dec[u]*h + he[u];
        }
    }
    g_hin[hb + (size_t)48*4096] = h;
}

__global__ __launch_bounds__(256) void scan_phase3(const float* __restrict__ A_log,
                                                   const float* __restrict__ Dp){
    __shared__ float part[8*32*33];
    int warp = threadIdx.x >> 5, lane = threadIdx.x & 31;
    int gw = blockIdx.x * 8 + warp;
    int dpair = gw & 127;
    int chunk = (gw >> 7) % NCH;
    int b = gw / (128*NCH);
    int dbase = dpair*2;
    int d = dbase + (lane >> 4);
    int s = lane & 15;
    float Aval = -__expf(A_log[d*16 + s]);
    float dp0 = Dp[dbase], dp1 = Dp[dbase+1];
    size_t hidx = ((size_t)(b*NCH + chunk)*256 + d)*16 + s;
    float h = g_hin[hidx];
    float* pp = part + warp*32*33 + lane*33;
    float* wp = part + warp*32*33;
    int tb = b*LSEQ + chunk*CH;
    #pragma unroll 1
    for (int half = 0; half < 2; half++) {
        int base = half*32;
        #pragma unroll 1
        for (int g = 0; g < 32; g += 8) {
            float dtv[8], xcv[8], Bv[8], Cv[8];
            #pragma unroll
            for (int u=0;u<8;u++){
                int t = tb + base + g + u;
                dtv[u] = g_dt[(size_t)t*256 + d];
                xcv[u] = g_xc[(size_t)t*256 + d];
                Bv[u]  = g_dbl[(size_t)t*40 + 8 + s];
                Cv[u]  = g_dbl[(size_t)t*40 + 24 + s];
            }
            #pragma unroll
            for (int u=0;u<8;u++){
                float a = __expf(dtv[u]*Aval);
                h = a*h + dtv[u]*Bv[u]*xcv[u];
                pp[g+u] = h * Cv[u];
            }
        }
        __syncwarp();
        {
            int lu = lane;
            int t = tb + base + lu;
            #pragma unroll
            for (int c2=0;c2<2;c2++){
                float ys = 0.f;
                #pragma unroll
                for (int ss=0; ss<16; ss++) ys += wp[(c2*16+ss)*33 + lu];
                int d2 = dbase + c2;
                float xcv2 = g_xc[(size_t)t*256 + d2];
                float zv = g_xz[(size_t)t*512 + 256 + d2];
                float yv = ys + xcv2 * (c2 ? dp1 : dp0);
                float sg = 1.f/(1.f+__expf(-zv));
                g_y[(size_t)t*256 + d2] = yv * zv * sg;
            }
        }
        __syncwarp();
    }
}

// ---------------- launch ----------------
extern "C" void kernel_launch(void* const* d_in, const int* in_sizes, int n_in,
                              void* d_out, int out_size) {
    const float* x        = (const float*)d_in[0];
    const float* ln1_g    = (const float*)d_in[1];
    const float* ln1_b    = (const float*)d_in[2];
    const float* qkv_w    = (const float*)d_in[3];
    const float* qkv_b    = (const float*)d_in[4];
    const float* rpb      = (const float*)d_in[5];
    const float* proj_w   = (const float*)d_in[6];
    const float* proj_b   = (const float*)d_in[7];
    const float* in_w     = (const float*)d_in[8];
    const float* in_b     = (const float*)d_in[9];
    const float* conv_w   = (const float*)d_in[10];
    const float* conv_b   = (const float*)d_in[11];
    const float* xproj_w  = (const float*)d_in[12];
    const float* dtw      = (const float*)d_in[13];
    const float* dtb      = (const float*)d_in[14];
    const float* A_log    = (const float*)d_in[15];
    const float* Dp       = (const float*)d_in[16];
    const float* out_w    = (const float*)d_in[17];
    const float* out_b    = (const float*)d_in[18];
    const float* gate_w   = (const float*)d_in[19];
    const float* gate_b   = (const float*)d_in[20];
    const float* ln2_g    = (const float*)d_in[21];
    const float* ln2_b    = (const float*)d_in[22];
    const float* mlp_w1   = (const float*)d_in[23];
    const float* mlp_b1   = (const float*)d_in[24];
    const float* mlp_w2   = (const float*)d_in[25];
    const float* mlp_b2   = (const float*)d_in[26];
    float* out = (float*)d_out;

    float *xn, *qkv, *awb, *attn, *xz, *y, *mamba, *x1, *h2, *hid, *xc, *dbl;
    cudaGetSymbolAddress((void**)&xn,    g_xn);
    cudaGetSymbolAddress((void**)&qkv,   g_qkv);
    cudaGetSymbolAddress((void**)&awb,   g_awb);
    cudaGetSymbolAddress((void**)&attn,  g_attn);
    cudaGetSymbolAddress((void**)&xz,    g_xz);
    cudaGetSymbolAddress((void**)&y,     g_y);
    cudaGetSymbolAddress((void**)&mamba, g_mamba);
    cudaGetSymbolAddress((void**)&x1,    g_x1);
    cudaGetSymbolAddress((void**)&h2,    g_h2);
    cudaGetSymbolAddress((void**)&hid,   g_hid);
    cudaGetSymbolAddress((void**)&xc,    g_xc);
    cudaGetSymbolAddress((void**)&dbl,   g_dbl);

    // one-time host-side stream/event setup (first call is the non-captured
    // correctness run, so creation never happens during graph capture)
    static cudaStream_t s_attn = nullptr;
    static cudaEvent_t ev_fork = nullptr, ev_join = nullptr;
    if (!s_attn){
        cudaStreamCreateWithFlags(&s_attn, cudaStreamNonBlocking);
        cudaEventCreateWithFlags(&ev_fork, cudaEventDisableTiming);
        cudaEventCreateWithFlags(&ev_join, cudaEventDisableTiming);
    }

    const int SM64  = 3*(2048 + 64*32)*4;    // 48 KB
    const int SM128 = 3*(2048 + 128*32)*4;   // 72 KB
    cudaFuncSetAttribute(mma_gemm<128,0,0,0,1>, cudaFuncAttributeMaxDynamicSharedMemorySize, SM128);
    cudaFuncSetAttribute(mma_gemm<128,1,0,0,0>, cudaFuncAttributeMaxDynamicSharedMemorySize, SM128);
    cudaFuncSetAttribute(mma_gemm<64,0,0,0,0>,  cudaFuncAttributeMaxDynamicSharedMemorySize, SM64);
    cudaFuncSetAttribute(mma_gemm<64,0,0,1,0>,  cudaFuncAttributeMaxDynamicSharedMemorySize, SM64);
    cudaFuncSetAttribute(mma_gemm<64,2,1,0,0>,  cudaFuncAttributeMaxDynamicSharedMemorySize, SM64);
    cudaFuncSetAttribute(mma_gemm<64,3,0,0,0>,  cudaFuncAttributeMaxDynamicSharedMemorySize, SM64);

    // LN1
    ln_kernel<<<TOK/8, 256>>>(x, ln1_g, ln1_b, xn);
    // merged qkv + in_proj GEMM (N=896, K=128): n<384 -> qkv, else -> xz
    mma_gemm<128,0,0,0,1><<<dim3(7,196), 256, SM128>>>(xn, qkv_w, qkv_b, qkv, 384, 128, xz, in_w, in_b);

    // ---- fork: attention branch on s_attn ----
    cudaEventRecord(ev_fork, 0);
    cudaStreamWaitEvent(s_attn, ev_fork, 0);
    attn_kernel<<<NWIN*4, 128, 0, s_attn>>>(rpb);
    mma_gemm<64,0,0,0,0><<<dim3(2,196), 256, SM64, s_attn>>>(awb, proj_w, proj_b, attn, 128, 128, nullptr, nullptr, nullptr);
    cudaEventRecord(ev_join, s_attn);

    // ---- mamba branch on default stream ----
    conv_kernel<<<BATCH*98, 256>>>(conv_w, conv_b);
    mma_gemm<64,0,0,1,0><<<dim3(1,196), 256, SM64>>>(xc, xproj_w, nullptr, dbl, 40, 256, nullptr, nullptr, nullptr);
    dtproj_kernel<<<TOK, 256>>>(dtw, dtb);
    scan_phase1<<<(BATCH*NCH*128)/8, 256>>>(A_log);
    scan_phase2<<<64, 256>>>(A_log);
    scan_phase3<<<(BATCH*NCH*128)/8, 256>>>(A_log, Dp);
    mma_gemm<64,0,0,0,0><<<dim3(2,196), 256, SM64>>>(y, out_w, out_b, mamba, 128, 256, nullptr, nullptr, nullptr);

    // ---- join, then gate + MLP ----
    cudaStreamWaitEvent(0, ev_join, 0);
    mma_gemm<64,2,1,0,0><<<dim3(2,196), 256, SM64>>>(nullptr, gate_w, gate_b, x1, 128, 256, x, attn, mamba);
    ln_kernel<<<TOK/8, 256>>>(x1, ln2_g, ln2_b, h2);
    mma_gemm<128,1,0,0,0><<<dim3(4,196), 256, SM128>>>(h2, mlp_w1, mlp_b1, hid, 512, 128, nullptr, nullptr, nullptr);
    mma_gemm<64,3,0,0,0><<<dim3(2,196), 256, SM64>>>(hid, mlp_w2, mlp_b2, out, 128, 512, x1, nullptr, nullptr);

    (void)in_sizes; (void)n_in; (void)out_size;
}

// round 12
// speedup vs baseline: 2.1462x; 1.0980x over previous
#include <cuda_runtime.h>
#include <math.h>
#include <stdint.h>

#define TOK   12544
#define BATCH 4
#define LSEQ  3136
#define NWIN  256
#define NCH   49
#define CH    64

// ---------------- scratch ----------------
__device__ float g_xn[TOK*128];
__device__ float g_qkv[TOK*384];
__device__ float g_awb[TOK*128];
__device__ float g_attn[TOK*128];
__device__ float g_xz[TOK*512];
__device__ float g_xc[TOK*256];
__device__ float g_xcT[256*TOK];
__device__ float g_dtT[256*TOK];
__device__ float g_dbl[TOK*40];
__device__ float g_y[TOK*256];
__device__ float g_mamba[TOK*128];
__device__ float g_x1[TOK*128];
__device__ float g_h2[TOK*128];
__device__ float g_hid[TOK*512];
__device__ float g_hend[BATCH*NCH*256*16];
__device__ float g_hin[BATCH*NCH*256*16];
__device__ float g_sumdt[BATCH*NCH*256];

__device__ __forceinline__ float gelu_f(float x){ return 0.5f*x*(1.f+erff(x*0.70710678118f)); }
__device__ __forceinline__ uint32_t smem_u32(const void* p){
    uint32_t a; asm("{ .reg .u64 t; cvta.to.shared.u64 t, %1; cvt.u32.u64 %0, t; }" : "=r"(a) : "l"(p)); return a;
}
__device__ __forceinline__ void cpa16(uint32_t dst, const void* src){
    asm volatile("cp.async.cg.shared.global [%0], [%1], 16;" :: "r"(dst), "l"(src));
}
__device__ __forceinline__ void cpa16z(uint32_t dst, const void* src){
    asm volatile("cp.async.cg.shared.global [%0], [%1], 16, 0;" :: "r"(dst), "l"(src));
}
__device__ __forceinline__ void ldsm4(uint32_t* d, uint32_t addr){
    asm volatile("ldmatrix.sync.aligned.m8n8.x4.shared.b16 {%0,%1,%2,%3}, [%4];"
        : "=r"(d[0]),"=r"(d[1]),"=r"(d[2]),"=r"(d[3]) : "r"(addr));
}
__device__ __forceinline__ void mma8(float* c, const uint32_t* a, const uint32_t* b){
    asm volatile("mma.sync.aligned.m16n8k8.row.col.f32.tf32.tf32.f32 "
        "{%0,%1,%2,%3}, {%4,%5,%6,%7}, {%8,%9}, {%0,%1,%2,%3};"
        : "+f"(c[0]),"+f"(c[1]),"+f"(c[2]),"+f"(c[3])
        : "r"(a[0]),"r"(a[1]),"r"(a[2]),"r"(a[3]), "r"(b[0]),"r"(b[1]));
}

// ================= cp.async + ldmatrix tf32 mma GEMM =================
template<int NT, int EPI, int AG, int NP, int QI>
__global__ __launch_bounds__(256)
void mma_gemm(const float* __restrict__ A, const float* __restrict__ W,
              const float* __restrict__ bias, float* __restrict__ C,
              int Nout, int K,
              const float* __restrict__ e0, const float* __restrict__ e1,
              const float* __restrict__ e2)
{
    extern __shared__ float sm[];
    const int NW  = NT/32;
    const int MW  = 8/NW;
    const int MT  = 64/(16*MW);
    const int STG = 2048 + NT*32;
    const int BCH = (NT*8)/256;
    uint32_t sbase = smem_u32(sm);
    int tid = threadIdx.x, wid = tid>>5, lane = tid&31;
    int warp_n = wid % NW, warp_m = wid / NW;
    int bm = blockIdx.y*64, bn = blockIdx.x*NT;
    int m0 = warp_m * MT * 16;

    float acc[MT][4][4];
    #pragma unroll
    for (int i=0;i<MT;i++)
        #pragma unroll
        for (int j=0;j<4;j++)
            #pragma unroll
            for (int q=0;q<4;q++) acc[i][j][q]=0.f;

    auto issue = [&](int kt){
        int st = kt % 3;
        uint32_t abase = sbase + (uint32_t)st*STG*4;
        uint32_t bbase = abase + 2048*4;
        int kc = kt*32;
        #pragma unroll
        for (int i=0;i<2;i++){
            int ch = tid + i*256;
            int row = ch>>3, col = (ch&7)*4;
            uint32_t dst = abase + (uint32_t)(row*32 + (col ^ ((row&7)<<2)))*4;
            const float* src;
            if (AG){
                int kg = kc + col;
                src = (kg<128) ? e1 + (size_t)(bm+row)*128 + kg
                               : e2 + (size_t)(bm+row)*128 + (kg-128);
            } else {
                src = A + (size_t)(bm+row)*K + kc + col;
            }
            cpa16(dst, src);
        }
        #pragma unroll
        for (int i=0;i<BCH;i++){
            int ch = tid + i*256;
            int row = ch>>3, col = (ch&7)*4;
            uint32_t dst = bbase + (uint32_t)(row*32 + (col ^ ((row&7)<<2)))*4;
            if (QI){
                int rw = bn + row;
                const float* src = (rw < 384) ? W + (size_t)rw*K + kc + col
                                              : e1 + (size_t)(rw-384)*K + kc + col;
                cpa16(dst, src);
            } else if (NP && (bn+row) >= Nout) {
                cpa16z(dst, W);
            } else {
                cpa16(dst, W + (size_t)(bn+row)*K + kc + col);
            }
        }
        asm volatile("cp.async.commit_group;" ::: "memory");
    };

    int KT = K >> 5;
    issue(0);
    issue(1);

    int a_r  = m0 + (lane&7) + ((lane>>3)&1)*8;
    int a_cq = (lane>>4)*4;
    int b_nb = warp_n*32 + ((lane>>4))*8 + (lane&7);
    int b_kq = ((lane>>3)&1)*4;

    for (int kt=0; kt<KT; kt++){
        if (kt == KT-1) asm volatile("cp.async.wait_group 0;" ::: "memory");
        else            asm volatile("cp.async.wait_group 1;" ::: "memory");
        __syncthreads();
        if (kt+2 < KT) issue(kt+2);

        uint32_t abase = sbase + (uint32_t)((kt%3)*STG)*4;
        uint32_t bbase = abase + 2048*4;
        #pragma unroll
        for (int ks=0; ks<4; ks++){
            uint32_t af[MT][4];
            #pragma unroll
            for (int i=0;i<MT;i++){
                int r = a_r + i*16;
                int c = (ks*8 + a_cq) ^ ((r&7)<<2);
                ldsm4(af[i], abase + (uint32_t)(r*32 + c)*4);
            }
            uint32_t bf[2][4];
            #pragma unroll
            for (int j2=0;j2<2;j2++){
                int n = b_nb + j2*16;
                int c = (ks*8 + b_kq) ^ ((n&7)<<2);
                ldsm4(bf[j2], bbase + (uint32_t)(n*32 + c)*4);
            }
            #pragma unroll
            for (int i=0;i<MT;i++)
                #pragma unroll
                for (int j2=0;j2<2;j2++)
                    #pragma unroll
                    for (int jj=0;jj<2;jj++)
                        mma8(acc[i][2*j2+jj], af[i], &bf[j2][2*jj]);
        }
    }

    #pragma unroll
    for (int i=0;i<MT;i++){
        #pragma unroll
        for (int j=0;j<4;j++){
            int n = bn + warp_n*32 + j*8 + 2*(lane&3);
            if (NP && n >= Nout) continue;
            #pragma unroll
            for (int half=0; half<2; half++){
                int m = bm + m0 + i*16 + (lane>>2) + half*8;
                float vx = acc[i][j][half*2+0];
                float vy = acc[i][j][half*2+1];
                if (QI){
                    if (bn < 384){
                        float2 bv = *(const float2*)(bias + n);
                        vx += bv.x; vy += bv.y;
                        *(float2*)(C + (size_t)m*384 + n) = make_float2(vx, vy);
                    } else {
                        int n2 = n - 384;
                        float2 bv = *(const float2*)(e2 + n2);
                        vx += bv.x; vy += bv.y;
                        *(float2*)((float*)e0 + (size_t)m*512 + n2) = make_float2(vx, vy);
                    }
                    continue;
                }
                float2 bv = bias ? *(const float2*)(bias + n) : make_float2(0.f,0.f);
                vx += bv.x; vy += bv.y;
                size_t idx = (size_t)m*Nout + n;
                if (EPI == 1){
                    vx = gelu_f(vx); vy = gelu_f(vy);
                } else if (EPI == 2){
                    float2 r0 = *(const float2*)(e0 + idx);
                    float2 r1 = *(const float2*)(e1 + idx);
                    float2 r2 = *(const float2*)(e2 + idx);
                    float gx = 1.f/(1.f+__expf(-vx));
                    float gy = 1.f/(1.f+__expf(-vy));
                    vx = r0.x + gx*r1.x + (1.f-gx)*r2.x;
                    vy = r0.y + gy*r1.y + (1.f-gy)*r2.y;
                } else if (EPI == 3){
                    float2 r0 = *(const float2*)(e0 + idx);
                    vx += r0.x; vy += r0.y;
                }
                *(float2*)(C + idx) = make_float2(vx, vy);
            }
        }
    }
}

// ---------------- LayerNorm ----------------
__global__ void ln_kernel(const float* __restrict__ in, const float* __restrict__ g,
                          const float* __restrict__ b, float* __restrict__ out) {
    int warp = (blockIdx.x * blockDim.x + threadIdx.x) >> 5;
    int lane = threadIdx.x & 31;
    if (warp >= TOK) return;
    float4 v = ((const float4*)(in + (size_t)warp*128))[lane];
    float s = v.x+v.y+v.z+v.w;
    #pragma unroll
    for (int o=16;o;o>>=1) s += __shfl_xor_sync(~0u, s, o);
    float mean = s * (1.f/128.f);
    float dx=v.x-mean, dy=v.y-mean, dz=v.z-mean, dw=v.w-mean;
    float q = dx*dx+dy*dy+dz*dz+dw*dw;
    #pragma unroll
    for (int o=16;o;o>>=1) q += __shfl_xor_sync(~0u, q, o);
    float rstd = rsqrtf(q*(1.f/128.f) + 1e-5f);
    float4 gv = ((const float4*)g)[lane];
    float4 bv = ((const float4*)b)[lane];
    float4 ov;
    ov.x = dx*rstd*gv.x + bv.x;
    ov.y = dy*rstd*gv.y + bv.y;
    ov.z = dz*rstd*gv.z + bv.z;
    ov.w = dw*rstd*gv.w + bv.w;
    ((float4*)(out + (size_t)warp*128))[lane] = ov;
}

// ---------------- window attention ----------------
__global__ void attn_kernel(const float* __restrict__ rpb) {
    int w = blockIdx.x >> 2;
    int head = blockIdx.x & 3;
    int b = w >> 6, wh = (w >> 3) & 7, ww = w & 7;
    __shared__ float qs[49][32], ks[49][32], vs[49][32];
    __shared__ float sc[49][49];
    int tid = threadIdx.x;
    const float scale = 0.17677669529663689f;
    for (int i = tid; i < 49*32; i += 128) {
        int n = i >> 5, d = i & 31;
        int t = ((b*56 + wh*7 + n/7)*56 + ww*7 + n%7);
        const float* base = g_qkv + (size_t)t*384 + head*32 + d;
        qs[n][d] = base[0] * scale;
        ks[n][d] = base[128];
        vs[n][d] = base[256];
    }
    __syncthreads();
    for (int idx = tid; idx < 49*49; idx += 128) {
        int i = idx/49, j = idx%49;
        float s = 0.f;
        const float4* qp = (const float4*)qs[i];
        const float4* kp = (const float4*)ks[j];
        #pragma unroll
        for (int k=0;k<8;k++){ float4 a=qp[k], c=kp[k]; s += a.x*c.x+a.y*c.y+a.z*c.z+a.w*c.w; }
        int dr = i/7 - j/7 + 6, dc = i%7 - j%7 + 6;
        sc[i][j] = s + rpb[(dr*13+dc)*4 + head];
    }
    __syncthreads();
    if (tid < 49) {
        int i = tid;
        float m = -1e30f;
        for (int j=0;j<49;j++) m = fmaxf(m, sc[i][j]);
        float sum = 0.f;
        for (int j=0;j<49;j++){ float e=__expf(sc[i][j]-m); sc[i][j]=e; sum+=e; }
        float inv = 1.f/sum;
        for (int j=0;j<49;j++) sc[i][j] *= inv;
    }
    __syncthreads();
    for (int idx = tid; idx < 49*32; idx += 128) {
        int i = idx >> 5, d = idx & 31;
        float o = 0.f;
        for (int j=0;j<49;j++) o += sc[i][j]*vs[j][d];
        int t = ((b*56 + wh*7 + i/7)*56 + ww*7 + i%7);
        g_awb[(size_t)t*128 + head*32 + d] = o;
    }
}

// ---------------- tiled causal conv (k=4) + SiLU, dual-layout output ----------------
__global__ __launch_bounds__(256) void conv_kernel(const float* __restrict__ cw,
                                                   const float* __restrict__ cb) {
    __shared__ float tile[35][256];
    int blk = blockIdx.x;                 // BATCH*98
    int b = blk / 98;
    int t0 = (blk % 98) * 32;
    int tid = threadIdx.x;
    for (int idx = tid; idx < 35*256; idx += 256){
        int row = idx >> 8, col = idx & 255;
        int tg = t0 + row - 3;
        tile[row][col] = (tg >= 0) ? g_xz[((size_t)(b*LSEQ + tg))*512 + col] : 0.f;
    }
    __syncthreads();
    int d = tid;
    float w0 = cw[d*4+0], w1 = cw[d*4+1], w2 = cw[d*4+2], w3 = cw[d*4+3];
    float bb = cb[d];
    float vals[32];
    #pragma unroll 4
    for (int tt = 0; tt < 32; tt++){
        float acc = bb
            + w0*tile[tt+0][d] + w1*tile[tt+1][d]
            + w2*tile[tt+2][d] + w3*tile[tt+3][d];
        float sg = 1.f/(1.f+__expf(-acc));
        float v = acc * sg;
        vals[tt] = v;
        g_xc[((size_t)(b*LSEQ + t0 + tt))*256 + d] = v;
    }
    float* dstT = g_xcT + (size_t)d*TOK + b*LSEQ + t0;
    #pragma unroll
    for (int i=0;i<8;i++)
        ((float4*)dstT)[i] = make_float4(vals[4*i+0], vals[4*i+1], vals[4*i+2], vals[4*i+3]);
}

// ---------------- dt_proj + softplus -> transposed dtT[d][t] ----------------
__global__ __launch_bounds__(256) void dtproj_kernel(const float* __restrict__ wt,
                                                     const float* __restrict__ bias){
    int t0 = blockIdx.x * 32;             // TOK/32 = 392 blocks
    int d = threadIdx.x;
    float wr[8];
    #pragma unroll
    for (int k=0;k<8;k++) wr[k] = wt[d*8+k];
    float bb = bias[d];
    float vals[32];
    #pragma unroll 4
    for (int tt=0; tt<32; tt++){
        const float4* r = (const float4*)(g_dbl + (size_t)(t0+tt)*40);
        float4 r0 = r[0], r1 = r[1];
        float acc = bb + r0.x*wr[0] + r0.y*wr[1] + r0.z*wr[2] + r0.w*wr[3]
                       + r1.x*wr[4] + r1.y*wr[5] + r1.z*wr[6] + r1.w*wr[7];
        vals[tt] = (acc > 20.f) ? acc : log1pf(__expf(acc));
    }
    float* dst = g_dtT + (size_t)d*TOK + t0;
    #pragma unroll
    for (int i=0;i<8;i++)
        ((float4*)dst)[i] = make_float4(vals[4*i+0], vals[4*i+1], vals[4*i+2], vals[4*i+3]);
}

// ============ chunk-parallel selective scan (staged loads) ============
__global__ __launch_bounds__(256) void scan_phase1(const float* __restrict__ A_log){
    __shared__ float sdt[8][2][64], sxc[8][2][64];
    int warp = threadIdx.x >> 5, lane = threadIdx.x & 31;
    int gw = blockIdx.x * 8 + warp;
    int dpair = gw & 127;
    int chunk = (gw >> 7) % NCH;
    int b = gw / (128*NCH);
    int dbase = dpair*2;
    int d = dbase + (lane >> 4);
    int s = lane & 15;
    float Aval = -__expf(A_log[d*16 + s]);
    int tb = b*LSEQ + chunk*CH;
    // stage dt/xc for this chunk: 1 LDG.128 per lane per array
    {
        int rr = lane >> 4, c4 = (lane & 15)*4;
        *(float4*)&sdt[warp][rr][c4] = *(const float4*)&g_dtT[(size_t)(dbase+rr)*TOK + tb + c4];
        *(float4*)&sxc[warp][rr][c4] = *(const float4*)&g_xcT[(size_t)(dbase+rr)*TOK + tb + c4];
    }
    __syncwarp();
    int rr = lane >> 4;
    float h = 0.f, sd = 0.f;
    #pragma unroll 1
    for (int g = 0; g < CH; g += 8) {
        float Bv[8];
        #pragma unroll
        for (int u=0;u<8;u++)
            Bv[u] = g_dbl[(size_t)(tb + g + u)*40 + 8 + s];
        #pragma unroll
        for (int u=0;u<8;u++){
            float dtv = sdt[warp][rr][g+u];
            float xcv = sxc[warp][rr][g+u];
            sd += dtv;
            float a = __expf(dtv*Aval);
            h = a*h + dtv*Bv[u]*xcv;
        }
    }
    size_t hidx = ((size_t)(b*NCH + chunk)*256 + d)*16 + s;
    g_hend[hidx] = h;
    if (s == 0) g_sumdt[(b*NCH + chunk)*256 + d] = sd;
}

// Phase 2: serial chain, batched prefetch of 8 chunks
__global__ __launch_bounds__(256) void scan_phase2(const float* __restrict__ A_log){
    int gw = (blockIdx.x*blockDim.x + threadIdx.x) >> 5;
    int lane = threadIdx.x & 31;
    int b = gw >> 7;
    int dpair = gw & 127;
    int d = dpair*2 + (lane >> 4);
    int s = lane & 15;
    float Aval = -__expf(A_log[d*16 + s]);
    float h = 0.f;
    size_t hb = ((size_t)(b*NCH)*256 + d)*16 + s;
    int    sb = (b*NCH)*256 + d;
    #pragma unroll 1
    for (int c0 = 0; c0 < 48; c0 += 8){
        float sd[8], he[8];
        #pragma unroll
        for (int u=0;u<8;u++){
            sd[u] = g_sumdt[sb + (c0+u)*256];
            he[u] = g_hend[hb + (size_t)(c0+u)*4096];
        }
        float dec[8];
        #pragma unroll
        for (int u=0;u<8;u++) dec[u] = __expf(Aval*sd[u]);
        #pragma unroll
        for (int u=0;u<8;u++){
            g_hin[hb + (size_t)(c0+u)*4096] = h;
            h = dec[u]*h + he[u];
        }
    }
    g_hin[hb + (size_t)48*4096] = h;
}

__global__ __launch_bounds__(256) void scan_phase3(const float* __restrict__ A_log,
                                                   const float* __restrict__ Dp){
    __shared__ float part[8*32*33];
    __shared__ float sdt[8][2][64], sxc[8][2][64];
    int warp = threadIdx.x >> 5, lane = threadIdx.x & 31;
    int gw = blockIdx.x * 8 + warp;
    int dpair = gw & 127;
    int chunk = (gw >> 7) % NCH;
    int b = gw / (128*NCH);
    int dbase = dpair*2;
    int d = dbase + (lane >> 4);
    int s = lane & 15;
    float Aval = -__expf(A_log[d*16 + s]);
    float dp0 = Dp[dbase], dp1 = Dp[dbase+1];
    size_t hidx = ((size_t)(b*NCH + chunk)*256 + d)*16 + s;
    float h = g_hin[hidx];
    float* pp = part + warp*32*33 + lane*33;
    float* wp = part + warp*32*33;
    int tb = b*LSEQ + chunk*CH;
    // stage dt/xc
    {
        int rr = lane >> 4, c4 = (lane & 15)*4;
        *(float4*)&sdt[warp][rr][c4] = *(const float4*)&g_dtT[(size_t)(dbase+rr)*TOK + tb + c4];
        *(float4*)&sxc[warp][rr][c4] = *(const float4*)&g_xcT[(size_t)(dbase+rr)*TOK + tb + c4];
    }
    __syncwarp();
    int rr = lane >> 4;
    #pragma unroll 1
    for (int half = 0; half < 2; half++) {
        int base = half*32;
        #pragma unroll 1
        for (int g = 0; g < 32; g += 8) {
            float Bv[8], Cv[8];
            #pragma unroll
            for (int u=0;u<8;u++){
                int t = tb + base + g + u;
                Bv[u]  = g_dbl[(size_t)t*40 + 8 + s];
                Cv[u]  = g_dbl[(size_t)t*40 + 24 + s];
            }
            #pragma unroll
            for (int u=0;u<8;u++){
                float dtv = sdt[warp][rr][base+g+u];
                float xcv = sxc[warp][rr][base+g+u];
                float a = __expf(dtv*Aval);
                h = a*h + dtv*Bv[u]*xcv;
                pp[g+u] = h * Cv[u];
            }
        }
        __syncwarp();
        {
            int lu = lane;
            int t = tb + base + lu;
            float y0 = 0.f, y1 = 0.f;
            #pragma unroll
            for (int ss=0; ss<16; ss++){
                y0 += wp[ss*33 + lu];
                y1 += wp[(16+ss)*33 + lu];
            }
            float xc0 = sxc[warp][0][base+lu];
            float xc1 = sxc[warp][1][base+lu];
            float2 zv = *(const float2*)&g_xz[(size_t)t*512 + 256 + dbase];
            float yv0 = y0 + xc0*dp0;
            float yv1 = y1 + xc1*dp1;
            float sg0 = 1.f/(1.f+__expf(-zv.x));
            float sg1 = 1.f/(1.f+__expf(-zv.y));
            *(float2*)&g_y[(size_t)t*256 + dbase] = make_float2(yv0*zv.x*sg0, yv1*zv.y*sg1);
        }
        __syncwarp();
    }
}

// ---------------- launch ----------------
extern "C" void kernel_launch(void* const* d_in, const int* in_sizes, int n_in,
                              void* d_out, int out_size) {
    const float* x        = (const float*)d_in[0];
    const float* ln1_g    = (const float*)d_in[1];
    const float* ln1_b    = (const float*)d_in[2];
    const float* qkv_w    = (const float*)d_in[3];
    const float* qkv_b    = (const float*)d_in[4];
    const float* rpb      = (const float*)d_in[5];
    const float* proj_w   = (const float*)d_in[6];
    const float* proj_b   = (const float*)d_in[7];
    const float* in_w     = (const float*)d_in[8];
    const float* in_b     = (const float*)d_in[9];
    const float* conv_w   = (const float*)d_in[10];
    const float* conv_b   = (const float*)d_in[11];
    const float* xproj_w  = (const float*)d_in[12];
    const float* dtw      = (const float*)d_in[13];
    const float* dtb      = (const float*)d_in[14];
    const float* A_log    = (const float*)d_in[15];
    const float* Dp       = (const float*)d_in[16];
    const float* out_w    = (const float*)d_in[17];
    const float* out_b    = (const float*)d_in[18];
    const float* gate_w   = (const float*)d_in[19];
    const float* gate_b   = (const float*)d_in[20];
    const float* ln2_g    = (const float*)d_in[21];
    const float* ln2_b    = (const float*)d_in[22];
    const float* mlp_w1   = (const float*)d_in[23];
    const float* mlp_b1   = (const float*)d_in[24];
    const float* mlp_w2   = (const float*)d_in[25];
    const float* mlp_b2   = (const float*)d_in[26];
    float* out = (float*)d_out;

    float *xn, *qkv, *awb, *attn, *xz, *y, *mamba, *x1, *h2, *hid, *xc, *dbl;
    cudaGetSymbolAddress((void**)&xn,    g_xn);
    cudaGetSymbolAddress((void**)&qkv,   g_qkv);
    cudaGetSymbolAddress((void**)&awb,   g_awb);
    cudaGetSymbolAddress((void**)&attn,  g_attn);
    cudaGetSymbolAddress((void**)&xz,    g_xz);
    cudaGetSymbolAddress((void**)&y,     g_y);
    cudaGetSymbolAddress((void**)&mamba, g_mamba);
    cudaGetSymbolAddress((void**)&x1,    g_x1);
    cudaGetSymbolAddress((void**)&h2,    g_h2);
    cudaGetSymbolAddress((void**)&hid,   g_hid);
    cudaGetSymbolAddress((void**)&xc,    g_xc);
    cudaGetSymbolAddress((void**)&dbl,   g_dbl);

    static cudaStream_t s_attn = nullptr;
    static cudaEvent_t ev_fork = nullptr, ev_join = nullptr;
    if (!s_attn){
        cudaStreamCreateWithFlags(&s_attn, cudaStreamNonBlocking);
        cudaEventCreateWithFlags(&ev_fork, cudaEventDisableTiming);
        cudaEventCreateWithFlags(&ev_join, cudaEventDisableTiming);
    }

    const int SM64  = 3*(2048 + 64*32)*4;    // 48 KB
    const int SM128 = 3*(2048 + 128*32)*4;   // 72 KB
    cudaFuncSetAttribute(mma_gemm<128,0,0,0,1>, cudaFuncAttributeMaxDynamicSharedMemorySize, SM128);
    cudaFuncSetAttribute(mma_gemm<128,1,0,0,0>, cudaFuncAttributeMaxDynamicSharedMemorySize, SM128);
    cudaFuncSetAttribute(mma_gemm<64,0,0,0,0>,  cudaFuncAttributeMaxDynamicSharedMemorySize, SM64);
    cudaFuncSetAttribute(mma_gemm<64,0,0,1,0>,  cudaFuncAttributeMaxDynamicSharedMemorySize, SM64);
    cudaFuncSetAttribute(mma_gemm<64,2,1,0,0>,  cudaFuncAttributeMaxDynamicSharedMemorySize, SM64);
    cudaFuncSetAttribute(mma_gemm<64,3,0,0,0>,  cudaFuncAttributeMaxDynamicSharedMemorySize, SM64);

    // LN1
    ln_kernel<<<TOK/8, 256>>>(x, ln1_g, ln1_b, xn);
    // merged qkv + in_proj GEMM (N=896, K=128): n<384 -> qkv, else -> xz
    mma_gemm<128,0,0,0,1><<<dim3(7,196), 256, SM128>>>(xn, qkv_w, qkv_b, qkv, 384, 128, xz, in_w, in_b);

    // ---- fork: attention branch on s_attn ----
    cudaEventRecord(ev_fork, 0);
    cudaStreamWaitEvent(s_attn, ev_fork, 0);
    attn_kernel<<<NWIN*4, 128, 0, s_attn>>>(rpb);
    mma_gemm<64,0,0,0,0><<<dim3(2,196), 256, SM64, s_attn>>>(awb, proj_w, proj_b, attn, 128, 128, nullptr, nullptr, nullptr);
    cudaEventRecord(ev_join, s_attn);

    // ---- mamba branch on default stream ----
    conv_kernel<<<BATCH*98, 256>>>(conv_w, conv_b);
    mma_gemm<64,0,0,1,0><<<dim3(1,196), 256, SM64>>>(xc, xproj_w, nullptr, dbl, 40, 256, nullptr, nullptr, nullptr);
    dtproj_kernel<<<TOK/32, 256>>>(dtw, dtb);
    scan_phase1<<<(BATCH*NCH*128)/8, 256>>>(A_log);
    scan_phase2<<<64, 256>>>(A_log);
    scan_phase3<<<(BATCH*NCH*128)/8, 256>>>(A_log, Dp);
    mma_gemm<64,0,0,0,0><<<dim3(2,196), 256, SM64>>>(y, out_w, out_b, mamba, 128, 256, nullptr, nullptr, nullptr);

    // ---- join, then gate + MLP ----
    cudaStreamWaitEvent(0, ev_join, 0);
    mma_gemm<64,2,1,0,0><<<dim3(2,196), 256, SM64>>>(nullptr, gate_w, gate_b, x1, 128, 256, x, attn, mamba);
    ln_kernel<<<TOK/8, 256>>>(x1, ln2_g, ln2_b, h2);
    mma_gemm<128,1,0,0,0><<<dim3(4,196), 256, SM128>>>(h2, mlp_w1, mlp_b1, hid, 512, 128, nullptr, nullptr, nullptr);
    mma_gemm<64,3,0,0,0><<<dim3(2,196), 256, SM64>>>(hid, mlp_w2, mlp_b2, out, 128, 512, x1, nullptr, nullptr);

    (void)in_sizes; (void)n_in; (void)out_size;
}

// round 13
// speedup vs baseline: 2.2315x; 1.0397x over previous
#include <cuda_runtime.h>
#include <math.h>
#include <stdint.h>

#define TOK   12544
#define BATCH 4
#define LSEQ  3136
#define NWIN  256
#define NCH   49
#define CH    64

// ---------------- scratch ----------------
__device__ float g_xn[TOK*128];
__device__ float g_qkv[TOK*384];
__device__ float g_awb[TOK*128];
__device__ float g_attn[TOK*128];
__device__ float g_xz[TOK*512];
__device__ float g_xc[TOK*256];
__device__ float g_xcT[256*TOK];
__device__ float g_dtT[256*TOK];
__device__ float g_dbl[TOK*40];
__device__ float g_y[TOK*256];
__device__ float g_mamba[TOK*128];
__device__ float g_x1[TOK*128];
__device__ float g_h2[TOK*128];
__device__ float g_hid[TOK*512];
__device__ float g_hend[BATCH*NCH*256*16];
__device__ float g_hin[BATCH*NCH*256*16];
__device__ float g_sumdt[BATCH*NCH*256];

__device__ __forceinline__ float gelu_f(float x){ return 0.5f*x*(1.f+erff(x*0.70710678118f)); }
__device__ __forceinline__ uint32_t smem_u32(const void* p){
    uint32_t a; asm("{ .reg .u64 t; cvta.to.shared.u64 t, %1; cvt.u32.u64 %0, t; }" : "=r"(a) : "l"(p)); return a;
}
__device__ __forceinline__ void cpa16(uint32_t dst, const void* src){
    asm volatile("cp.async.cg.shared.global [%0], [%1], 16;" :: "r"(dst), "l"(src));
}
__device__ __forceinline__ void cpa16z(uint32_t dst, const void* src){
    asm volatile("cp.async.cg.shared.global [%0], [%1], 16, 0;" :: "r"(dst), "l"(src));
}
__device__ __forceinline__ void ldsm4(uint32_t* d, uint32_t addr){
    asm volatile("ldmatrix.sync.aligned.m8n8.x4.shared.b16 {%0,%1,%2,%3}, [%4];"
        : "=r"(d[0]),"=r"(d[1]),"=r"(d[2]),"=r"(d[3]) : "r"(addr));
}
__device__ __forceinline__ void mma8(float* c, const uint32_t* a, const uint32_t* b){
    asm volatile("mma.sync.aligned.m16n8k8.row.col.f32.tf32.tf32.f32 "
        "{%0,%1,%2,%3}, {%4,%5,%6,%7}, {%8,%9}, {%0,%1,%2,%3};"
        : "+f"(c[0]),"+f"(c[1]),"+f"(c[2]),"+f"(c[3])
        : "r"(a[0]),"r"(a[1]),"r"(a[2]),"r"(a[3]), "r"(b[0]),"r"(b[1]));
}

// ================= cp.async + ldmatrix tf32 mma GEMM =================
// EPI: 0 none, 1 gelu, 2 gate-fuse, 3 residual(e0), 4 gate-fuse + fused LN2 (NT=128)
// AG: A gathered as [e1|e2] (K==256). NP: pad. QI: merged qkv+in_proj.
template<int NT, int EPI, int AG, int NP, int QI>
__global__ __launch_bounds__(256)
void mma_gemm(const float* __restrict__ A, const float* __restrict__ W,
              const float* __restrict__ bias, float* __restrict__ C,
              int Nout, int K,
              const float* __restrict__ e0, const float* __restrict__ e1,
              const float* __restrict__ e2,
              const float* __restrict__ p_g, const float* __restrict__ p_b,
              float* __restrict__ p_h2)
{
    extern __shared__ float sm[];
    const int NW  = NT/32;
    const int MW  = 8/NW;
    const int MT  = 64/(16*MW);
    const int STG = 2048 + NT*32;
    const int BCH = (NT*8)/256;
    uint32_t sbase = smem_u32(sm);
    int tid = threadIdx.x, wid = tid>>5, lane = tid&31;
    int warp_n = wid % NW, warp_m = wid / NW;
    int bm = blockIdx.y*64, bn = blockIdx.x*NT;
    int m0 = warp_m * MT * 16;

    float acc[MT][4][4];
    #pragma unroll
    for (int i=0;i<MT;i++)
        #pragma unroll
        for (int j=0;j<4;j++)
            #pragma unroll
            for (int q=0;q<4;q++) acc[i][j][q]=0.f;

    auto issue = [&](int kt){
        int st = kt % 3;
        uint32_t abase = sbase + (uint32_t)st*STG*4;
        uint32_t bbase = abase + 2048*4;
        int kc = kt*32;
        #pragma unroll
        for (int i=0;i<2;i++){
            int ch = tid + i*256;
            int row = ch>>3, col = (ch&7)*4;
            uint32_t dst = abase + (uint32_t)(row*32 + (col ^ ((row&7)<<2)))*4;
            const float* src;
            if (AG){
                int kg = kc + col;
                src = (kg<128) ? e1 + (size_t)(bm+row)*128 + kg
                               : e2 + (size_t)(bm+row)*128 + (kg-128);
            } else {
                src = A + (size_t)(bm+row)*K + kc + col;
            }
            cpa16(dst, src);
        }
        #pragma unroll
        for (int i=0;i<BCH;i++){
            int ch = tid + i*256;
            int row = ch>>3, col = (ch&7)*4;
            uint32_t dst = bbase + (uint32_t)(row*32 + (col ^ ((row&7)<<2)))*4;
            if (QI){
                int rw = bn + row;
                const float* src = (rw < 384) ? W + (size_t)rw*K + kc + col
                                              : e1 + (size_t)(rw-384)*K + kc + col;
                cpa16(dst, src);
            } else if (NP && (bn+row) >= Nout) {
                cpa16z(dst, W);
            } else {
                cpa16(dst, W + (size_t)(bn+row)*K + kc + col);
            }
        }
        asm volatile("cp.async.commit_group;" ::: "memory");
    };

    int KT = K >> 5;
    issue(0);
    issue(1);

    int a_r  = m0 + (lane&7) + ((lane>>3)&1)*8;
    int a_cq = (lane>>4)*4;
    int b_nb = warp_n*32 + ((lane>>4))*8 + (lane&7);
    int b_kq = ((lane>>3)&1)*4;

    for (int kt=0; kt<KT; kt++){
        if (kt == KT-1) asm volatile("cp.async.wait_group 0;" ::: "memory");
        else            asm volatile("cp.async.wait_group 1;" ::: "memory");
        __syncthreads();
        if (kt+2 < KT) issue(kt+2);

        uint32_t abase = sbase + (uint32_t)((kt%3)*STG)*4;
        uint32_t bbase = abase + 2048*4;
        #pragma unroll
        for (int ks=0; ks<4; ks++){
            uint32_t af[MT][4];
            #pragma unroll
            for (int i=0;i<MT;i++){
                int r = a_r + i*16;
                int c = (ks*8 + a_cq) ^ ((r&7)<<2);
                ldsm4(af[i], abase + (uint32_t)(r*32 + c)*4);
            }
            uint32_t bf[2][4];
            #pragma unroll
            for (int j2=0;j2<2;j2++){
                int n = b_nb + j2*16;
                int c = (ks*8 + b_kq) ^ ((n&7)<<2);
                ldsm4(bf[j2], bbase + (uint32_t)(n*32 + c)*4);
            }
            #pragma unroll
            for (int i=0;i<MT;i++)
                #pragma unroll
                for (int j2=0;j2<2;j2++)
                    #pragma unroll
                    for (int jj=0;jj<2;jj++)
                        mma8(acc[i][2*j2+jj], af[i], &bf[j2][2*jj]);
        }
    }

    if (EPI == 4){
        // gate blend + write x1 + fused LayerNorm -> h2   (requires NT=128, Nout=128, bn=0)
        float* xs = sm;                      // 64 x 129 tile (mainloop smem is free now)
        __syncthreads();
        #pragma unroll
        for (int i=0;i<MT;i++){
            #pragma unroll
            for (int j=0;j<4;j++){
                int n = warp_n*32 + j*8 + 2*(lane&3);
                float2 bv = *(const float2*)(bias + n);
                #pragma unroll
                for (int half=0; half<2; half++){
                    int r = m0 + i*16 + (lane>>2) + half*8;
                    int m = bm + r;
                    float vx = acc[i][j][half*2+0] + bv.x;
                    float vy = acc[i][j][half*2+1] + bv.y;
                    size_t idx = (size_t)m*128 + n;
                    float2 r0 = *(const float2*)(e0 + idx);
                    float2 r1 = *(const float2*)(e1 + idx);
                    float2 r2 = *(const float2*)(e2 + idx);
                    float gx = 1.f/(1.f+__expf(-vx));
                    float gy = 1.f/(1.f+__expf(-vy));
                    vx = r0.x + gx*r1.x + (1.f-gx)*r2.x;
                    vy = r0.y + gy*r1.y + (1.f-gy)*r2.y;
                    *(float2*)(C + idx) = make_float2(vx, vy);
                    xs[r*129 + n]     = vx;
                    xs[r*129 + n + 1] = vy;
                }
            }
        }
        __syncthreads();
        #pragma unroll 1
        for (int rr=0; rr<8; rr++){
            int r = wid*8 + rr;
            float v0 = xs[r*129 + lane];
            float v1 = xs[r*129 + lane + 32];
            float v2 = xs[r*129 + lane + 64];
            float v3 = xs[r*129 + lane + 96];
            float s = v0+v1+v2+v3;
            #pragma unroll
            for (int o=16;o;o>>=1) s += __shfl_xor_sync(~0u, s, o);
            float mean = s * (1.f/128.f);
            float d0=v0-mean, d1=v1-mean, d2=v2-mean, d3=v3-mean;
            float q = d0*d0+d1*d1+d2*d2+d3*d3;
            #pragma unroll
            for (int o=16;o;o>>=1) q += __shfl_xor_sync(~0u, q, o);
            float rstd = rsqrtf(q*(1.f/128.f) + 1e-5f);
            size_t mb = (size_t)(bm + r)*128;
            p_h2[mb + lane]      = d0*rstd*p_g[lane]      + p_b[lane];
            p_h2[mb + lane + 32] = d1*rstd*p_g[lane + 32] + p_b[lane + 32];
            p_h2[mb + lane + 64] = d2*rstd*p_g[lane + 64] + p_b[lane + 64];
            p_h2[mb + lane + 96] = d3*rstd*p_g[lane + 96] + p_b[lane + 96];
        }
        return;
    }

    #pragma unroll
    for (int i=0;i<MT;i++){
        #pragma unroll
        for (int j=0;j<4;j++){
            int n = bn + warp_n*32 + j*8 + 2*(lane&3);
            if (NP && n >= Nout) continue;
            #pragma unroll
            for (int half=0; half<2; half++){
                int m = bm + m0 + i*16 + (lane>>2) + half*8;
                float vx = acc[i][j][half*2+0];
                float vy = acc[i][j][half*2+1];
                if (QI){
                    if (bn < 384){
                        float2 bv = *(const float2*)(bias + n);
                        vx += bv.x; vy += bv.y;
                        *(float2*)(C + (size_t)m*384 + n) = make_float2(vx, vy);
                    } else {
                        int n2 = n - 384;
                        float2 bv = *(const float2*)(e2 + n2);
                        vx += bv.x; vy += bv.y;
                        *(float2*)((float*)e0 + (size_t)m*512 + n2) = make_float2(vx, vy);
                    }
                    continue;
                }
                float2 bv = bias ? *(const float2*)(bias + n) : make_float2(0.f,0.f);
                vx += bv.x; vy += bv.y;
                size_t idx = (size_t)m*Nout + n;
                if (EPI == 1){
                    vx = gelu_f(vx); vy = gelu_f(vy);
                } else if (EPI == 2){
                    float2 r0 = *(const float2*)(e0 + idx);
                    float2 r1 = *(const float2*)(e1 + idx);
                    float2 r2 = *(const float2*)(e2 + idx);
                    float gx = 1.f/(1.f+__expf(-vx));
                    float gy = 1.f/(1.f+__expf(-vy));
                    vx = r0.x + gx*r1.x + (1.f-gx)*r2.x;
                    vy = r0.y + gy*r1.y + (1.f-gy)*r2.y;
                } else if (EPI == 3){
                    float2 r0 = *(const float2*)(e0 + idx);
                    vx += r0.x; vy += r0.y;
                }
                *(float2*)(C + idx) = make_float2(vx, vy);
            }
        }
    }
}

// ---------------- LayerNorm ----------------
__global__ void ln_kernel(const float* __restrict__ in, const float* __restrict__ g,
                          const float* __restrict__ b, float* __restrict__ out) {
    int warp = (blockIdx.x * blockDim.x + threadIdx.x) >> 5;
    int lane = threadIdx.x & 31;
    if (warp >= TOK) return;
    float4 v = ((const float4*)(in + (size_t)warp*128))[lane];
    float s = v.x+v.y+v.z+v.w;
    #pragma unroll
    for (int o=16;o;o>>=1) s += __shfl_xor_sync(~0u, s, o);
    float mean = s * (1.f/128.f);
    float dx=v.x-mean, dy=v.y-mean, dz=v.z-mean, dw=v.w-mean;
    float q = dx*dx+dy*dy+dz*dz+dw*dw;
    #pragma unroll
    for (int o=16;o;o>>=1) q += __shfl_xor_sync(~0u, q, o);
    float rstd = rsqrtf(q*(1.f/128.f) + 1e-5f);
    float4 gv = ((const float4*)g)[lane];
    float4 bv = ((const float4*)b)[lane];
    float4 ov;
    ov.x = dx*rstd*gv.x + bv.x;
    ov.y = dy*rstd*gv.y + bv.y;
    ov.z = dz*rstd*gv.z + bv.z;
    ov.w = dw*rstd*gv.w + bv.w;
    ((float4*)(out + (size_t)warp*128))[lane] = ov;
}

// ---------------- window attention ----------------
__global__ void attn_kernel(const float* __restrict__ rpb) {
    int w = blockIdx.x >> 2;
    int head = blockIdx.x & 3;
    int b = w >> 6, wh = (w >> 3) & 7, ww = w & 7;
    __shared__ float qs[49][32], ks[49][32], vs[49][32];
    __shared__ float sc[49][49];
    int tid = threadIdx.x;
    const float scale = 0.17677669529663689f;
    for (int i = tid; i < 49*32; i += 128) {
        int n = i >> 5, d = i & 31;
        int t = ((b*56 + wh*7 + n/7)*56 + ww*7 + n%7);
        const float* base = g_qkv + (size_t)t*384 + head*32 + d;
        qs[n][d] = base[0] * scale;
        ks[n][d] = base[128];
        vs[n][d] = base[256];
    }
    __syncthreads();
    for (int idx = tid; idx < 49*49; idx += 128) {
        int i = idx/49, j = idx%49;
        float s = 0.f;
        const float4* qp = (const float4*)qs[i];
        const float4* kp = (const float4*)ks[j];
        #pragma unroll
        for (int k=0;k<8;k++){ float4 a=qp[k], c=kp[k]; s += a.x*c.x+a.y*c.y+a.z*c.z+a.w*c.w; }
        int dr = i/7 - j/7 + 6, dc = i%7 - j%7 + 6;
        sc[i][j] = s + rpb[(dr*13+dc)*4 + head];
    }
    __syncthreads();
    if (tid < 49) {
        int i = tid;
        float m = -1e30f;
        for (int j=0;j<49;j++) m = fmaxf(m, sc[i][j]);
        float sum = 0.f;
        for (int j=0;j<49;j++){ float e=__expf(sc[i][j]-m); sc[i][j]=e; sum+=e; }
        float inv = 1.f/sum;
        for (int j=0;j<49;j++) sc[i][j] *= inv;
    }
    __syncthreads();
    for (int idx = tid; idx < 49*32; idx += 128) {
        int i = idx >> 5, d = idx & 31;
        float o = 0.f;
        for (int j=0;j<49;j++) o += sc[i][j]*vs[j][d];
        int t = ((b*56 + wh*7 + i/7)*56 + ww*7 + i%7);
        g_awb[(size_t)t*128 + head*32 + d] = o;
    }
}

// ---------------- tiled causal conv (k=4) + SiLU, dual-layout output ----------------
__global__ __launch_bounds__(256) void conv_kernel(const float* __restrict__ cw,
                                                   const float* __restrict__ cb) {
    __shared__ float tile[35][256];
    int blk = blockIdx.x;
    int b = blk / 98;
    int t0 = (blk % 98) * 32;
    int tid = threadIdx.x;
    for (int idx = tid; idx < 35*256; idx += 256){
        int row = idx >> 8, col = idx & 255;
        int tg = t0 + row - 3;
        tile[row][col] = (tg >= 0) ? g_xz[((size_t)(b*LSEQ + tg))*512 + col] : 0.f;
    }
    __syncthreads();
    int d = tid;
    float w0 = cw[d*4+0], w1 = cw[d*4+1], w2 = cw[d*4+2], w3 = cw[d*4+3];
    float bb = cb[d];
    float vals[32];
    #pragma unroll 4
    for (int tt = 0; tt < 32; tt++){
        float acc = bb
            + w0*tile[tt+0][d] + w1*tile[tt+1][d]
            + w2*tile[tt+2][d] + w3*tile[tt+3][d];
        float sg = 1.f/(1.f+__expf(-acc));
        float v = acc * sg;
        vals[tt] = v;
        g_xc[((size_t)(b*LSEQ + t0 + tt))*256 + d] = v;
    }
    float* dstT = g_xcT + (size_t)d*TOK + b*LSEQ + t0;
    #pragma unroll
    for (int i=0;i<8;i++)
        ((float4*)dstT)[i] = make_float4(vals[4*i+0], vals[4*i+1], vals[4*i+2], vals[4*i+3]);
}

// ---------------- dt_proj + softplus -> transposed dtT[d][t] ----------------
__global__ __launch_bounds__(256) void dtproj_kernel(const float* __restrict__ wt,
                                                     const float* __restrict__ bias){
    int t0 = blockIdx.x * 32;
    int d = threadIdx.x;
    float wr[8];
    #pragma unroll
    for (int k=0;k<8;k++) wr[k] = wt[d*8+k];
    float bb = bias[d];
    float vals[32];
    #pragma unroll 4
    for (int tt=0; tt<32; tt++){
        const float4* r = (const float4*)(g_dbl + (size_t)(t0+tt)*40);
        float4 r0 = r[0], r1 = r[1];
        float acc = bb + r0.x*wr[0] + r0.y*wr[1] + r0.z*wr[2] + r0.w*wr[3]
                       + r1.x*wr[4] + r1.y*wr[5] + r1.z*wr[6] + r1.w*wr[7];
        vals[tt] = (acc > 20.f) ? acc : log1pf(__expf(acc));
    }
    float* dst = g_dtT + (size_t)d*TOK + t0;
    #pragma unroll
    for (int i=0;i<8;i++)
        ((float4*)dst)[i] = make_float4(vals[4*i+0], vals[4*i+1], vals[4*i+2], vals[4*i+3]);
}

// ============ chunk-parallel selective scan (staged loads, block-shared B/C) ============
__global__ __launch_bounds__(256) void scan_phase1(const float* __restrict__ A_log){
    __shared__ float sdt[8][2][64], sxc[8][2][64];
    __shared__ float sB[64][16];
    int warp = threadIdx.x >> 5, lane = threadIdx.x & 31;
    int gw = blockIdx.x * 8 + warp;
    int dpair = gw & 127;
    int d = dpair*2 + (lane >> 4);
    int s = lane & 15;
    float Aval = -__expf(A_log[d*16 + s]);
    // block-uniform chunk/batch (blocks never straddle chunk or batch boundaries)
    int gw0 = blockIdx.x * 8;
    int chunk = (gw0 >> 7) % NCH;
    int b = gw0 / (128*NCH);
    int tb = b*LSEQ + chunk*CH;
    // stage B for whole block: 1 float4 per thread
    {
        int tt = threadIdx.x >> 2, q = (threadIdx.x & 3)*4;
        *(float4*)&sB[tt][q] = *(const float4*)&g_dbl[(size_t)(tb+tt)*40 + 8 + q];
    }
    // per-warp dt/xc staging
    {
        int rr = lane >> 4, c4 = (lane & 15)*4;
        int dbase = dpair*2;
        *(float4*)&sdt[warp][rr][c4] = *(const float4*)&g_dtT[(size_t)(dbase+rr)*TOK + tb + c4];
        *(float4*)&sxc[warp][rr][c4] = *(const float4*)&g_xcT[(size_t)(dbase+rr)*TOK + tb + c4];
    }
    __syncthreads();
    int rr = lane >> 4;
    float h = 0.f, sd = 0.f;
    #pragma unroll 1
    for (int g = 0; g < CH; g += 8) {
        #pragma unroll
        for (int u=0;u<8;u++){
            float dtv = sdt[warp][rr][g+u];
            float xcv = sxc[warp][rr][g+u];
            float Bv  = sB[g+u][s];
            sd += dtv;
            float a = __expf(dtv*Aval);
            h = a*h + dtv*Bv*xcv;
        }
    }
    size_t hidx = ((size_t)(b*NCH + chunk)*256 + d)*16 + s;
    g_hend[hidx] = h;
    if (s == 0) g_sumdt[(b*NCH + chunk)*256 + d] = sd;
}

// Phase 2: serial chain, batched prefetch of 8 chunks
__global__ __launch_bounds__(256) void scan_phase2(const float* __restrict__ A_log){
    int gw = (blockIdx.x*blockDim.x + threadIdx.x) >> 5;
    int lane = threadIdx.x & 31;
    int b = gw >> 7;
    int dpair = gw & 127;
    int d = dpair*2 + (lane >> 4);
    int s = lane & 15;
    float Aval = -__expf(A_log[d*16 + s]);
    float h = 0.f;
    size_t hb = ((size_t)(b*NCH)*256 + d)*16 + s;
    int    sb = (b*NCH)*256 + d;
    #pragma unroll 1
    for (int c0 = 0; c0 < 48; c0 += 8){
        float sd[8], he[8];
        #pragma unroll
        for (int u=0;u<8;u++){
            sd[u] = g_sumdt[sb + (c0+u)*256];
            he[u] = g_hend[hb + (size_t)(c0+u)*4096];
        }
        float dec[8];
        #pragma unroll
        for (int u=0;u<8;u++) dec[u] = __expf(Aval*sd[u]);
        #pragma unroll
        for (int u=0;u<8;u++){
            g_hin[hb + (size_t)(c0+u)*4096] = h;
            h = dec[u]*h + he[u];
        }
    }
    g_hin[hb + (size_t)48*4096] = h;
}

__global__ __launch_bounds__(256) void scan_phase3(const float* __restrict__ A_log,
                                                   const float* __restrict__ Dp){
    __shared__ float part[8*32*33];
    __shared__ float sdt[8][2][64], sxc[8][2][64];
    __shared__ float sB[64][16], sC[64][16];
    int warp = threadIdx.x >> 5, lane = threadIdx.x & 31;
    int gw = blockIdx.x * 8 + warp;
    int dpair = gw & 127;
    int dbase = dpair*2;
    int d = dbase + (lane >> 4);
    int s = lane & 15;
    float Aval = -__expf(A_log[d*16 + s]);
    float dp0 = Dp[dbase], dp1 = Dp[dbase+1];
    int gw0 = blockIdx.x * 8;
    int chunk = (gw0 >> 7) % NCH;
    int b = gw0 / (128*NCH);
    int tb = b*LSEQ + chunk*CH;
    size_t hidx = ((size_t)(b*NCH + chunk)*256 + d)*16 + s;
    float h = g_hin[hidx];
    float* pp = part + warp*32*33 + lane*33;
    float* wp = part + warp*32*33;
    // block-shared B/C staging
    {
        int tt = threadIdx.x >> 2, q = (threadIdx.x & 3)*4;
        *(float4*)&sB[tt][q] = *(const float4*)&g_dbl[(size_t)(tb+tt)*40 + 8 + q];
        *(float4*)&sC[tt][q] = *(const float4*)&g_dbl[(size_t)(tb+tt)*40 + 24 + q];
    }
    // per-warp dt/xc staging
    {
        int rr = lane >> 4, c4 = (lane & 15)*4;
        *(float4*)&sdt[warp][rr][c4] = *(const float4*)&g_dtT[(size_t)(dbase+rr)*TOK + tb + c4];
        *(float4*)&sxc[warp][rr][c4] = *(const float4*)&g_xcT[(size_t)(dbase+rr)*TOK + tb + c4];
    }
    __syncthreads();
    int rr = lane >> 4;
    #pragma unroll 1
    for (int half = 0; half < 2; half++) {
        int base = half*32;
        #pragma unroll 1
        for (int g = 0; g < 32; g += 8) {
            #pragma unroll
            for (int u=0;u<8;u++){
                float dtv = sdt[warp][rr][base+g+u];
                float xcv = sxc[warp][rr][base+g+u];
                float Bv  = sB[base+g+u][s];
                float Cv  = sC[base+g+u][s];
                float a = __expf(dtv*Aval);
                h = a*h + dtv*Bv*xcv;
                pp[g+u] = h * Cv;
            }
        }
        __syncwarp();
        {
            int lu = lane;
            int t = tb + base + lu;
            float y0 = 0.f, y1 = 0.f;
            #pragma unroll
            for (int ss=0; ss<16; ss++){
                y0 += wp[ss*33 + lu];
                y1 += wp[(16+ss)*33 + lu];
            }
            float xc0 = sxc[warp][0][base+lu];
            float xc1 = sxc[warp][1][base+lu];
            float2 zv = *(const float2*)&g_xz[(size_t)t*512 + 256 + dbase];
            float yv0 = y0 + xc0*dp0;
            float yv1 = y1 + xc1*dp1;
            float sg0 = 1.f/(1.f+__expf(-zv.x));
            float sg1 = 1.f/(1.f+__expf(-zv.y));
            *(float2*)&g_y[(size_t)t*256 + dbase] = make_float2(yv0*zv.x*sg0, yv1*zv.y*sg1);
        }
        __syncwarp();
    }
}

// ---------------- launch ----------------
extern "C" void kernel_launch(void* const* d_in, const int* in_sizes, int n_in,
                              void* d_out, int out_size) {
    const float* x        = (const float*)d_in[0];
    const float* ln1_g    = (const float*)d_in[1];
    const float* ln1_b    = (const float*)d_in[2];
    const float* qkv_w    = (const float*)d_in[3];
    const float* qkv_b    = (const float*)d_in[4];
    const float* rpb      = (const float*)d_in[5];
    const float* proj_w   = (const float*)d_in[6];
    const float* proj_b   = (const float*)d_in[7];
    const float* in_w     = (const float*)d_in[8];
    const float* in_b     = (const float*)d_in[9];
    const float* conv_w   = (const float*)d_in[10];
    const float* conv_b   = (const float*)d_in[11];
    const float* xproj_w  = (const float*)d_in[12];
    const float* dtw      = (const float*)d_in[13];
    const float* dtb      = (const float*)d_in[14];
    const float* A_log    = (const float*)d_in[15];
    const float* Dp       = (const float*)d_in[16];
    const float* out_w    = (const float*)d_in[17];
    const float* out_b    = (const float*)d_in[18];
    const float* gate_w   = (const float*)d_in[19];
    const float* gate_b   = (const float*)d_in[20];
    const float* ln2_g    = (const float*)d_in[21];
    const float* ln2_b    = (const float*)d_in[22];
    const float* mlp_w1   = (const float*)d_in[23];
    const float* mlp_b1   = (const float*)d_in[24];
    const float* mlp_w2   = (const float*)d_in[25];
    const float* mlp_b2   = (const float*)d_in[26];
    float* out = (float*)d_out;

    float *xn, *qkv, *awb, *attn, *xz, *y, *mamba, *x1, *h2, *hid, *xc, *dbl;
    cudaGetSymbolAddress((void**)&xn,    g_xn);
    cudaGetSymbolAddress((void**)&qkv,   g_qkv);
    cudaGetSymbolAddress((void**)&awb,   g_awb);
    cudaGetSymbolAddress((void**)&attn,  g_attn);
    cudaGetSymbolAddress((void**)&xz,    g_xz);
    cudaGetSymbolAddress((void**)&y,     g_y);
    cudaGetSymbolAddress((void**)&mamba, g_mamba);
    cudaGetSymbolAddress((void**)&x1,    g_x1);
    cudaGetSymbolAddress((void**)&h2,    g_h2);
    cudaGetSymbolAddress((void**)&hid,   g_hid);
    cudaGetSymbolAddress((void**)&xc,    g_xc);
    cudaGetSymbolAddress((void**)&dbl,   g_dbl);

    static cudaStream_t s_attn = nullptr;
    static cudaEvent_t ev_fork = nullptr, ev_join = nullptr;
    if (!s_attn){
        cudaStreamCreateWithFlags(&s_attn, cudaStreamNonBlocking);
        cudaEventCreateWithFlags(&ev_fork, cudaEventDisableTiming);
        cudaEventCreateWithFlags(&ev_join, cudaEventDisableTiming);
    }

    const int SM64  = 3*(2048 + 64*32)*4;    // 48 KB
    const int SM128 = 3*(2048 + 128*32)*4;   // 72 KB
    cudaFuncSetAttribute(mma_gemm<128,0,0,0,1>, cudaFuncAttributeMaxDynamicSharedMemorySize, SM128);
    cudaFuncSetAttribute(mma_gemm<128,1,0,0,0>, cudaFuncAttributeMaxDynamicSharedMemorySize, SM128);
    cudaFuncSetAttribute(mma_gemm<128,4,1,0,0>, cudaFuncAttributeMaxDynamicSharedMemorySize, SM128);
    cudaFuncSetAttribute(mma_gemm<64,0,0,0,0>,  cudaFuncAttributeMaxDynamicSharedMemorySize, SM64);
    cudaFuncSetAttribute(mma_gemm<64,0,0,1,0>,  cudaFuncAttributeMaxDynamicSharedMemorySize, SM64);
    cudaFuncSetAttribute(mma_gemm<64,3,0,0,0>,  cudaFuncAttributeMaxDynamicSharedMemorySize, SM64);

    // LN1
    ln_kernel<<<TOK/8, 256>>>(x, ln1_g, ln1_b, xn);
    // merged qkv + in_proj GEMM (N=896, K=128): n<384 -> qkv, else -> xz
    mma_gemm<128,0,0,0,1><<<dim3(7,196), 256, SM128>>>(xn, qkv_w, qkv_b, qkv, 384, 128, xz, in_w, in_b, nullptr, nullptr, nullptr);

    // ---- fork: attention branch on s_attn ----
    cudaEventRecord(ev_fork, 0);
    cudaStreamWaitEvent(s_attn, ev_fork, 0);
    attn_kernel<<<NWIN*4, 128, 0, s_attn>>>(rpb);
    mma_gemm<64,0,0,0,0><<<dim3(2,196), 256, SM64, s_attn>>>(awb, proj_w, proj_b, attn, 128, 128, nullptr, nullptr, nullptr, nullptr, nullptr, nullptr);
    cudaEventRecord(ev_join, s_attn);

    // ---- mamba branch on default stream ----
    conv_kernel<<<BATCH*98, 256>>>(conv_w, conv_b);
    mma_gemm<64,0,0,1,0><<<dim3(1,196), 256, SM64>>>(xc, xproj_w, nullptr, dbl, 40, 256, nullptr, nullptr, nullptr, nullptr, nullptr, nullptr);
    dtproj_kernel<<<TOK/32, 256>>>(dtw, dtb);
    scan_phase1<<<(BATCH*NCH*128)/8, 256>>>(A_log);
    scan_phase2<<<64, 256>>>(A_log);
    scan_phase3<<<(BATCH*NCH*128)/8, 256>>>(A_log, Dp);
    mma_gemm<64,0,0,0,0><<<dim3(2,196), 256, SM64>>>(y, out_w, out_b, mamba, 128, 256, nullptr, nullptr, nullptr, nullptr, nullptr, nullptr);

    // ---- join, then gate(+LN2 fused) + MLP ----
    cudaStreamWaitEvent(0, ev_join, 0);
    mma_gemm<128,4,1,0,0><<<dim3(1,196), 256, SM128>>>(nullptr, gate_w, gate_b, x1, 128, 256, x, attn, mamba, ln2_g, ln2_b, h2);
    mma_gemm<128,1,0,0,0><<<dim3(4,196), 256, SM128>>>(h2, mlp_w1, mlp_b1, hid, 512, 128, nullptr, nullptr, nullptr, nullptr, nullptr, nullptr);
    mma_gemm<64,3,0,0,0><<<dim3(2,196), 256, SM64>>>(hid, mlp_w2, mlp_b2, out, 128, 512, x1, nullptr, nullptr, nullptr, nullptr, nullptr);

    (void)in_sizes; (void)n_in; (void)out_size;
}

// round 15
// speedup vs baseline: 2.2694x; 1.0170x over previous
#include <cuda_runtime.h>
#include <math.h>
#include <stdint.h>

#define TOK   12544
#define BATCH 4
#define LSEQ  3136
#define NWIN  256
#define NCH   49
#define CH    64

// ---------------- scratch ----------------
__device__ float g_xn[TOK*128];
__device__ float g_qkv[TOK*384];
__device__ float g_awb[TOK*128];
__device__ float g_attn[TOK*128];
__device__ float g_xz[TOK*512];
__device__ float g_xc[TOK*256];
__device__ float g_xcT[256*TOK];
__device__ float g_dtT[256*TOK];
__device__ float g_dbl[TOK*40];
__device__ float g_y[TOK*256];
__device__ float g_x1[TOK*128];
__device__ float g_h2[TOK*128];
__device__ float g_hid[TOK*512];
__device__ float g_hend[BATCH*NCH*256*16];
__device__ float g_hin[BATCH*NCH*256*16];
__device__ float g_sumdt[BATCH*NCH*256];

__device__ __forceinline__ float gelu_f(float x){ return 0.5f*x*(1.f+erff(x*0.70710678118f)); }
__device__ __forceinline__ uint32_t smem_u32(const void* p){
    uint32_t a; asm("{ .reg .u64 t; cvta.to.shared.u64 t, %1; cvt.u32.u64 %0, t; }" : "=r"(a) : "l"(p)); return a;
}
__device__ __forceinline__ void cpa16(uint32_t dst, const void* src){
    asm volatile("cp.async.cg.shared.global [%0], [%1], 16;" :: "r"(dst), "l"(src));
}
__device__ __forceinline__ void cpa16z(uint32_t dst, const void* src){
    asm volatile("cp.async.cg.shared.global [%0], [%1], 16, 0;" :: "r"(dst), "l"(src));
}
__device__ __forceinline__ void ldsm4(uint32_t* d, uint32_t addr){
    asm volatile("ldmatrix.sync.aligned.m8n8.x4.shared.b16 {%0,%1,%2,%3}, [%4];"
        : "=r"(d[0]),"=r"(d[1]),"=r"(d[2]),"=r"(d[3]) : "r"(addr));
}
__device__ __forceinline__ void mma8(float* c, const uint32_t* a, const uint32_t* b){
    asm volatile("mma.sync.aligned.m16n8k8.row.col.f32.tf32.tf32.f32 "
        "{%0,%1,%2,%3}, {%4,%5,%6,%7}, {%8,%9}, {%0,%1,%2,%3};"
        : "+f"(c[0]),"+f"(c[1]),"+f"(c[2]),"+f"(c[3])
        : "r"(a[0]),"r"(a[1]),"r"(a[2]),"r"(a[3]), "r"(b[0]),"r"(b[1]));
}

// ================= cp.async + ldmatrix tf32 mma GEMM =================
// EPI: 0 none, 1 gelu, 3 residual(e0). AG unused here. NP pad. QI merged qkv+in_proj.
template<int NT, int EPI, int AG, int NP, int QI>
__global__ __launch_bounds__(256)
void mma_gemm(const float* __restrict__ A, const float* __restrict__ W,
              const float* __restrict__ bias, float* __restrict__ C,
              int Nout, int K,
              const float* __restrict__ e0, const float* __restrict__ e1,
              const float* __restrict__ e2)
{
    extern __shared__ float sm[];
    const int NW  = NT/32;
    const int MW  = 8/NW;
    const int MT  = 64/(16*MW);
    const int STG = 2048 + NT*32;
    const int BCH = (NT*8)/256;
    uint32_t sbase = smem_u32(sm);
    int tid = threadIdx.x, wid = tid>>5, lane = tid&31;
    int warp_n = wid % NW, warp_m = wid / NW;
    int bm = blockIdx.y*64, bn = blockIdx.x*NT;
    int m0 = warp_m * MT * 16;

    float acc[MT][4][4];
    #pragma unroll
    for (int i=0;i<MT;i++)
        #pragma unroll
        for (int j=0;j<4;j++)
            #pragma unroll
            for (int q=0;q<4;q++) acc[i][j][q]=0.f;

    auto issue = [&](int kt){
        int st = kt % 3;
        uint32_t abase = sbase + (uint32_t)st*STG*4;
        uint32_t bbase = abase + 2048*4;
        int kc = kt*32;
        #pragma unroll
        for (int i=0;i<2;i++){
            int ch = tid + i*256;
            int row = ch>>3, col = (ch&7)*4;
            uint32_t dst = abase + (uint32_t)(row*32 + (col ^ ((row&7)<<2)))*4;
            const float* src;
            if (AG){
                int kg = kc + col;
                src = (kg<128) ? e1 + (size_t)(bm+row)*128 + kg
                               : e2 + (size_t)(bm+row)*128 + (kg-128);
            } else {
                src = A + (size_t)(bm+row)*K + kc + col;
            }
            cpa16(dst, src);
        }
        #pragma unroll
        for (int i=0;i<BCH;i++){
            int ch = tid + i*256;
            int row = ch>>3, col = (ch&7)*4;
            uint32_t dst = bbase + (uint32_t)(row*32 + (col ^ ((row&7)<<2)))*4;
            if (QI){
                int rw = bn + row;
                const float* src = (rw < 384) ? W + (size_t)rw*K + kc + col
                                              : e1 + (size_t)(rw-384)*K + kc + col;
                cpa16(dst, src);
            } else if (NP && (bn+row) >= Nout) {
                cpa16z(dst, W);
            } else {
                cpa16(dst, W + (size_t)(bn+row)*K + kc + col);
            }
        }
        asm volatile("cp.async.commit_group;" ::: "memory");
    };

    int KT = K >> 5;
    issue(0);
    issue(1);

    int a_r  = m0 + (lane&7) + ((lane>>3)&1)*8;
    int a_cq = (lane>>4)*4;
    int b_nb = warp_n*32 + ((lane>>4))*8 + (lane&7);
    int b_kq = ((lane>>3)&1)*4;

    for (int kt=0; kt<KT; kt++){
        if (kt == KT-1) asm volatile("cp.async.wait_group 0;" ::: "memory");
        else            asm volatile("cp.async.wait_group 1;" ::: "memory");
        __syncthreads();
        if (kt+2 < KT) issue(kt+2);

        uint32_t abase = sbase + (uint32_t)((kt%3)*STG)*4;
        uint32_t bbase = abase + 2048*4;
        #pragma unroll
        for (int ks=0; ks<4; ks++){
            uint32_t af[MT][4];
            #pragma unroll
            for (int i=0;i<MT;i++){
                int r = a_r + i*16;
                int c = (ks*8 + a_cq) ^ ((r&7)<<2);
                ldsm4(af[i], abase + (uint32_t)(r*32 + c)*4);
            }
            uint32_t bf[2][4];
            #pragma unroll
            for (int j2=0;j2<2;j2++){
                int n = b_nb + j2*16;
                int c = (ks*8 + b_kq) ^ ((n&7)<<2);
                ldsm4(bf[j2], bbase + (uint32_t)(n*32 + c)*4);
            }
            #pragma unroll
            for (int i=0;i<MT;i++)
                #pragma unroll
                for (int j2=0;j2<2;j2++)
                    #pragma unroll
                    for (int jj=0;jj<2;jj++)
                        mma8(acc[i][2*j2+jj], af[i], &bf[j2][2*jj]);
        }
    }

    #pragma unroll
    for (int i=0;i<MT;i++){
        #pragma unroll
        for (int j=0;j<4;j++){
            int n = bn + warp_n*32 + j*8 + 2*(lane&3);
            if (NP && n >= Nout) continue;
            #pragma unroll
            for (int half=0; half<2; half++){
                int m = bm + m0 + i*16 + (lane>>2) + half*8;
                float vx = acc[i][j][half*2+0];
                float vy = acc[i][j][half*2+1];
                if (QI){
                    if (bn < 384){
                        float2 bv = *(const float2*)(bias + n);
                        vx += bv.x; vy += bv.y;
                        *(float2*)(C + (size_t)m*384 + n) = make_float2(vx, vy);
                    } else {
                        int n2 = n - 384;
                        float2 bv = *(const float2*)(e2 + n2);
                        vx += bv.x; vy += bv.y;
                        *(float2*)((float*)e0 + (size_t)m*512 + n2) = make_float2(vx, vy);
                    }
                    continue;
                }
                float2 bv = bias ? *(const float2*)(bias + n) : make_float2(0.f,0.f);
                vx += bv.x; vy += bv.y;
                size_t idx = (size_t)m*Nout + n;
                if (EPI == 1){
                    vx = gelu_f(vx); vy = gelu_f(vy);
                } else if (EPI == 3){
                    float2 r0 = *(const float2*)(e0 + idx);
                    vx += r0.x; vy += r0.y;
                }
                *(float2*)(C + idx) = make_float2(vx, vy);
            }
        }
    }
}

// ================= fused out_proj + gate + LN2 =================
// grid (1, 196), 256 threads. Phase A: mamba = y@out_w^T + out_b -> smem (A-stage fmt).
// Phase B: gate = [attn|mamba]@gate_w^T + gate_b; blend + x1 + LN2 -> h2.
__global__ __launch_bounds__(256)
void fused_out_gate(const float* __restrict__ y, const float* __restrict__ out_w,
                    const float* __restrict__ out_b,
                    const float* __restrict__ gate_w, const float* __restrict__ gate_b,
                    const float* __restrict__ x, const float* __restrict__ attn,
                    float* __restrict__ x1,
                    const float* __restrict__ ln_g, const float* __restrict__ ln_b,
                    float* __restrict__ h2)
{
    extern __shared__ float sm[];
    const int NT = 128, NW = 4, MT = 2;
    const int STG = 2048 + NT*32;            // 6144 floats
    float* msbuf = sm + 3*STG;               // 4 x 2048 floats (mamba k-tiles)
    uint32_t sbase = smem_u32(sm);
    uint32_t msbase = sbase + (uint32_t)(3*STG)*4;
    int tid = threadIdx.x, wid = tid>>5, lane = tid&31;
    int warp_n = wid % NW, warp_m = wid / NW;
    int bm = blockIdx.y*64;
    int m0 = warp_m * MT * 16;

    float acc[MT][4][4];
    #pragma unroll
    for (int i=0;i<MT;i++)
        #pragma unroll
        for (int j=0;j<4;j++)
            #pragma unroll
            for (int q=0;q<4;q++) acc[i][j][q]=0.f;

    int a_r  = m0 + (lane&7) + ((lane>>3)&1)*8;
    int a_cq = (lane>>4)*4;
    int b_nb = warp_n*32 + ((lane>>4))*8 + (lane&7);
    int b_kq = ((lane>>3)&1)*4;

    // ---------- Phase A: mamba tile ----------
    auto issueA = [&](int kt){
        int st = kt % 3;
        uint32_t abase = sbase + (uint32_t)st*STG*4;
        uint32_t bbase = abase + 2048*4;
        int kc = kt*32;
        #pragma unroll
        for (int i=0;i<2;i++){
            int ch = tid + i*256;
            int row = ch>>3, col = (ch&7)*4;
            uint32_t dst = abase + (uint32_t)(row*32 + (col ^ ((row&7)<<2)))*4;
            cpa16(dst, y + (size_t)(bm+row)*256 + kc + col);
        }
        #pragma unroll
        for (int i=0;i<4;i++){
            int ch = tid + i*256;
            int row = ch>>3, col = (ch&7)*4;
            uint32_t dst = bbase + (uint32_t)(row*32 + (col ^ ((row&7)<<2)))*4;
            cpa16(dst, out_w + (size_t)row*256 + kc + col);
        }
        asm volatile("cp.async.commit_group;" ::: "memory");
    };
    issueA(0); issueA(1);
    for (int kt=0; kt<8; kt++){
        if (kt == 7) asm volatile("cp.async.wait_group 0;" ::: "memory");
        else         asm volatile("cp.async.wait_group 1;" ::: "memory");
        __syncthreads();
        if (kt+2 < 8) issueA(kt+2);
        uint32_t abase = sbase + (uint32_t)((kt%3)*STG)*4;
        uint32_t bbase = abase + 2048*4;
        #pragma unroll
        for (int ks=0; ks<4; ks++){
            uint32_t af[MT][4];
            #pragma unroll
            for (int i=0;i<MT;i++){
                int r = a_r + i*16;
                int c = (ks*8 + a_cq) ^ ((r&7)<<2);
                ldsm4(af[i], abase + (uint32_t)(r*32 + c)*4);
            }
            uint32_t bf[2][4];
            #pragma unroll
            for (int j2=0;j2<2;j2++){
                int n = b_nb + j2*16;
                int c = (ks*8 + b_kq) ^ ((n&7)<<2);
                ldsm4(bf[j2], bbase + (uint32_t)(n*32 + c)*4);
            }
            #pragma unroll
            for (int i=0;i<MT;i++)
                #pragma unroll
                for (int j2=0;j2<2;j2++)
                    #pragma unroll
                    for (int jj=0;jj<2;jj++)
                        mma8(acc[i][2*j2+jj], af[i], &bf[j2][2*jj]);
        }
    }
    __syncthreads();
    // write mamba tile to msbuf in A-stage swizzled format (+bias)
    #pragma unroll
    for (int i=0;i<MT;i++){
        #pragma unroll
        for (int j=0;j<4;j++){
            int n = warp_n*32 + j*8 + 2*(lane&3);
            float2 bv = *(const float2*)(out_b + n);
            #pragma unroll
            for (int half=0; half<2; half++){
                int r = m0 + i*16 + (lane>>2) + half*8;
                float vx = acc[i][j][half*2+0] + bv.x;
                float vy = acc[i][j][half*2+1] + bv.y;
                int ktm = n>>5, c = n&31, sw = (r&7)<<2;
                msbuf[ktm*2048 + r*32 + (c^sw)]     = vx;
                msbuf[ktm*2048 + r*32 + ((c^sw)+1)] = vy;   // low bit unaffected by sw
            }
        }
    }
    __syncthreads();

    // ---------- Phase B: gate ----------
    #pragma unroll
    for (int i=0;i<MT;i++)
        #pragma unroll
        for (int j=0;j<4;j++)
            #pragma unroll
            for (int q=0;q<4;q++) acc[i][j][q]=0.f;

    // kt 0..3: A = mamba (resident), gate_w cols 128+kt*32
    // kt 4..7: A = attn (cp.async), gate_w cols (kt-4)*32
    auto issueB = [&](int kt){
        int st = kt % 3;
        uint32_t abase = sbase + (uint32_t)st*STG*4;
        uint32_t bbase = abase + 2048*4;
        int bcol = (kt < 4) ? 128 + kt*32 : (kt-4)*32;
        if (kt >= 4){
            int acol = (kt-4)*32;
            #pragma unroll
            for (int i=0;i<2;i++){
                int ch = tid + i*256;
                int row = ch>>3, col = (ch&7)*4;
                uint32_t dst = abase + (uint32_t)(row*32 + (col ^ ((row&7)<<2)))*4;
                cpa16(dst, attn + (size_t)(bm+row)*128 + acol + col);
            }
        }
        #pragma unroll
        for (int i=0;i<4;i++){
            int ch = tid + i*256;
            int row = ch>>3, col = (ch&7)*4;
            uint32_t dst = bbase + (uint32_t)(row*32 + (col ^ ((row&7)<<2)))*4;
            cpa16(dst, gate_w + (size_t)row*256 + bcol + col);
        }
        asm volatile("cp.async.commit_group;" ::: "memory");
    };
    issueB(0); issueB(1);
    for (int kt=0; kt<8; kt++){
        if (kt == 7) asm volatile("cp.async.wait_group 0;" ::: "memory");
        else         asm volatile("cp.async.wait_group 1;" ::: "memory");
        __syncthreads();
        if (kt+2 < 8) issueB(kt+2);
        uint32_t abase = (kt < 4) ? (msbase + (uint32_t)kt*2048*4)
                                  : (sbase + (uint32_t)((kt%3)*STG)*4);
        uint32_t bbase = sbase + (uint32_t)((kt%3)*STG)*4 + 2048*4;
        #pragma unroll
        for (int ks=0; ks<4; ks++){
            uint32_t af[MT][4];
            #pragma unroll
            for (int i=0;i<MT;i++){
                int r = a_r + i*16;
                int c = (ks*8 + a_cq) ^ ((r&7)<<2);
                ldsm4(af[i], abase + (uint32_t)(r*32 + c)*4);
            }
            uint32_t bf[2][4];
            #pragma unroll
            for (int j2=0;j2<2;j2++){
                int n = b_nb + j2*16;
                int c = (ks*8 + b_kq) ^ ((n&7)<<2);
                ldsm4(bf[j2], bbase + (uint32_t)(n*32 + c)*4);
            }
            #pragma unroll
            for (int i=0;i<MT;i++)
                #pragma unroll
                for (int j2=0;j2<2;j2++)
                    #pragma unroll
                    for (int jj=0;jj<2;jj++)
                        mma8(acc[i][2*j2+jj], af[i], &bf[j2][2*jj]);
        }
    }

    // ---------- epilogue: blend + x1 + LN2 -> h2 ----------
    float* xs = sm;                          // 64 x 129 (pipeline region is free)
    __syncthreads();
    #pragma unroll
    for (int i=0;i<MT;i++){
        #pragma unroll
        for (int j=0;j<4;j++){
            int n = warp_n*32 + j*8 + 2*(lane&3);
            float2 bv = *(const float2*)(gate_b + n);
            #pragma unroll
            for (int half=0; half<2; half++){
                int r = m0 + i*16 + (lane>>2) + half*8;
                int m = bm + r;
                float vx = acc[i][j][half*2+0] + bv.x;
                float vy = acc[i][j][half*2+1] + bv.y;
                size_t idx = (size_t)m*128 + n;
                float2 r0 = *(const float2*)(x + idx);
                float2 r1 = *(const float2*)(attn + idx);
                int ktm = n>>5, c = n&31, sw = (r&7)<<2;
                float m2x = msbuf[ktm*2048 + r*32 + (c^sw)];
                float m2y = msbuf[ktm*2048 + r*32 + ((c^sw)+1)];
                float gx = 1.f/(1.f+__expf(-vx));
                float gy = 1.f/(1.f+__expf(-vy));
                vx = r0.x + gx*r1.x + (1.f-gx)*m2x;
                vy = r0.y + gy*r1.y + (1.f-gy)*m2y;
                *(float2*)(x1 + idx) = make_float2(vx, vy);
                xs[r*129 + n]     = vx;
                xs[r*129 + n + 1] = vy;
            }
        }
    }
    __syncthreads();
    #pragma unroll 1
    for (int rr=0; rr<8; rr++){
        int r = wid*8 + rr;
        float v0 = xs[r*129 + lane];
        float v1 = xs[r*129 + lane + 32];
        float v2 = xs[r*129 + lane + 64];
        float v3 = xs[r*129 + lane + 96];
        float s = v0+v1+v2+v3;
        #pragma unroll
        for (int o=16;o;o>>=1) s += __shfl_xor_sync(~0u, s, o);
        float mean = s * (1.f/128.f);
        float d0=v0-mean, d1=v1-mean, d2=v2-mean, d3=v3-mean;
        float q = d0*d0+d1*d1+d2*d2+d3*d3;
        #pragma unroll
        for (int o=16;o;o>>=1) q += __shfl_xor_sync(~0u, q, o);
        float rstd = rsqrtf(q*(1.f/128.f) + 1e-5f);
        size_t mb = (size_t)(bm + r)*128;
        h2[mb + lane]      = d0*rstd*ln_g[lane]      + ln_b[lane];
        h2[mb + lane + 32] = d1*rstd*ln_g[lane + 32] + ln_b[lane + 32];
        h2[mb + lane + 64] = d2*rstd*ln_g[lane + 64] + ln_b[lane + 64];
        h2[mb + lane + 96] = d3*rstd*ln_g[lane + 96] + ln_b[lane + 96];
    }
}

// ---------------- LayerNorm ----------------
__global__ void ln_kernel(const float* __restrict__ in, const float* __restrict__ g,
                          const float* __restrict__ b, float* __restrict__ out) {
    int warp = (blockIdx.x * blockDim.x + threadIdx.x) >> 5;
    int lane = threadIdx.x & 31;
    if (warp >= TOK) return;
    float4 v = ((const float4*)(in + (size_t)warp*128))[lane];
    float s = v.x+v.y+v.z+v.w;
    #pragma unroll
    for (int o=16;o;o>>=1) s += __shfl_xor_sync(~0u, s, o);
    float mean = s * (1.f/128.f);
    float dx=v.x-mean, dy=v.y-mean, dz=v.z-mean, dw=v.w-mean;
    float q = dx*dx+dy*dy+dz*dz+dw*dw;
    #pragma unroll
    for (int o=16;o;o>>=1) q += __shfl_xor_sync(~0u, q, o);
    float rstd = rsqrtf(q*(1.f/128.f) + 1e-5f);
    float4 gv = ((const float4*)g)[lane];
    float4 bv = ((const float4*)b)[lane];
    float4 ov;
    ov.x = dx*rstd*gv.x + bv.x;
    ov.y = dy*rstd*gv.y + bv.y;
    ov.z = dz*rstd*gv.z + bv.z;
    ov.w = dw*rstd*gv.w + bv.w;
    ((float4*)(out + (size_t)warp*128))[lane] = ov;
}

// ---------------- window attention ----------------
__global__ void attn_kernel(const float* __restrict__ rpb) {
    int w = blockIdx.x >> 2;
    int head = blockIdx.x & 3;
    int b = w >> 6, wh = (w >> 3) & 7, ww = w & 7;
    __shared__ float qs[49][32], ks[49][32], vs[49][32];
    __shared__ float sc[49][49];
    int tid = threadIdx.x;
    const float scale = 0.17677669529663689f;
    for (int i = tid; i < 49*32; i += 128) {
        int n = i >> 5, d = i & 31;
        int t = ((b*56 + wh*7 + n/7)*56 + ww*7 + n%7);
        const float* base = g_qkv + (size_t)t*384 + head*32 + d;
        qs[n][d] = base[0] * scale;
        ks[n][d] = base[128];
        vs[n][d] = base[256];
    }
    __syncthreads();
    for (int idx = tid; idx < 49*49; idx += 128) {
        int i = idx/49, j = idx%49;
        float s = 0.f;
        const float4* qp = (const float4*)qs[i];
        const float4* kp = (const float4*)ks[j];
        #pragma unroll
        for (int k=0;k<8;k++){ float4 a=qp[k], c=kp[k]; s += a.x*c.x+a.y*c.y+a.z*c.z+a.w*c.w; }
        int dr = i/7 - j/7 + 6, dc = i%7 - j%7 + 6;
        sc[i][j] = s + rpb[(dr*13+dc)*4 + head];
    }
    __syncthreads();
    if (tid < 49) {
        int i = tid;
        float m = -1e30f;
        for (int j=0;j<49;j++) m = fmaxf(m, sc[i][j]);
        float sum = 0.f;
        for (int j=0;j<49;j++){ float e=__expf(sc[i][j]-m); sc[i][j]=e; sum+=e; }
        float inv = 1.f/sum;
        for (int j=0;j<49;j++) sc[i][j] *= inv;
    }
    __syncthreads();
    for (int idx = tid; idx < 49*32; idx += 128) {
        int i = idx >> 5, d = idx & 31;
        float o = 0.f;
        for (int j=0;j<49;j++) o += sc[i][j]*vs[j][d];
        int t = ((b*56 + wh*7 + i/7)*56 + ww*7 + i%7);
        g_awb[(size_t)t*128 + head*32 + d] = o;
    }
}

// ---------------- tiled causal conv (k=4) + SiLU, dual-layout output ----------------
__global__ __launch_bounds__(256) void conv_kernel(const float* __restrict__ cw,
                                                   const float* __restrict__ cb) {
    __shared__ float tile[35][256];
    int blk = blockIdx.x;
    int b = blk / 98;
    int t0 = (blk % 98) * 32;
    int tid = threadIdx.x;
    for (int idx = tid; idx < 35*256; idx += 256){
        int row = idx >> 8, col = idx & 255;
        int tg = t0 + row - 3;
        tile[row][col] = (tg >= 0) ? g_xz[((size_t)(b*LSEQ + tg))*512 + col] : 0.f;
    }
    __syncthreads();
    int d = tid;
    float w0 = cw[d*4+0], w1 = cw[d*4+1], w2 = cw[d*4+2], w3 = cw[d*4+3];
    float bb = cb[d];
    float vals[32];
    #pragma unroll 4
    for (int tt = 0; tt < 32; tt++){
        float acc = bb
            + w0*tile[tt+0][d] + w1*tile[tt+1][d]
            + w2*tile[tt+2][d] + w3*tile[tt+3][d];
        float sg = 1.f/(1.f+__expf(-acc));
        float v = acc * sg;
        vals[tt] = v;
        g_xc[((size_t)(b*LSEQ + t0 + tt))*256 + d] = v;
    }
    float* dstT = g_xcT + (size_t)d*TOK + b*LSEQ + t0;
    #pragma unroll
    for (int i=0;i<8;i++)
        ((float4*)dstT)[i] = make_float4(vals[4*i+0], vals[4*i+1], vals[4*i+2], vals[4*i+3]);
}

// ---------------- dt_proj + softplus -> transposed dtT[d][t] ----------------
__global__ __launch_bounds__(256) void dtproj_kernel(const float* __restrict__ wt,
                                                     const float* __restrict__ bias){
    int t0 = blockIdx.x * 32;
    int d = threadIdx.x;
    float wr[8];
    #pragma unroll
    for (int k=0;k<8;k++) wr[k] = wt[d*8+k];
    float bb = bias[d];
    float vals[32];
    #pragma unroll 4
    for (int tt=0; tt<32; tt++){
        const float4* r = (const float4*)(g_dbl + (size_t)(t0+tt)*40);
        float4 r0 = r[0], r1 = r[1];
        float acc = bb + r0.x*wr[0] + r0.y*wr[1] + r0.z*wr[2] + r0.w*wr[3]
                       + r1.x*wr[4] + r1.y*wr[5] + r1.z*wr[6] + r1.w*wr[7];
        vals[tt] = (acc > 20.f) ? acc : log1pf(__expf(acc));
    }
    float* dst = g_dtT + (size_t)d*TOK + t0;
    #pragma unroll
    for (int i=0;i<8;i++)
        ((float4*)dst)[i] = make_float4(vals[4*i+0], vals[4*i+1], vals[4*i+2], vals[4*i+3]);
}

// ============ chunk-parallel selective scan (staged loads, block-shared B/C) ============
__global__ __launch_bounds__(256) void scan_phase1(const float* __restrict__ A_log){
    __shared__ float sdt[8][2][64], sxc[8][2][64];
    __shared__ float sB[64][16];
    int warp = threadIdx.x >> 5, lane = threadIdx.x & 31;
    int gw = blockIdx.x * 8 + warp;
    int dpair = gw & 127;
    int d = dpair*2 + (lane >> 4);
    int s = lane & 15;
    float Aval = -__expf(A_log[d*16 + s]);
    int gw0 = blockIdx.x * 8;
    int chunk = (gw0 >> 7) % NCH;
    int b = gw0 / (128*NCH);
    int tb = b*LSEQ + chunk*CH;
    {
        int tt = threadIdx.x >> 2, q = (threadIdx.x & 3)*4;
        *(float4*)&sB[tt][q] = *(const float4*)&g_dbl[(size_t)(tb+tt)*40 + 8 + q];
    }
    {
        int rr = lane >> 4, c4 = (lane & 15)*4;
        int dbase = dpair*2;
        *(float4*)&sdt[warp][rr][c4] = *(const float4*)&g_dtT[(size_t)(dbase+rr)*TOK + tb + c4];
        *(float4*)&sxc[warp][rr][c4] = *(const float4*)&g_xcT[(size_t)(dbase+rr)*TOK + tb + c4];
    }
    __syncthreads();
    int rr = lane >> 4;
    float h = 0.f, sd = 0.f;
    #pragma unroll 1
    for (int g = 0; g < CH; g += 8) {
        #pragma unroll
        for (int u=0;u<8;u++){
            float dtv = sdt[warp][rr][g+u];
            float xcv = sxc[warp][rr][g+u];
            float Bv  = sB[g+u][s];
            sd += dtv;
            float a = __expf(dtv*Aval);
            h = a*h + dtv*Bv*xcv;
        }
    }
    size_t hidx = ((size_t)(b*NCH + chunk)*256 + d)*16 + s;
    g_hend[hidx] = h;
    if (s == 0) g_sumdt[(b*NCH + chunk)*256 + d] = sd;
}

// Phase 2: serial chain, batched prefetch of 8 chunks
__global__ __launch_bounds__(128) void scan_phase2(const float* __restrict__ A_log){
    int gw = (blockIdx.x*blockDim.x + threadIdx.x) >> 5;
    int lane = threadIdx.x & 31;
    int b = gw >> 7;
    int dpair = gw & 127;
    int d = dpair*2 + (lane >> 4);
    int s = lane & 15;
    float Aval = -__expf(A_log[d*16 + s]);
    float h = 0.f;
    size_t hb = ((size_t)(b*NCH)*256 + d)*16 + s;
    int    sb = (b*NCH)*256 + d;
    #pragma unroll 1
    for (int c0 = 0; c0 < 48; c0 += 8){
        float sd[8], he[8];
        #pragma unroll
        for (int u=0;u<8;u++){
            sd[u] = g_sumdt[sb + (c0+u)*256];
            he[u] = g_hend[hb + (size_t)(c0+u)*4096];
        }
        float dec[8];
        #pragma unroll
        for (int u=0;u<8;u++) dec[u] = __expf(Aval*sd[u]);
        #pragma unroll
        for (int u=0;u<8;u++){
            g_hin[hb + (size_t)(c0+u)*4096] = h;
            h = dec[u]*h + he[u];
        }
    }
    g_hin[hb + (size_t)48*4096] = h;
}

__global__ __launch_bounds__(256) void scan_phase3(const float* __restrict__ A_log,
                                                   const float* __restrict__ Dp){
    __shared__ float part[8*32*33];
    __shared__ float sdt[8][2][64], sxc[8][2][64];
    __shared__ float sB[64][16], sC[64][16];
    int warp = threadIdx.x >> 5, lane = threadIdx.x & 31;
    int gw = blockIdx.x * 8 + warp;
    int dpair = gw & 127;
    int dbase = dpair*2;
    int d = dbase + (lane >> 4);
    int s = lane & 15;
    float Aval = -__expf(A_log[d*16 + s]);
    float dp0 = Dp[dbase], dp1 = Dp[dbase+1];
    int gw0 = blockIdx.x * 8;
    int chunk = (gw0 >> 7) % NCH;
    int b = gw0 / (128*NCH);
    int tb = b*LSEQ + chunk*CH;
    size_t hidx = ((size_t)(b*NCH + chunk)*256 + d)*16 + s;
    float h = g_hin[hidx];
    float* pp = part + warp*32*33 + lane*33;
    float* wp = part + warp*32*33;
    {
        int tt = threadIdx.x >> 2, q = (threadIdx.x & 3)*4;
        *(float4*)&sB[tt][q] = *(const float4*)&g_dbl[(size_t)(tb+tt)*40 + 8 + q];
        *(float4*)&sC[tt][q] = *(const float4*)&g_dbl[(size_t)(tb+tt)*40 + 24 + q];
    }
    {
        int rr = lane >> 4, c4 = (lane & 15)*4;
        *(float4*)&sdt[warp][rr][c4] = *(const float4*)&g_dtT[(size_t)(dbase+rr)*TOK + tb + c4];
        *(float4*)&sxc[warp][rr][c4] = *(const float4*)&g_xcT[(size_t)(dbase+rr)*TOK + tb + c4];
    }
    __syncthreads();
    int rr = lane >> 4;
    #pragma unroll 1
    for (int half = 0; half < 2; half++) {
        int base = half*32;
        #pragma unroll 1
        for (int g = 0; g < 32; g += 8) {
            #pragma unroll
            for (int u=0;u<8;u++){
                float dtv = sdt[warp][rr][base+g+u];
                float xcv = sxc[warp][rr][base+g+u];
                float Bv  = sB[base+g+u][s];
                float Cv  = sC[base+g+u][s];
                float a = __expf(dtv*Aval);
                h = a*h + dtv*Bv*xcv;
                pp[g+u] = h * Cv;
            }
        }
        __syncwarp();
        {
            int lu = lane;
            int t = tb + base + lu;
            float y0 = 0.f, y1 = 0.f;
            #pragma unroll
            for (int ss=0; ss<16; ss++){
                y0 += wp[ss*33 + lu];
                y1 += wp[(16+ss)*33 + lu];
            }
            float xc0 = sxc[warp][0][base+lu];
            float xc1 = sxc[warp][1][base+lu];
            float2 zv = *(const float2*)&g_xz[(size_t)t*512 + 256 + dbase];
            float yv0 = y0 + xc0*dp0;
            float yv1 = y1 + xc1*dp1;
            float sg0 = 1.f/(1.f+__expf(-zv.x));
            float sg1 = 1.f/(1.f+__expf(-zv.y));
            *(float2*)&g_y[(size_t)t*256 + dbase] = make_float2(yv0*zv.x*sg0, yv1*zv.y*sg1);
        }
        __syncwarp();
    }
}

// ---------------- launch ----------------
extern "C" void kernel_launch(void* const* d_in, const int* in_sizes, int n_in,
                              void* d_out, int out_size) {
    const float* x        = (const float*)d_in[0];
    const float* ln1_g    = (const float*)d_in[1];
    const float* ln1_b    = (const float*)d_in[2];
    const float* qkv_w    = (const float*)d_in[3];
    const float* qkv_b    = (const float*)d_in[4];
    const float* rpb      = (const float*)d_in[5];
    const float* proj_w   = (const float*)d_in[6];
    const float* proj_b   = (const float*)d_in[7];
    const float* in_w     = (const float*)d_in[8];
    const float* in_b     = (const float*)d_in[9];
    const float* conv_w   = (const float*)d_in[10];
    const float* conv_b   = (const float*)d_in[11];
    const float* xproj_w  = (const float*)d_in[12];
    const float* dtw      = (const float*)d_in[13];
    const float* dtb      = (const float*)d_in[14];
    const float* A_log    = (const float*)d_in[15];
    const float* Dp       = (const float*)d_in[16];
    const float* out_w    = (const float*)d_in[17];
    const float* out_b    = (const float*)d_in[18];
    const float* gate_w   = (const float*)d_in[19];
    const float* gate_b   = (const float*)d_in[20];
    const float* ln2_g    = (const float*)d_in[21];
    const float* ln2_b    = (const float*)d_in[22];
    const float* mlp_w1   = (const float*)d_in[23];
    const float* mlp_b1   = (const float*)d_in[24];
    const float* mlp_w2   = (const float*)d_in[25];
    const float* mlp_b2   = (const float*)d_in[26];
    float* out = (float*)d_out;

    float *xn, *qkv, *awb, *attn, *xz, *y, *x1, *h2, *hid, *xc, *dbl;
    cudaGetSymbolAddress((void**)&xn,    g_xn);
    cudaGetSymbolAddress((void**)&qkv,   g_qkv);
    cudaGetSymbolAddress((void**)&awb,   g_awb);
    cudaGetSymbolAddress((void**)&attn,  g_attn);
    cudaGetSymbolAddress((void**)&xz,    g_xz);
    cudaGetSymbolAddress((void**)&y,     g_y);
    cudaGetSymbolAddress((void**)&x1,    g_x1);
    cudaGetSymbolAddress((void**)&h2,    g_h2);
    cudaGetSymbolAddress((void**)&hid,   g_hid);
    cudaGetSymbolAddress((void**)&xc,    g_xc);
    cudaGetSymbolAddress((void**)&dbl,   g_dbl);

    static cudaStream_t s_attn = nullptr;
    static cudaEvent_t ev_fork = nullptr, ev_join = nullptr;
    if (!s_attn){
        cudaStreamCreateWithFlags(&s_attn, cudaStreamNonBlocking);
        cudaEventCreateWithFlags(&ev_fork, cudaEventDisableTiming);
        cudaEventCreateWithFlags(&ev_join, cudaEventDisableTiming);
    }

    const int SM64  = 3*(2048 + 64*32)*4;    // 48 KB
    const int SM128 = 3*(2048 + 128*32)*4;   // 72 KB
    const int SMFG  = (3*(2048+128*32) + 4*2048)*4;  // 106496 B
    cudaFuncSetAttribute(mma_gemm<128,0,0,0,1>, cudaFuncAttributeMaxDynamicSharedMemorySize, SM128);
    cudaFuncSetAttribute(mma_gemm<128,1,0,0,0>, cudaFuncAttributeMaxDynamicSharedMemorySize, SM128);
    cudaFuncSetAttribute(mma_gemm<64,0,0,0,0>,  cudaFuncAttributeMaxDynamicSharedMemorySize, SM64);
    cudaFuncSetAttribute(mma_gemm<64,0,0,1,0>,  cudaFuncAttributeMaxDynamicSharedMemorySize, SM64);
    cudaFuncSetAttribute(mma_gemm<64,3,0,0,0>,  cudaFuncAttributeMaxDynamicSharedMemorySize, SM64);
    cudaFuncSetAttribute(fused_out_gate,        cudaFuncAttributeMaxDynamicSharedMemorySize, SMFG);

    // LN1
    ln_kernel<<<TOK/8, 256>>>(x, ln1_g, ln1_b, xn);
    // merged qkv + in_proj GEMM (N=896, K=128): n<384 -> qkv, else -> xz
    mma_gemm<128,0,0,0,1><<<dim3(7,196), 256, SM128>>>(xn, qkv_w, qkv_b, qkv, 384, 128, xz, in_w, in_b);

    // ---- fork: attention branch on s_attn ----
    cudaEventRecord(ev_fork, 0);
    cudaStreamWaitEvent(s_attn, ev_fork, 0);
    attn_kernel<<<NWIN*4, 128, 0, s_attn>>>(rpb);
    mma_gemm<64,0,0,0,0><<<dim3(2,196), 256, SM64, s_attn>>>(awb, proj_w, proj_b, attn, 128, 128, nullptr, nullptr, nullptr);
    cudaEventRecord(ev_join, s_attn);

    // ---- mamba branch on default stream ----
    conv_kernel<<<BATCH*98, 256>>>(conv_w, conv_b);
    mma_gemm<64,0,0,1,0><<<dim3(1,196), 256, SM64>>>(xc, xproj_w, nullptr, dbl, 40, 256, nullptr, nullptr, nullptr);
    dtproj_kernel<<<TOK/32, 256>>>(dtw, dtb);
    scan_phase1<<<(BATCH*NCH*128)/8, 256>>>(A_log);
    scan_phase2<<<128, 128>>>(A_log);
    scan_phase3<<<(BATCH*NCH*128)/8, 256>>>(A_log, Dp);

    // ---- join, then fused out_proj+gate+LN2, MLP ----
    cudaStreamWaitEvent(0, ev_join, 0);
    fused_out_gate<<<dim3(1,196), 256, SMFG>>>(y, out_w, out_b, gate_w, gate_b,
                                               x, attn, x1, ln2_g, ln2_b, h2);
    mma_gemm<128,1,0,0,0><<<dim3(4,196), 256, SM128>>>(h2, mlp_w1, mlp_b1, hid, 512, 128, nullptr, nullptr, nullptr);
    mma_gemm<64,3,0,0,0><<<dim3(2,196), 256, SM64>>>(hid, mlp_w2, mlp_b2, out, 128, 512, x1, nullptr, nullptr);

    (void)in_sizes; (void)n_in; (void)out_size;
}